// round 8
// baseline (speedup 1.0000x reference)
#include <cuda_runtime.h>
#include <cuda_fp16.h>
#include <cstdint>
#include <math.h>

// Problem dims
#define BNROWS 32768   // B*N
#define DDIM   256
#define KCODES 1024
#define THRESH 6.0f

// Output layout (float32, reference return order)
#define OFF_Q      0ull
#define OFF_DICT   8388608ull
#define OFF_COMMIT 8388609ull
#define OFF_IDX    8388610ull
#define OFF_PERP   8421378ull

// ---------------- scratch (device globals) -----------------------------------
__device__ float  g_partS [256][DDIM];
__device__ float  g_partS2[256][DDIM];
__device__ float  g_partC [256];
__device__ float  g_cnt;
__device__ __align__(16) float g_scale[DDIM];
__device__ __align__(16) float g_shift[DDIM];
__device__ __align__(16) __half g_eBh[(size_t)KCODES * DDIM]; // fp16(E^T)
__device__ __align__(16) float g_ET[(size_t)KCODES * DDIM];   // codebook^T [K][D]
__device__ __align__(16) float g_csq[KCODES];
__device__ float  g_xsq[BNROWS];
__device__ __align__(16) ulonglong2 g_tres[(size_t)BNROWS * 4]; // per (row, codeTile): {p1, m2}
__device__ unsigned long long g_packed[BNROWS];                 // (mono(d)<<32)|idx
__device__ int    g_reflist[BNROWS];
__device__ int    g_nref;
__device__ float  g_counts[KCODES];
__device__ double g_loss;
__device__ int    g_ticket;

// ---------------- helpers ------------------------------------------------------
__device__ __forceinline__ uint32_t s2u(const void* p) {
    uint32_t a;
    asm("{ .reg .u64 t; cvta.to.shared.u64 t, %1; cvt.u32.u64 %0, t; }" : "=r"(a) : "l"(p));
    return a;
}
__device__ __forceinline__ uint32_t swz(uint32_t off) { return off ^ ((off >> 3) & 0x70); }

__device__ __forceinline__ void cp16(uint32_t dst, const void* src) {
    asm volatile("cp.async.cg.shared.global [%0], [%1], 16;" :: "r"(dst), "l"(src) : "memory");
}
#define CP_COMMIT() asm volatile("cp.async.commit_group;" ::: "memory")
#define CP_WAIT(N)  asm volatile("cp.async.wait_group %0;" :: "n"(N) : "memory")

__device__ __forceinline__ void ldsm_x4(uint32_t* r, uint32_t addr) {
    asm volatile("ldmatrix.sync.aligned.m8n8.x4.shared.b16 {%0,%1,%2,%3}, [%4];"
                 : "=r"(r[0]), "=r"(r[1]), "=r"(r[2]), "=r"(r[3]) : "r"(addr));
}
__device__ __forceinline__ void ldsm_x2(uint32_t* r, uint32_t addr) {
    asm volatile("ldmatrix.sync.aligned.m8n8.x2.shared.b16 {%0,%1}, [%2];"
                 : "=r"(r[0]), "=r"(r[1]) : "r"(addr));
}
__device__ __forceinline__ void mma16816(float* c, const uint32_t* a, const uint32_t* b) {
    asm volatile(
        "mma.sync.aligned.m16n8k16.row.col.f32.f16.f16.f32 "
        "{%0,%1,%2,%3}, {%4,%5,%6,%7}, {%8,%9}, {%0,%1,%2,%3};"
        : "+f"(c[0]), "+f"(c[1]), "+f"(c[2]), "+f"(c[3])
        : "r"(a[0]), "r"(a[1]), "r"(a[2]), "r"(a[3]), "r"(b[0]), "r"(b[1]));
}
__device__ __forceinline__ unsigned mono(float d) {
    unsigned u = __float_as_uint(d);
    return ((int)u < 0) ? ~u : (u | 0x80000000u);
}
__device__ __forceinline__ float unmono(unsigned k) {
    unsigned u = (k & 0x80000000u) ? (k & 0x7fffffffu) : ~k;
    return __uint_as_float(u);
}

// ---------------- K1: masked stats partials -------------------------------------
__global__ void k_stats(const float* __restrict__ x, const int* __restrict__ mask) {
    int d4 = threadIdx.x;   // 0..63
    int ty = threadIdx.y;   // 0..3
    int b  = blockIdx.x;
    int r0 = b * 128 + ty * 32;
    const float4* x4 = (const float4*)x;
    float4 s  = make_float4(0.f, 0.f, 0.f, 0.f);
    float4 s2 = make_float4(0.f, 0.f, 0.f, 0.f);
    float  c  = 0.f;
    for (int r = 0; r < 32; r++) {
        if (mask[r0 + r]) {
            float4 v = x4[(size_t)(r0 + r) * 64 + d4];
            s.x += v.x; s.y += v.y; s.z += v.z; s.w += v.w;
            s2.x += v.x * v.x; s2.y += v.y * v.y; s2.z += v.z * v.z; s2.w += v.w * v.w;
            c += 1.f;
        }
    }
    __shared__ float4 sS[4][64], sS2[4][64];
    __shared__ float  sC[4];
    sS[ty][d4] = s; sS2[ty][d4] = s2;
    if (d4 == 0) sC[ty] = c;
    __syncthreads();
    if (ty == 0) {
        for (int y = 1; y < 4; y++) {
            float4 a = sS[y][d4], a2 = sS2[y][d4];
            s.x += a.x; s.y += a.y; s.z += a.z; s.w += a.w;
            s2.x += a2.x; s2.y += a2.y; s2.z += a2.z; s2.w += a2.w;
        }
        ((float4*)g_partS [b])[d4] = s;
        ((float4*)g_partS2[b])[d4] = s2;
        if (d4 == 0) g_partC[b] = sC[0] + sC[1] + sC[2] + sC[3];
    }
}

// ---------------- K2: transpose E + fp16 + deterministic csq ---------------------
__global__ void k_prep_e(const float* __restrict__ E) {   // grid 32, block (32,8)
    int tx = threadIdx.x;  // code local
    int ty = threadIdx.y;  // d group
    int code = blockIdx.x * 32 + tx;
    float sq = 0.f;
    for (int d = ty; d < DDIM; d += 8) {
        float v = E[(size_t)d * KCODES + code];
        g_ET [(size_t)code * DDIM + d] = v;
        g_eBh[(size_t)code * DDIM + d] = __float2half_rn(v);
        sq = fmaf(v, v, sq);
    }
    __shared__ float ssq[8][32];
    ssq[ty][tx] = sq;
    __syncthreads();
    if (ty == 0) {
        float s = 0.f;
        for (int i = 0; i < 8; i++) s += ssq[i][tx];
        g_csq[code] = s;
    }
}

// ---------------- K3: reduce stats -> scale/shift; zero run state ----------------
__global__ void k_reduce_stats(const float* __restrict__ gamma, const float* __restrict__ beta) {
    int d = threadIdx.x;
    float s = 0.f, s2 = 0.f, cnt = 0.f;
#pragma unroll 8
    for (int b = 0; b < 256; b++) {
        s  += g_partS [b][d];
        s2 += g_partS2[b][d];
        cnt += g_partC[b];
    }
    for (int i = d; i < KCODES; i += 256) g_counts[i] = 0.f;
    if (d == 0) { g_cnt = cnt; g_loss = 0.0; g_ticket = 0; g_nref = 0; }
    float nv = fmaxf(cnt, 1.f);
    float mu  = s / nv;
    float var = s2 / nv - mu * mu;
    float sc  = rsqrtf(var + 1e-5f) * gamma[d];
    g_scale[d] = sc;
    g_shift[d] = beta[d] - mu * sc;
}

// ---------------- K4: persistent 1-pass fp16 HMMA coarse GEMM + best2 ------------
// 1024 tickets = 256 row-tiles (128 rows) x 4 code-tiles (256 codes, 2 subtiles of
// 128). 256 threads = 8 warps (2m x 4n), warp tile 64x32. A = fp16(xb) built
// in-kernel (16KB x 4 k-chunks). B = fp16(E^T) streamed: 8 chunks of 16KB,
// 5-stage cp.async ring. Tracks (best1,idx,best2) per row, writes per-tile
// results to g_tres (no atomics; each tile owned by exactly one ticket).
#define NTILES  1024
#define NSTG    5
#define B_OFF   65536
#define CSQ_OFF (B_OFF + NSTG * 16384)    // 147456
#define XSQ_OFF (CSQ_OFF + 4096)          // 151552
#define SP1_OFF (XSQ_OFF + 1024)          // 152576  u64[128][4]
#define SM2_OFF (SP1_OFF + 4096)          // 156672  u32[128][4]
#define TK_OFF  (SM2_OFF + 2048)          // 158720
#define SMEMSZ  (TK_OFF + 16)

__global__ void __launch_bounds__(256, 1) k_coarse(const float* __restrict__ x) {
    extern __shared__ char smem[];
    const uint32_t sbA = s2u(smem);
    const uint32_t sbB = sbA + B_OFF;
    const int tid  = threadIdx.x;
    const int lane = tid & 31;
    const int wid  = tid >> 5;
    const int wm   = wid >> 2;       // 0..1
    const int wn   = wid & 3;        // 0..3

    ((float4*)(smem + CSQ_OFF))[tid] = ((const float4*)g_csq)[tid];
    int* s_tk = (int*)(smem + TK_OFF);
    float* sxsq = (float*)(smem + XSQ_OFF);
    unsigned long long* sp1 = (unsigned long long*)(smem + SP1_OFF);
    unsigned* sm2 = (unsigned*)(smem + SM2_OFF);
    const float* scsq = (const float*)(smem + CSQ_OFF);

    const int colA = tid & 63;
    const float4 scv = ((const float4*)g_scale)[colA];
    const float4 shv = ((const float4*)g_shift)[colA];

    const uint32_t aRow = (uint32_t)(wm * 64 + (lane & 15));
    const uint32_t aKG  = (uint32_t)((lane >> 4) << 4);
    const uint32_t bRow = (uint32_t)(wn * 32 + (lane & 7));
    const uint32_t bKG  = (uint32_t)(((lane >> 3) & 1) << 4);

    int cachedRow = -1;
    for (;;) {
        __syncthreads();
        if (tid == 0) *s_tk = atomicAdd(&g_ticket, 1);
        __syncthreads();
        const int tk = *s_tk;
        if (tk >= NTILES) break;
        const int rowTile  = tk >> 2;
        const int codeTile = tk & 3;
        const int rowBase  = rowTile << 7;
        const int codeBase = codeTile << 8;

        // ---- B prologue: chunks (nsub=0, kc=0..3) into stages 0..3 ----
        {
            const char* bs = (const char*)(g_eBh + (size_t)codeBase * DDIM);
#pragma unroll
            for (int c0 = 0; c0 < 4; c0++) {
#pragma unroll
                for (int v = 0; v < 4; v++) {
                    int idx = tid + v * 256;   // 0..1023
                    int r = idx >> 3, j = idx & 7;
                    cp16(sbB + c0 * 16384 + swz((r << 7) + (j << 4)),
                         bs + (size_t)r * 512 + c0 * 128 + j * 16);
                }
                CP_COMMIT();
            }
        }

        // ---- A load/convert (only when row-tile changes) ----
        if (rowTile != cachedRow) {
            cachedRow = rowTile;
            const float4* xs = (const float4*)(x + (size_t)rowBase * DDIM);
            const int kc = colA >> 4;
            const int kb = (colA & 15) * 4;
#pragma unroll 4
            for (int i = 0; i < 32; i++) {
                int m = (tid >> 6) + i * 4;
                float4 v = xs[(size_t)m * 64 + colA];
                float b0 = v.x * scv.x + shv.x;
                float b1 = v.y * scv.y + shv.y;
                float b2 = v.z * scv.z + shv.z;
                float b3 = v.w * scv.w + shv.w;
                __half2 h01 = __floats2half2_rn(b0, b1);
                __half2 h23 = __floats2half2_rn(b2, b3);
                uint32_t so = swz((uint32_t)(m << 7) + (uint32_t)kb * 2);
                asm volatile("st.shared.v2.u32 [%0], {%1,%2};"
                             :: "r"(sbA + kc * 16384 + so),
                                "r"(*(uint32_t*)&h01), "r"(*(uint32_t*)&h23));
                float s = b0 * b0 + b1 * b1 + b2 * b2 + b3 * b3;
                for (int o = 16; o; o >>= 1) s += __shfl_down_sync(0xffffffffu, s, o);
                if (lane == 0) sxsq[m * 2 + (wid & 1)] = s;
            }
            __syncthreads();
            if (tid < 128) g_xsq[rowBase + tid] = sxsq[tid * 2] + sxsq[tid * 2 + 1];
        }

        float acc[4][4][4];
        unsigned long long p1[8];
        unsigned m2[8];
#pragma unroll
        for (int s = 0; s < 8; s++) { p1[s] = 0xFFFFFFFFFFFFFFFFull; m2[s] = 0xFFFFFFFFu; }

        // ---- mainloop: 8 chunks (2 subtiles x 4 k-chunks) ----
#pragma unroll 1
        for (int c = 0; c < 8; c++) {
            const int nsub = c >> 2;
            const int kc = c & 3;
            const int stage = (c >= NSTG) ? c - NSTG : c;

            if (c <= 4)      CP_WAIT(3);
            else if (c == 5) CP_WAIT(2);
            else if (c == 6) CP_WAIT(1);
            else             CP_WAIT(0);
            __syncthreads();

            if (kc == 0) {
#pragma unroll
                for (int mf = 0; mf < 4; mf++)
#pragma unroll
                    for (int nf = 0; nf < 4; nf++)
#pragma unroll
                        for (int t = 0; t < 4; t++) acc[mf][nf][t] = 0.f;
            }

            const uint32_t bbase = sbB + stage * 16384;
            const uint32_t ah = sbA + kc * 16384;
#pragma unroll
            for (int ks = 0; ks < 4; ks++) {
                uint32_t b[4][2];
#pragma unroll
                for (int nf = 0; nf < 4; nf++)
                    ldsm_x2(b[nf], bbase + swz(((bRow + nf * 8) << 7) + ks * 32 + bKG));
                uint32_t a[4][4];
#pragma unroll
                for (int mf = 0; mf < 4; mf++)
                    ldsm_x4(a[mf], ah + swz(((aRow + mf * 16) << 7) + ks * 32 + aKG));
#pragma unroll
                for (int mf = 0; mf < 4; mf++)
#pragma unroll
                    for (int nf = 0; nf < 4; nf++)
                        mma16816(acc[mf][nf], a[mf], b[nf]);
            }

            if (kc == 3) {
                const float* csqp = scsq + codeBase + nsub * 128 + wn * 32 + 2 * (lane & 3);
#pragma unroll
                for (int nf = 0; nf < 4; nf++) {
                    float q0 = csqp[nf * 8];
                    float q1 = csqp[nf * 8 + 1];
                    int n0 = codeBase + nsub * 128 + wn * 32 + nf * 8 + 2 * (lane & 3);
#pragma unroll
                    for (int mf = 0; mf < 4; mf++) {
#pragma unroll
                        for (int h = 0; h < 2; h++) {
                            int s = mf * 2 + h;
#pragma unroll
                            for (int w = 0; w < 2; w++) {
                                float d = (w ? q1 : q0) - 2.f * acc[mf][nf][h * 2 + w];
                                unsigned mk = mono(d);
                                unsigned long long pk =
                                    ((unsigned long long)mk << 32) | (unsigned)(n0 + w);
                                if (pk < p1[s]) {
                                    m2[s] = min(m2[s], (unsigned)(p1[s] >> 32));
                                    p1[s] = pk;
                                } else {
                                    m2[s] = min(m2[s], mk);
                                }
                            }
                        }
                    }
                }
            }

            if (c + 4 < 8) {
                const int cc = c + 4;
                const int nsub2 = cc >> 2, kc2 = cc & 3;
                const int st2 = (stage + 4 >= NSTG) ? stage + 4 - NSTG : stage + 4;
                const char* bs = (const char*)(g_eBh + (size_t)(codeBase + nsub2 * 128) * DDIM);
#pragma unroll
                for (int v = 0; v < 4; v++) {
                    int idx = tid + v * 256;
                    int r = idx >> 3, j = idx & 7;
                    cp16(sbB + st2 * 16384 + swz((r << 7) + (j << 4)),
                         bs + (size_t)r * 512 + kc2 * 128 + j * 16);
                }
                CP_COMMIT();
            }
        }

        // ---- per-ticket (best1,idx,best2) reduce ----
        __syncthreads();
#pragma unroll
        for (int s = 0; s < 8; s++) {
            unsigned long long p = p1[s];
            unsigned m = m2[s];
#pragma unroll
            for (int off = 1; off <= 2; off <<= 1) {
                unsigned long long op = __shfl_xor_sync(0xffffffffu, p, off);
                unsigned om = __shfl_xor_sync(0xffffffffu, m, off);
                if (op < p) {
                    m = min(min(m, (unsigned)(p >> 32)), om);
                    p = op;
                } else {
                    m = min(min(m, (unsigned)(op >> 32)), om);
                }
            }
            if ((lane & 3) == 0) {
                int row = wm * 64 + (s >> 1) * 16 + (lane >> 2) + (s & 1) * 8;
                sp1[row * 4 + wn] = p;
                sm2[row * 4 + wn] = m;
            }
        }
        __syncthreads();
        if (tid < 128) {
            unsigned long long p = sp1[tid * 4];
            unsigned m = sm2[tid * 4];
#pragma unroll
            for (int t = 1; t < 4; t++) {
                unsigned long long op = sp1[tid * 4 + t];
                unsigned om = sm2[tid * 4 + t];
                if (op < p) {
                    m = min(min(m, (unsigned)(p >> 32)), om);
                    p = op;
                } else {
                    m = min(min(m, (unsigned)(op >> 32)), om);
                }
            }
            ulonglong2 r;
            r.x = p; r.y = (unsigned long long)m;
            g_tres[(size_t)(rowBase + tid) * 4 + codeTile] = r;
        }
    }
}

// ---------------- K5: select winners / build refine list -------------------------
__global__ void k_select() {
    int row = blockIdx.x * 256 + threadIdx.x;
    const ulonglong2* tr = &g_tres[(size_t)row * 4];
    ulonglong2 r0 = tr[0];
    unsigned long long p = r0.x;
    unsigned m = (unsigned)r0.y;
#pragma unroll
    for (int t = 1; t < 4; t++) {
        ulonglong2 rt = tr[t];
        unsigned long long op = rt.x;
        unsigned om = (unsigned)rt.y;
        if (op < p) {
            m = min(min(m, (unsigned)(p >> 32)), om);
            p = op;
        } else {
            m = min(min(m, (unsigned)(op >> 32)), om);
        }
    }
    g_packed[row] = p;
    float b1 = unmono((unsigned)(p >> 32));
    float b2 = unmono(m);
    if (b2 - b1 < THRESH) {
        int pos = atomicAdd(&g_nref, 1);
        g_reflist[pos] = row;
    }
}

// ---------------- K6: exact fp32 refine of near-tie rows -------------------------
#define RSMEM (65536 + 1024 + 64)
__global__ void __launch_bounds__(256) k_refine(const float* __restrict__ x) {
    extern __shared__ char rsm[];
    float* sE  = (float*)rsm;                 // 64 codes x 256 dims
    float* sxb = (float*)(rsm + 65536);       // 256
    unsigned long long* sred = (unsigned long long*)(rsm + 66560);
    const int tid = threadIdx.x;
    const int nref = g_nref;
    const int cl = tid >> 2, q = tid & 3;

    for (int t = blockIdx.x; t < nref; t += gridDim.x) {
        int row = g_reflist[t];
        __syncthreads();
        sxb[tid] = x[(size_t)row * DDIM + tid] * g_scale[tid] + g_shift[tid];
        unsigned long long lbest = 0xFFFFFFFFFFFFFFFFull;
#pragma unroll 1
        for (int tile = 0; tile < 16; tile++) {
            __syncthreads();
            for (int i = tid; i < 16384; i += 256)
                sE[i] = g_ET[(size_t)tile * 16384 + i];
            __syncthreads();
            float dot = 0.f;
            const float* ep = sE + cl * 256 + q * 64;
            const float* xp = sxb + q * 64;
#pragma unroll 16
            for (int d = 0; d < 64; d++) dot = fmaf(ep[d], xp[d], dot);
            dot += __shfl_xor_sync(0xffffffffu, dot, 1);
            dot += __shfl_xor_sync(0xffffffffu, dot, 2);
            if (q == 0) {
                int code = tile * 64 + cl;
                float dd = g_csq[code] - 2.f * dot;
                unsigned long long pk =
                    ((unsigned long long)mono(dd) << 32) | (unsigned)code;
                if (pk < lbest) lbest = pk;
            }
        }
        for (int off = 16; off; off >>= 1) {
            unsigned long long o = __shfl_xor_sync(0xffffffffu, lbest, off);
            if (o < lbest) lbest = o;
        }
        if ((tid & 31) == 0) sred[tid >> 5] = lbest;
        __syncthreads();
        if (tid == 0) {
            unsigned long long b = sred[0];
            for (int i = 1; i < 8; i++) if (sred[i] < b) b = sred[i];
            g_packed[row] = b;
        }
    }
}

// ---------------- K7: gather q, output, loss, counts, idx ------------------------
__global__ void k_quant(const int* __restrict__ mask,
                        float* __restrict__ outQ, float* __restrict__ outIdx) {
    int w = threadIdx.x >> 5, lane = threadIdx.x & 31;
    int row = blockIdx.x * 8 + w;
    int m = mask[row];
    unsigned long long pk = g_packed[row];
    int idx = (int)(pk & 0xffffffffull);
    const float4* qv = (const float4*)&g_ET[(size_t)idx * DDIM];
    float4* ov = (float4*)&outQ[(size_t)row * DDIM];
    float4 z = make_float4(0.f, 0.f, 0.f, 0.f);
#pragma unroll
    for (int t = 0; t < 2; t++) {
        int j = lane + t * 32;
        ov[j] = m ? qv[j] : z;
    }
    __shared__ float red[8];
    if (lane == 0) {
        float best = unmono((unsigned)(pk >> 32));
        red[w] = m ? (g_xsq[row] + best) : 0.f;
        outIdx[row] = m ? (float)idx : -1.f;
        if (m) atomicAdd(&g_counts[idx], 1.f);
    }
    __syncthreads();
    if (threadIdx.x == 0) {
        float t = 0.f;
        for (int i = 0; i < 8; i++) t += red[i];
        atomicAdd(&g_loss, (double)t);
    }
}

// ---------------- K8: finalize scalars -------------------------------------------
__global__ void k_final(float* __restrict__ out) {
    int t = threadIdx.x;  // 1024 threads
    float nv = fmaxf(g_cnt, 1.f);
    float p = g_counts[t] / nv;
    float h = -p * logf(p + 1e-10f);
    for (int o = 16; o; o >>= 1) h += __shfl_down_sync(0xffffffffu, h, o);
    __shared__ float red[32];
    if ((t & 31) == 0) red[t >> 5] = h;
    __syncthreads();
    if (t < 32) {
        float s = red[t];
        for (int o = 16; o; o >>= 1) s += __shfl_down_sync(0xffffffffu, s, o);
        if (t == 0) {
            float loss = (float)(g_loss / ((double)nv * (double)DDIM));
            out[OFF_DICT]   = loss;
            out[OFF_COMMIT] = loss;
            out[OFF_PERP]   = expf(s);
        }
    }
}

// ---------------- launch ------------------------------------------------------------
extern "C" void kernel_launch(void* const* d_in, const int* in_sizes, int n_in,
                              void* d_out, int out_size) {
    const float* x     = (const float*)d_in[0];
    const int*   mask  = (const int*)  d_in[1];
    const float* E     = (const float*)d_in[2];
    const float* gamma = (const float*)d_in[3];
    const float* beta  = (const float*)d_in[4];
    float* out = (float*)d_out;

    cudaFuncSetAttribute(k_coarse, cudaFuncAttributeMaxDynamicSharedMemorySize, SMEMSZ);
    cudaFuncSetAttribute(k_refine, cudaFuncAttributeMaxDynamicSharedMemorySize, RSMEM);

    k_stats<<<256, dim3(64, 4)>>>(x, mask);                  // 1
    k_prep_e<<<32, dim3(32, 8)>>>(E);                        // 2
    k_reduce_stats<<<1, 256>>>(gamma, beta);                 // 3
    k_coarse<<<148, 256, SMEMSZ>>>(x);                       // 4  (ncu lands here)
    k_select<<<128, 256>>>();                                // 5
    k_refine<<<148, 256, RSMEM>>>(x);                        // 6
    k_quant<<<BNROWS / 8, 256>>>(mask, out + OFF_Q, out + OFF_IDX);
    k_final<<<1, 1024>>>(out);
}

// round 9
// speedup vs baseline: 1.4730x; 1.4730x over previous
#include <cuda_runtime.h>
#include <cuda_fp16.h>
#include <cstdint>
#include <math.h>

// Problem dims
#define BNROWS 32768   // B*N
#define DDIM   256
#define KCODES 1024
#define THRESH 6.0f

// Output layout (float32, reference return order)
#define OFF_Q      0ull
#define OFF_DICT   8388608ull
#define OFF_COMMIT 8388609ull
#define OFF_IDX    8388610ull
#define OFF_PERP   8421378ull

// ---------------- scratch (device globals) -----------------------------------
__device__ float  g_partS [256][DDIM];
__device__ float  g_partS2[256][DDIM];
__device__ float  g_partC [256];
__device__ float  g_cnt;
__device__ __align__(16) float g_scale[DDIM];
__device__ __align__(16) float g_shift[DDIM];
__device__ __align__(16) __half g_eBh[(size_t)KCODES * DDIM]; // fp16(E^T)
__device__ __align__(16) float g_ET[(size_t)KCODES * DDIM];   // codebook^T [K][D]
__device__ __align__(16) float g_csq[KCODES];
__device__ float  g_xsq[BNROWS];
__device__ __align__(16) ulonglong2 g_tres[(size_t)BNROWS * 4]; // per (row, codeTile): {p1, m2}
__device__ unsigned long long g_packed[BNROWS];                 // (mono(d)<<32)|idx
__device__ int    g_reflist[BNROWS];
__device__ int    g_nref;
__device__ float  g_counts[KCODES];
__device__ double g_loss;
__device__ int    g_ticket;

// ---------------- helpers ------------------------------------------------------
__device__ __forceinline__ uint32_t s2u(const void* p) {
    uint32_t a;
    asm("{ .reg .u64 t; cvta.to.shared.u64 t, %1; cvt.u32.u64 %0, t; }" : "=r"(a) : "l"(p));
    return a;
}
__device__ __forceinline__ uint32_t swz(uint32_t off) { return off ^ ((off >> 3) & 0x70); }

__device__ __forceinline__ void cp16(uint32_t dst, const void* src) {
    asm volatile("cp.async.cg.shared.global [%0], [%1], 16;" :: "r"(dst), "l"(src) : "memory");
}
#define CP_COMMIT() asm volatile("cp.async.commit_group;" ::: "memory")
#define CP_WAIT(N)  asm volatile("cp.async.wait_group %0;" :: "n"(N) : "memory")

__device__ __forceinline__ void ldsm_x4(uint32_t* r, uint32_t addr) {
    asm volatile("ldmatrix.sync.aligned.m8n8.x4.shared.b16 {%0,%1,%2,%3}, [%4];"
                 : "=r"(r[0]), "=r"(r[1]), "=r"(r[2]), "=r"(r[3]) : "r"(addr));
}
__device__ __forceinline__ void ldsm_x2(uint32_t* r, uint32_t addr) {
    asm volatile("ldmatrix.sync.aligned.m8n8.x2.shared.b16 {%0,%1}, [%2];"
                 : "=r"(r[0]), "=r"(r[1]) : "r"(addr));
}
__device__ __forceinline__ void mma16816(float* c, const uint32_t* a, const uint32_t* b) {
    asm volatile(
        "mma.sync.aligned.m16n8k16.row.col.f32.f16.f16.f32 "
        "{%0,%1,%2,%3}, {%4,%5,%6,%7}, {%8,%9}, {%0,%1,%2,%3};"
        : "+f"(c[0]), "+f"(c[1]), "+f"(c[2]), "+f"(c[3])
        : "r"(a[0]), "r"(a[1]), "r"(a[2]), "r"(a[3]), "r"(b[0]), "r"(b[1]));
}
__device__ __forceinline__ unsigned mono(float d) {
    unsigned u = __float_as_uint(d);
    return ((int)u < 0) ? ~u : (u | 0x80000000u);
}
__device__ __forceinline__ float unmono(unsigned k) {
    unsigned u = (k & 0x80000000u) ? (k & 0x7fffffffu) : ~k;
    return __uint_as_float(u);
}

// ---------------- K1: masked stats partials -------------------------------------
__global__ void k_stats(const float* __restrict__ x, const int* __restrict__ mask) {
    int d4 = threadIdx.x;   // 0..63
    int ty = threadIdx.y;   // 0..3
    int b  = blockIdx.x;
    int r0 = b * 128 + ty * 32;
    const float4* x4 = (const float4*)x;
    float4 s  = make_float4(0.f, 0.f, 0.f, 0.f);
    float4 s2 = make_float4(0.f, 0.f, 0.f, 0.f);
    float  c  = 0.f;
    for (int r = 0; r < 32; r++) {
        if (mask[r0 + r]) {
            float4 v = x4[(size_t)(r0 + r) * 64 + d4];
            s.x += v.x; s.y += v.y; s.z += v.z; s.w += v.w;
            s2.x += v.x * v.x; s2.y += v.y * v.y; s2.z += v.z * v.z; s2.w += v.w * v.w;
            c += 1.f;
        }
    }
    __shared__ float4 sS[4][64], sS2[4][64];
    __shared__ float  sC[4];
    sS[ty][d4] = s; sS2[ty][d4] = s2;
    if (d4 == 0) sC[ty] = c;
    __syncthreads();
    if (ty == 0) {
        for (int y = 1; y < 4; y++) {
            float4 a = sS[y][d4], a2 = sS2[y][d4];
            s.x += a.x; s.y += a.y; s.z += a.z; s.w += a.w;
            s2.x += a2.x; s2.y += a2.y; s2.z += a2.z; s2.w += a2.w;
        }
        ((float4*)g_partS [b])[d4] = s;
        ((float4*)g_partS2[b])[d4] = s2;
        if (d4 == 0) g_partC[b] = sC[0] + sC[1] + sC[2] + sC[3];
    }
}

// ---------------- K2: transpose E + fp16 + deterministic csq ---------------------
__global__ void k_prep_e(const float* __restrict__ E) {   // grid 32, block (32,8)
    int tx = threadIdx.x;  // code local
    int ty = threadIdx.y;  // d group
    int code = blockIdx.x * 32 + tx;
    float sq = 0.f;
    for (int d = ty; d < DDIM; d += 8) {
        float v = E[(size_t)d * KCODES + code];
        g_ET [(size_t)code * DDIM + d] = v;
        g_eBh[(size_t)code * DDIM + d] = __float2half_rn(v);
        sq = fmaf(v, v, sq);
    }
    __shared__ float ssq[8][32];
    ssq[ty][tx] = sq;
    __syncthreads();
    if (ty == 0) {
        float s = 0.f;
        for (int i = 0; i < 8; i++) s += ssq[i][tx];
        g_csq[code] = s;
    }
}

// ---------------- K3: reduce stats -> scale/shift; zero run state ----------------
__global__ void k_reduce_stats(const float* __restrict__ gamma, const float* __restrict__ beta) {
    int d = threadIdx.x;
    float s = 0.f, s2 = 0.f, cnt = 0.f;
#pragma unroll 8
    for (int b = 0; b < 256; b++) {
        s  += g_partS [b][d];
        s2 += g_partS2[b][d];
        cnt += g_partC[b];
    }
    for (int i = d; i < KCODES; i += 256) g_counts[i] = 0.f;
    if (d == 0) { g_cnt = cnt; g_loss = 0.0; g_ticket = 0; g_nref = 0; }
    float nv = fmaxf(cnt, 1.f);
    float mu  = s / nv;
    float var = s2 / nv - mu * mu;
    float sc  = rsqrtf(var + 1e-5f) * gamma[d];
    g_scale[d] = sc;
    g_shift[d] = beta[d] - mu * sc;
}

// ---------------- K4: persistent 1-pass fp16 HMMA coarse GEMM + best2 ------------
#define NTILES  1024
#define NSTG    5
#define B_OFF   65536
#define CSQ_OFF (B_OFF + NSTG * 16384)    // 147456
#define XSQ_OFF (CSQ_OFF + 4096)          // 151552
#define SP1_OFF (XSQ_OFF + 1024)          // 152576  u64[128][4]
#define SM2_OFF (SP1_OFF + 4096)          // 156672  u32[128][4]
#define TK_OFF  (SM2_OFF + 2048)          // 158720
#define SMEMSZ  (TK_OFF + 16)

__global__ void __launch_bounds__(256, 1) k_coarse(const float* __restrict__ x) {
    extern __shared__ char smem[];
    const uint32_t sbA = s2u(smem);
    const uint32_t sbB = sbA + B_OFF;
    const int tid  = threadIdx.x;
    const int lane = tid & 31;
    const int wid  = tid >> 5;
    const int wm   = wid >> 2;       // 0..1
    const int wn   = wid & 3;        // 0..3

    ((float4*)(smem + CSQ_OFF))[tid] = ((const float4*)g_csq)[tid];
    int* s_tk = (int*)(smem + TK_OFF);
    float* sxsq = (float*)(smem + XSQ_OFF);
    unsigned long long* sp1 = (unsigned long long*)(smem + SP1_OFF);
    unsigned* sm2 = (unsigned*)(smem + SM2_OFF);
    const float* scsq = (const float*)(smem + CSQ_OFF);

    const int colA = tid & 63;
    const float4 scv = ((const float4*)g_scale)[colA];
    const float4 shv = ((const float4*)g_shift)[colA];

    const uint32_t aRow = (uint32_t)(wm * 64 + (lane & 15));
    const uint32_t aKG  = (uint32_t)((lane >> 4) << 4);
    const uint32_t bRow = (uint32_t)(wn * 32 + (lane & 7));
    const uint32_t bKG  = (uint32_t)(((lane >> 3) & 1) << 4);

    int cachedRow = -1;
    for (;;) {
        __syncthreads();
        if (tid == 0) *s_tk = atomicAdd(&g_ticket, 1);
        __syncthreads();
        const int tk = *s_tk;
        if (tk >= NTILES) break;
        const int rowTile  = tk >> 2;
        const int codeTile = tk & 3;
        const int rowBase  = rowTile << 7;
        const int codeBase = codeTile << 8;

        // ---- B prologue: chunks (nsub=0, kc=0..3) into stages 0..3 ----
        {
            const char* bs = (const char*)(g_eBh + (size_t)codeBase * DDIM);
#pragma unroll
            for (int c0 = 0; c0 < 4; c0++) {
#pragma unroll
                for (int v = 0; v < 4; v++) {
                    int idx = tid + v * 256;   // 0..1023
                    int r = idx >> 3, j = idx & 7;
                    cp16(sbB + c0 * 16384 + swz((r << 7) + (j << 4)),
                         bs + (size_t)r * 512 + c0 * 128 + j * 16);
                }
                CP_COMMIT();
            }
        }

        // ---- A load/convert (only when row-tile changes) ----
        if (rowTile != cachedRow) {
            cachedRow = rowTile;
            const float4* xs = (const float4*)(x + (size_t)rowBase * DDIM);
            const int kc = colA >> 4;
            const int kb = (colA & 15) * 4;
#pragma unroll 4
            for (int i = 0; i < 32; i++) {
                int m = (tid >> 6) + i * 4;
                float4 v = xs[(size_t)m * 64 + colA];
                float b0 = v.x * scv.x + shv.x;
                float b1 = v.y * scv.y + shv.y;
                float b2 = v.z * scv.z + shv.z;
                float b3 = v.w * scv.w + shv.w;
                __half2 h01 = __floats2half2_rn(b0, b1);
                __half2 h23 = __floats2half2_rn(b2, b3);
                uint32_t so = swz((uint32_t)(m << 7) + (uint32_t)kb * 2);
                asm volatile("st.shared.v2.u32 [%0], {%1,%2};"
                             :: "r"(sbA + kc * 16384 + so),
                                "r"(*(uint32_t*)&h01), "r"(*(uint32_t*)&h23));
                float s = b0 * b0 + b1 * b1 + b2 * b2 + b3 * b3;
                for (int o = 16; o; o >>= 1) s += __shfl_down_sync(0xffffffffu, s, o);
                if (lane == 0) sxsq[m * 2 + (wid & 1)] = s;
            }
            __syncthreads();
            if (tid < 128) g_xsq[rowBase + tid] = sxsq[tid * 2] + sxsq[tid * 2 + 1];
        }

        float acc[4][4][4];
        unsigned long long p1[8];
        unsigned m2[8];
#pragma unroll
        for (int s = 0; s < 8; s++) { p1[s] = 0xFFFFFFFFFFFFFFFFull; m2[s] = 0xFFFFFFFFu; }

        // ---- mainloop: 8 chunks (2 subtiles x 4 k-chunks) ----
#pragma unroll 1
        for (int c = 0; c < 8; c++) {
            const int nsub = c >> 2;
            const int kc = c & 3;
            const int stage = (c >= NSTG) ? c - NSTG : c;

            if (c <= 4)      CP_WAIT(3);
            else if (c == 5) CP_WAIT(2);
            else if (c == 6) CP_WAIT(1);
            else             CP_WAIT(0);
            __syncthreads();

            if (kc == 0) {
#pragma unroll
                for (int mf = 0; mf < 4; mf++)
#pragma unroll
                    for (int nf = 0; nf < 4; nf++)
#pragma unroll
                        for (int t = 0; t < 4; t++) acc[mf][nf][t] = 0.f;
            }

            const uint32_t bbase = sbB + stage * 16384;
            const uint32_t ah = sbA + kc * 16384;
#pragma unroll
            for (int ks = 0; ks < 4; ks++) {
                uint32_t b[4][2];
#pragma unroll
                for (int nf = 0; nf < 4; nf++)
                    ldsm_x2(b[nf], bbase + swz(((bRow + nf * 8) << 7) + ks * 32 + bKG));
                uint32_t a[4][4];
#pragma unroll
                for (int mf = 0; mf < 4; mf++)
                    ldsm_x4(a[mf], ah + swz(((aRow + mf * 16) << 7) + ks * 32 + aKG));
#pragma unroll
                for (int mf = 0; mf < 4; mf++)
#pragma unroll
                    for (int nf = 0; nf < 4; nf++)
                        mma16816(acc[mf][nf], a[mf], b[nf]);
            }

            if (kc == 3) {
                const float* csqp = scsq + codeBase + nsub * 128 + wn * 32 + 2 * (lane & 3);
#pragma unroll
                for (int nf = 0; nf < 4; nf++) {
                    float q0 = csqp[nf * 8];
                    float q1 = csqp[nf * 8 + 1];
                    int n0 = codeBase + nsub * 128 + wn * 32 + nf * 8 + 2 * (lane & 3);
#pragma unroll
                    for (int mf = 0; mf < 4; mf++) {
#pragma unroll
                        for (int h = 0; h < 2; h++) {
                            int s = mf * 2 + h;
#pragma unroll
                            for (int w = 0; w < 2; w++) {
                                float d = (w ? q1 : q0) - 2.f * acc[mf][nf][h * 2 + w];
                                unsigned mk = mono(d);
                                unsigned long long pk =
                                    ((unsigned long long)mk << 32) | (unsigned)(n0 + w);
                                if (pk < p1[s]) {
                                    m2[s] = min(m2[s], (unsigned)(p1[s] >> 32));
                                    p1[s] = pk;
                                } else {
                                    m2[s] = min(m2[s], mk);
                                }
                            }
                        }
                    }
                }
            }

            if (c + 4 < 8) {
                const int cc = c + 4;
                const int nsub2 = cc >> 2, kc2 = cc & 3;
                const int st2 = (stage + 4 >= NSTG) ? stage + 4 - NSTG : stage + 4;
                const char* bs = (const char*)(g_eBh + (size_t)(codeBase + nsub2 * 128) * DDIM);
#pragma unroll
                for (int v = 0; v < 4; v++) {
                    int idx = tid + v * 256;
                    int r = idx >> 3, j = idx & 7;
                    cp16(sbB + st2 * 16384 + swz((r << 7) + (j << 4)),
                         bs + (size_t)r * 512 + kc2 * 128 + j * 16);
                }
                CP_COMMIT();
            }
        }

        // ---- per-ticket (best1,idx,best2) reduce ----
        __syncthreads();
#pragma unroll
        for (int s = 0; s < 8; s++) {
            unsigned long long p = p1[s];
            unsigned m = m2[s];
#pragma unroll
            for (int off = 1; off <= 2; off <<= 1) {
                unsigned long long op = __shfl_xor_sync(0xffffffffu, p, off);
                unsigned om = __shfl_xor_sync(0xffffffffu, m, off);
                if (op < p) {
                    m = min(min(m, (unsigned)(p >> 32)), om);
                    p = op;
                } else {
                    m = min(min(m, (unsigned)(op >> 32)), om);
                }
            }
            if ((lane & 3) == 0) {
                int row = wm * 64 + (s >> 1) * 16 + (lane >> 2) + (s & 1) * 8;
                sp1[row * 4 + wn] = p;
                sm2[row * 4 + wn] = m;
            }
        }
        __syncthreads();
        if (tid < 128) {
            unsigned long long p = sp1[tid * 4];
            unsigned m = sm2[tid * 4];
#pragma unroll
            for (int t = 1; t < 4; t++) {
                unsigned long long op = sp1[tid * 4 + t];
                unsigned om = sm2[tid * 4 + t];
                if (op < p) {
                    m = min(min(m, (unsigned)(p >> 32)), om);
                    p = op;
                } else {
                    m = min(min(m, (unsigned)(op >> 32)), om);
                }
            }
            ulonglong2 r;
            r.x = p; r.y = (unsigned long long)m;
            g_tres[(size_t)(rowBase + tid) * 4 + codeTile] = r;
        }
    }
}

// ---------------- K5: select winners / build refine list -------------------------
__global__ void k_select() {
    int row = blockIdx.x * 256 + threadIdx.x;
    const ulonglong2* tr = &g_tres[(size_t)row * 4];
    ulonglong2 r0 = tr[0];
    unsigned long long p = r0.x;
    unsigned m = (unsigned)r0.y;
#pragma unroll
    for (int t = 1; t < 4; t++) {
        ulonglong2 rt = tr[t];
        unsigned long long op = rt.x;
        unsigned om = (unsigned)rt.y;
        if (op < p) {
            m = min(min(m, (unsigned)(p >> 32)), om);
            p = op;
        } else {
            m = min(min(m, (unsigned)(op >> 32)), om);
        }
    }
    g_packed[row] = p;
    float b1 = unmono((unsigned)(p >> 32));
    float b2 = unmono(m);
    if (b2 - b1 < THRESH) {
        int pos = atomicAdd(&g_nref, 1);
        g_reflist[pos] = row;
    }
}

// ---------------- K6: exact fp32 refine (warp-per-row, conflict-free) ------------
// 8 rows per block (one per warp), xb in registers (8/lane). E tiles of 64 codes
// staged in smem with 257-float row pitch (bank = (c+l)%32 -> conflict-free).
#define RSMEM (64 * 257 * 4 + 4096 + 2048 + 64)   // sE + scsq + scale/shift
__global__ void __launch_bounds__(256) k_refine(const float* __restrict__ x) {
    extern __shared__ char rsm[];
    float* sE   = (float*)rsm;                  // [64][257]
    float* scsq = (float*)(rsm + 64 * 257 * 4); // 1024
    float* ssc  = scsq + 1024;                  // 256
    float* ssh  = ssc + 256;                    // 256
    const int tid = threadIdx.x;
    const int lane = tid & 31;
    const int w = tid >> 5;
    const int nref = g_nref;
    if (nref == 0) return;

    for (int i = tid; i < KCODES; i += 256) scsq[i] = g_csq[i];
    ssc[tid] = g_scale[tid];
    ssh[tid] = g_shift[tid];
    __syncthreads();

    for (int base = blockIdx.x * 8; base < nref; base += gridDim.x * 8) {
        int row = -1;
        float xb[8];
        if (base + w < nref) {
            row = g_reflist[base + w];
#pragma unroll
            for (int j = 0; j < 8; j++) {
                int d = lane + 32 * j;
                xb[j] = x[(size_t)row * DDIM + d] * ssc[d] + ssh[d];
            }
        }
        unsigned long long best = 0xFFFFFFFFFFFFFFFFull;
#pragma unroll 1
        for (int tile = 0; tile < 16; tile++) {
            __syncthreads();
            for (int i = tid; i < 16384; i += 256) {
                int c = i >> 8, d = i & 255;
                sE[c * 257 + d] = g_ET[(size_t)tile * 16384 + i];
            }
            __syncthreads();
            if (row >= 0) {
#pragma unroll 4
                for (int c = 0; c < 64; c++) {
                    const float* ep = sE + c * 257 + lane;
                    float dot = 0.f;
#pragma unroll
                    for (int j = 0; j < 8; j++) dot = fmaf(xb[j], ep[32 * j], dot);
#pragma unroll
                    for (int o = 16; o; o >>= 1) dot += __shfl_xor_sync(0xffffffffu, dot, o);
                    int code = tile * 64 + c;
                    float dd = scsq[code] - 2.f * dot;
                    unsigned long long pk =
                        ((unsigned long long)mono(dd) << 32) | (unsigned)code;
                    if (pk < best) best = pk;
                }
            }
        }
        if (row >= 0 && lane == 0) g_packed[row] = best;
        __syncthreads();
    }
}

// ---------------- K7: gather q, output, loss, counts, idx ------------------------
__global__ void k_quant(const int* __restrict__ mask,
                        float* __restrict__ outQ, float* __restrict__ outIdx) {
    int w = threadIdx.x >> 5, lane = threadIdx.x & 31;
    int row = blockIdx.x * 8 + w;
    int m = mask[row];
    unsigned long long pk = g_packed[row];
    int idx = (int)(pk & 0xffffffffull);
    const float4* qv = (const float4*)&g_ET[(size_t)idx * DDIM];
    float4* ov = (float4*)&outQ[(size_t)row * DDIM];
    float4 z = make_float4(0.f, 0.f, 0.f, 0.f);
#pragma unroll
    for (int t = 0; t < 2; t++) {
        int j = lane + t * 32;
        ov[j] = m ? qv[j] : z;
    }
    __shared__ float red[8];
    if (lane == 0) {
        float best = unmono((unsigned)(pk >> 32));
        red[w] = m ? (g_xsq[row] + best) : 0.f;
        outIdx[row] = m ? (float)idx : -1.f;
        if (m) atomicAdd(&g_counts[idx], 1.f);
    }
    __syncthreads();
    if (threadIdx.x == 0) {
        float t = 0.f;
        for (int i = 0; i < 8; i++) t += red[i];
        atomicAdd(&g_loss, (double)t);
    }
}

// ---------------- K8: finalize scalars -------------------------------------------
__global__ void k_final(float* __restrict__ out) {
    int t = threadIdx.x;  // 1024 threads
    float nv = fmaxf(g_cnt, 1.f);
    float p = g_counts[t] / nv;
    float h = -p * logf(p + 1e-10f);
    for (int o = 16; o; o >>= 1) h += __shfl_down_sync(0xffffffffu, h, o);
    __shared__ float red[32];
    if ((t & 31) == 0) red[t >> 5] = h;
    __syncthreads();
    if (t < 32) {
        float s = red[t];
        for (int o = 16; o; o >>= 1) s += __shfl_down_sync(0xffffffffu, s, o);
        if (t == 0) {
            float loss = (float)(g_loss / ((double)nv * (double)DDIM));
            out[OFF_DICT]   = loss;
            out[OFF_COMMIT] = loss;
            out[OFF_PERP]   = expf(s);
        }
    }
}

// ---------------- launch ------------------------------------------------------------
extern "C" void kernel_launch(void* const* d_in, const int* in_sizes, int n_in,
                              void* d_out, int out_size) {
    const float* x     = (const float*)d_in[0];
    const int*   mask  = (const int*)  d_in[1];
    const float* E     = (const float*)d_in[2];
    const float* gamma = (const float*)d_in[3];
    const float* beta  = (const float*)d_in[4];
    float* out = (float*)d_out;

    cudaFuncSetAttribute(k_coarse, cudaFuncAttributeMaxDynamicSharedMemorySize, SMEMSZ);
    cudaFuncSetAttribute(k_refine, cudaFuncAttributeMaxDynamicSharedMemorySize, RSMEM);

    k_stats<<<256, dim3(64, 4)>>>(x, mask);                  // 1
    k_prep_e<<<32, dim3(32, 8)>>>(E);                        // 2
    k_reduce_stats<<<1, 256>>>(gamma, beta);                 // 3
    k_coarse<<<148, 256, SMEMSZ>>>(x);                       // 4  (ncu lands here)
    k_select<<<128, 256>>>();                                // 5
    k_refine<<<148, 256, RSMEM>>>(x);                        // 6
    k_quant<<<BNROWS / 8, 256>>>(mask, out + OFF_Q, out + OFF_IDX);
    k_final<<<1, 1024>>>(out);
}

// round 10
// speedup vs baseline: 2.2060x; 1.4976x over previous
#include <cuda_runtime.h>
#include <cuda_fp16.h>
#include <cstdint>
#include <math.h>

// Problem dims
#define BNROWS 32768   // B*N
#define DDIM   256
#define KCODES 1024
#define THRESH 6.0f

// Output layout (float32, reference return order)
#define OFF_Q      0ull
#define OFF_DICT   8388608ull
#define OFF_COMMIT 8388609ull
#define OFF_IDX    8388610ull
#define OFF_PERP   8421378ull

// ---------------- scratch (device globals) -----------------------------------
__device__ float  g_partS [256][DDIM];
__device__ float  g_partS2[256][DDIM];
__device__ float  g_partC [256];
__device__ float  g_cnt;
__device__ __align__(16) float g_scale[DDIM];
__device__ __align__(16) float g_shift[DDIM];
__device__ __align__(16) __half g_eBh[(size_t)KCODES * DDIM]; // fp16(E^T)
__device__ __align__(16) float g_ET[(size_t)KCODES * DDIM];   // codebook^T [K][D]
__device__ __align__(16) float g_csq[KCODES];
__device__ float  g_xsq[BNROWS];
__device__ __align__(16) ulonglong2 g_tres[(size_t)BNROWS * 4]; // per (row, codeTile): {p1, m2}
__device__ unsigned long long g_packed[BNROWS];                 // (mono(d)<<32)|idx
__device__ int    g_reflist[BNROWS];
__device__ int    g_nref;
__device__ float  g_counts[KCODES];
__device__ double g_loss;
__device__ int    g_ticket;

// ---------------- helpers ------------------------------------------------------
__device__ __forceinline__ uint32_t s2u(const void* p) {
    uint32_t a;
    asm("{ .reg .u64 t; cvta.to.shared.u64 t, %1; cvt.u32.u64 %0, t; }" : "=r"(a) : "l"(p));
    return a;
}
__device__ __forceinline__ uint32_t swz(uint32_t off) { return off ^ ((off >> 3) & 0x70); }

__device__ __forceinline__ void cp16(uint32_t dst, const void* src) {
    asm volatile("cp.async.cg.shared.global [%0], [%1], 16;" :: "r"(dst), "l"(src) : "memory");
}
#define CP_COMMIT() asm volatile("cp.async.commit_group;" ::: "memory")
#define CP_WAIT(N)  asm volatile("cp.async.wait_group %0;" :: "n"(N) : "memory")

__device__ __forceinline__ void ldsm_x4(uint32_t* r, uint32_t addr) {
    asm volatile("ldmatrix.sync.aligned.m8n8.x4.shared.b16 {%0,%1,%2,%3}, [%4];"
                 : "=r"(r[0]), "=r"(r[1]), "=r"(r[2]), "=r"(r[3]) : "r"(addr));
}
__device__ __forceinline__ void ldsm_x2(uint32_t* r, uint32_t addr) {
    asm volatile("ldmatrix.sync.aligned.m8n8.x2.shared.b16 {%0,%1}, [%2];"
                 : "=r"(r[0]), "=r"(r[1]) : "r"(addr));
}
__device__ __forceinline__ void mma16816(float* c, const uint32_t* a, const uint32_t* b) {
    asm volatile(
        "mma.sync.aligned.m16n8k16.row.col.f32.f16.f16.f32 "
        "{%0,%1,%2,%3}, {%4,%5,%6,%7}, {%8,%9}, {%0,%1,%2,%3};"
        : "+f"(c[0]), "+f"(c[1]), "+f"(c[2]), "+f"(c[3])
        : "r"(a[0]), "r"(a[1]), "r"(a[2]), "r"(a[3]), "r"(b[0]), "r"(b[1]));
}
__device__ __forceinline__ unsigned mono(float d) {
    unsigned u = __float_as_uint(d);
    return ((int)u < 0) ? ~u : (u | 0x80000000u);
}
__device__ __forceinline__ float unmono(unsigned k) {
    unsigned u = (k & 0x80000000u) ? (k & 0x7fffffffu) : ~k;
    return __uint_as_float(u);
}

// ---------------- K1: masked stats partials -------------------------------------
__global__ void k_stats(const float* __restrict__ x, const int* __restrict__ mask) {
    int d4 = threadIdx.x;   // 0..63
    int ty = threadIdx.y;   // 0..3
    int b  = blockIdx.x;
    int r0 = b * 128 + ty * 32;
    const float4* x4 = (const float4*)x;
    float4 s  = make_float4(0.f, 0.f, 0.f, 0.f);
    float4 s2 = make_float4(0.f, 0.f, 0.f, 0.f);
    float  c  = 0.f;
    for (int r = 0; r < 32; r++) {
        if (mask[r0 + r]) {
            float4 v = x4[(size_t)(r0 + r) * 64 + d4];
            s.x += v.x; s.y += v.y; s.z += v.z; s.w += v.w;
            s2.x += v.x * v.x; s2.y += v.y * v.y; s2.z += v.z * v.z; s2.w += v.w * v.w;
            c += 1.f;
        }
    }
    __shared__ float4 sS[4][64], sS2[4][64];
    __shared__ float  sC[4];
    sS[ty][d4] = s; sS2[ty][d4] = s2;
    if (d4 == 0) sC[ty] = c;
    __syncthreads();
    if (ty == 0) {
        for (int y = 1; y < 4; y++) {
            float4 a = sS[y][d4], a2 = sS2[y][d4];
            s.x += a.x; s.y += a.y; s.z += a.z; s.w += a.w;
            s2.x += a2.x; s2.y += a2.y; s2.z += a2.z; s2.w += a2.w;
        }
        ((float4*)g_partS [b])[d4] = s;
        ((float4*)g_partS2[b])[d4] = s2;
        if (d4 == 0) g_partC[b] = sC[0] + sC[1] + sC[2] + sC[3];
    }
}

// ---------------- K2: transpose E + fp16 + deterministic csq ---------------------
__global__ void k_prep_e(const float* __restrict__ E) {   // grid 32, block (32,8)
    int tx = threadIdx.x;  // code local
    int ty = threadIdx.y;  // d group
    int code = blockIdx.x * 32 + tx;
    float sq = 0.f;
    for (int d = ty; d < DDIM; d += 8) {
        float v = E[(size_t)d * KCODES + code];
        g_ET [(size_t)code * DDIM + d] = v;
        g_eBh[(size_t)code * DDIM + d] = __float2half_rn(v);
        sq = fmaf(v, v, sq);
    }
    __shared__ float ssq[8][32];
    ssq[ty][tx] = sq;
    __syncthreads();
    if (ty == 0) {
        float s = 0.f;
        for (int i = 0; i < 8; i++) s += ssq[i][tx];
        g_csq[code] = s;
    }
}

// ---------------- K3: reduce stats -> scale/shift; zero run state ----------------
__global__ void k_reduce_stats(const float* __restrict__ gamma, const float* __restrict__ beta) {
    int d = threadIdx.x;
    float s = 0.f, s2 = 0.f, cnt = 0.f;
#pragma unroll 8
    for (int b = 0; b < 256; b++) {
        s  += g_partS [b][d];
        s2 += g_partS2[b][d];
        cnt += g_partC[b];
    }
    for (int i = d; i < KCODES; i += 256) g_counts[i] = 0.f;
    if (d == 0) { g_cnt = cnt; g_loss = 0.0; g_ticket = 0; g_nref = 0; }
    float nv = fmaxf(cnt, 1.f);
    float mu  = s / nv;
    float var = s2 / nv - mu * mu;
    float sc  = rsqrtf(var + 1e-5f) * gamma[d];
    g_scale[d] = sc;
    g_shift[d] = beta[d] - mu * sc;
}

// ---------------- K4: persistent 1-pass fp16 HMMA coarse GEMM + best2 ------------
#define NTILES  1024
#define NSTG    5
#define B_OFF   65536
#define CSQ_OFF (B_OFF + NSTG * 16384)    // 147456
#define XSQ_OFF (CSQ_OFF + 4096)          // 151552
#define SP1_OFF (XSQ_OFF + 1024)          // 152576  u64[128][4]
#define SM2_OFF (SP1_OFF + 4096)          // 156672  u32[128][4]
#define TK_OFF  (SM2_OFF + 2048)          // 158720
#define SMEMSZ  (TK_OFF + 16)

__global__ void __launch_bounds__(256, 1) k_coarse(const float* __restrict__ x) {
    extern __shared__ char smem[];
    const uint32_t sbA = s2u(smem);
    const uint32_t sbB = sbA + B_OFF;
    const int tid  = threadIdx.x;
    const int lane = tid & 31;
    const int wid  = tid >> 5;
    const int wm   = wid >> 2;       // 0..1
    const int wn   = wid & 3;        // 0..3

    ((float4*)(smem + CSQ_OFF))[tid] = ((const float4*)g_csq)[tid];
    int* s_tk = (int*)(smem + TK_OFF);
    float* sxsq = (float*)(smem + XSQ_OFF);
    unsigned long long* sp1 = (unsigned long long*)(smem + SP1_OFF);
    unsigned* sm2 = (unsigned*)(smem + SM2_OFF);
    const float* scsq = (const float*)(smem + CSQ_OFF);

    const int colA = tid & 63;
    const float4 scv = ((const float4*)g_scale)[colA];
    const float4 shv = ((const float4*)g_shift)[colA];

    const uint32_t aRow = (uint32_t)(wm * 64 + (lane & 15));
    const uint32_t aKG  = (uint32_t)((lane >> 4) << 4);
    const uint32_t bRow = (uint32_t)(wn * 32 + (lane & 7));
    const uint32_t bKG  = (uint32_t)(((lane >> 3) & 1) << 4);

    int cachedRow = -1;
    for (;;) {
        __syncthreads();
        if (tid == 0) *s_tk = atomicAdd(&g_ticket, 1);
        __syncthreads();
        const int tk = *s_tk;
        if (tk >= NTILES) break;
        const int rowTile  = tk >> 2;
        const int codeTile = tk & 3;
        const int rowBase  = rowTile << 7;
        const int codeBase = codeTile << 8;

        // ---- B prologue: chunks (nsub=0, kc=0..3) into stages 0..3 ----
        {
            const char* bs = (const char*)(g_eBh + (size_t)codeBase * DDIM);
#pragma unroll
            for (int c0 = 0; c0 < 4; c0++) {
#pragma unroll
                for (int v = 0; v < 4; v++) {
                    int idx = tid + v * 256;   // 0..1023
                    int r = idx >> 3, j = idx & 7;
                    cp16(sbB + c0 * 16384 + swz((r << 7) + (j << 4)),
                         bs + (size_t)r * 512 + c0 * 128 + j * 16);
                }
                CP_COMMIT();
            }
        }

        // ---- A load/convert (only when row-tile changes) ----
        if (rowTile != cachedRow) {
            cachedRow = rowTile;
            const float4* xs = (const float4*)(x + (size_t)rowBase * DDIM);
            const int kc = colA >> 4;
            const int kb = (colA & 15) * 4;
#pragma unroll 4
            for (int i = 0; i < 32; i++) {
                int m = (tid >> 6) + i * 4;
                float4 v = xs[(size_t)m * 64 + colA];
                float b0 = v.x * scv.x + shv.x;
                float b1 = v.y * scv.y + shv.y;
                float b2 = v.z * scv.z + shv.z;
                float b3 = v.w * scv.w + shv.w;
                __half2 h01 = __floats2half2_rn(b0, b1);
                __half2 h23 = __floats2half2_rn(b2, b3);
                uint32_t so = swz((uint32_t)(m << 7) + (uint32_t)kb * 2);
                asm volatile("st.shared.v2.u32 [%0], {%1,%2};"
                             :: "r"(sbA + kc * 16384 + so),
                                "r"(*(uint32_t*)&h01), "r"(*(uint32_t*)&h23));
                float s = b0 * b0 + b1 * b1 + b2 * b2 + b3 * b3;
                for (int o = 16; o; o >>= 1) s += __shfl_down_sync(0xffffffffu, s, o);
                if (lane == 0) sxsq[m * 2 + (wid & 1)] = s;
            }
            __syncthreads();
            if (tid < 128) g_xsq[rowBase + tid] = sxsq[tid * 2] + sxsq[tid * 2 + 1];
        }

        float acc[4][4][4];
        unsigned long long p1[8];
        unsigned m2[8];
#pragma unroll
        for (int s = 0; s < 8; s++) { p1[s] = 0xFFFFFFFFFFFFFFFFull; m2[s] = 0xFFFFFFFFu; }

        // ---- mainloop: 8 chunks (2 subtiles x 4 k-chunks) ----
#pragma unroll 1
        for (int c = 0; c < 8; c++) {
            const int nsub = c >> 2;
            const int kc = c & 3;
            const int stage = (c >= NSTG) ? c - NSTG : c;

            if (c <= 4)      CP_WAIT(3);
            else if (c == 5) CP_WAIT(2);
            else if (c == 6) CP_WAIT(1);
            else             CP_WAIT(0);
            __syncthreads();

            if (kc == 0) {
#pragma unroll
                for (int mf = 0; mf < 4; mf++)
#pragma unroll
                    for (int nf = 0; nf < 4; nf++)
#pragma unroll
                        for (int t = 0; t < 4; t++) acc[mf][nf][t] = 0.f;
            }

            const uint32_t bbase = sbB + stage * 16384;
            const uint32_t ah = sbA + kc * 16384;
#pragma unroll
            for (int ks = 0; ks < 4; ks++) {
                uint32_t b[4][2];
#pragma unroll
                for (int nf = 0; nf < 4; nf++)
                    ldsm_x2(b[nf], bbase + swz(((bRow + nf * 8) << 7) + ks * 32 + bKG));
                uint32_t a[4][4];
#pragma unroll
                for (int mf = 0; mf < 4; mf++)
                    ldsm_x4(a[mf], ah + swz(((aRow + mf * 16) << 7) + ks * 32 + aKG));
#pragma unroll
                for (int mf = 0; mf < 4; mf++)
#pragma unroll
                    for (int nf = 0; nf < 4; nf++)
                        mma16816(acc[mf][nf], a[mf], b[nf]);
            }

            if (kc == 3) {
                const float* csqp = scsq + codeBase + nsub * 128 + wn * 32 + 2 * (lane & 3);
#pragma unroll
                for (int nf = 0; nf < 4; nf++) {
                    float q0 = csqp[nf * 8];
                    float q1 = csqp[nf * 8 + 1];
                    int n0 = codeBase + nsub * 128 + wn * 32 + nf * 8 + 2 * (lane & 3);
#pragma unroll
                    for (int mf = 0; mf < 4; mf++) {
#pragma unroll
                        for (int h = 0; h < 2; h++) {
                            int s = mf * 2 + h;
#pragma unroll
                            for (int w = 0; w < 2; w++) {
                                float d = (w ? q1 : q0) - 2.f * acc[mf][nf][h * 2 + w];
                                unsigned mk = mono(d);
                                unsigned long long pk =
                                    ((unsigned long long)mk << 32) | (unsigned)(n0 + w);
                                if (pk < p1[s]) {
                                    m2[s] = min(m2[s], (unsigned)(p1[s] >> 32));
                                    p1[s] = pk;
                                } else {
                                    m2[s] = min(m2[s], mk);
                                }
                            }
                        }
                    }
                }
            }

            if (c + 4 < 8) {
                const int cc = c + 4;
                const int nsub2 = cc >> 2, kc2 = cc & 3;
                const int st2 = (stage + 4 >= NSTG) ? stage + 4 - NSTG : stage + 4;
                const char* bs = (const char*)(g_eBh + (size_t)(codeBase + nsub2 * 128) * DDIM);
#pragma unroll
                for (int v = 0; v < 4; v++) {
                    int idx = tid + v * 256;
                    int r = idx >> 3, j = idx & 7;
                    cp16(sbB + st2 * 16384 + swz((r << 7) + (j << 4)),
                         bs + (size_t)r * 512 + kc2 * 128 + j * 16);
                }
                CP_COMMIT();
            }
        }

        // ---- per-ticket (best1,idx,best2) reduce ----
        __syncthreads();
#pragma unroll
        for (int s = 0; s < 8; s++) {
            unsigned long long p = p1[s];
            unsigned m = m2[s];
#pragma unroll
            for (int off = 1; off <= 2; off <<= 1) {
                unsigned long long op = __shfl_xor_sync(0xffffffffu, p, off);
                unsigned om = __shfl_xor_sync(0xffffffffu, m, off);
                if (op < p) {
                    m = min(min(m, (unsigned)(p >> 32)), om);
                    p = op;
                } else {
                    m = min(min(m, (unsigned)(op >> 32)), om);
                }
            }
            if ((lane & 3) == 0) {
                int row = wm * 64 + (s >> 1) * 16 + (lane >> 2) + (s & 1) * 8;
                sp1[row * 4 + wn] = p;
                sm2[row * 4 + wn] = m;
            }
        }
        __syncthreads();
        if (tid < 128) {
            unsigned long long p = sp1[tid * 4];
            unsigned m = sm2[tid * 4];
#pragma unroll
            for (int t = 1; t < 4; t++) {
                unsigned long long op = sp1[tid * 4 + t];
                unsigned om = sm2[tid * 4 + t];
                if (op < p) {
                    m = min(min(m, (unsigned)(p >> 32)), om);
                    p = op;
                } else {
                    m = min(min(m, (unsigned)(op >> 32)), om);
                }
            }
            ulonglong2 r;
            r.x = p; r.y = (unsigned long long)m;
            g_tres[(size_t)(rowBase + tid) * 4 + codeTile] = r;
        }
    }
}

// ---------------- K5: select winners / build refine list -------------------------
__global__ void k_select() {
    int row = blockIdx.x * 256 + threadIdx.x;
    const ulonglong2* tr = &g_tres[(size_t)row * 4];
    ulonglong2 r0 = tr[0];
    unsigned long long p = r0.x;
    unsigned m = (unsigned)r0.y;
#pragma unroll
    for (int t = 1; t < 4; t++) {
        ulonglong2 rt = tr[t];
        unsigned long long op = rt.x;
        unsigned om = (unsigned)rt.y;
        if (op < p) {
            m = min(min(m, (unsigned)(p >> 32)), om);
            p = op;
        } else {
            m = min(min(m, (unsigned)(op >> 32)), om);
        }
    }
    g_packed[row] = p;
    float b1 = unmono((unsigned)(p >> 32));
    float b2 = unmono(m);
    if (b2 - b1 < THRESH) {
        int pos = atomicAdd(&g_nref, 1);
        g_reflist[pos] = row;
    }
}

// ---------------- K6: exact fp32 refine v3 (lane-per-code, no reductions) --------
// 16 rows per block (2 per warp), xb in registers. E staged per block as
// contiguous 16-d slices of the ORIGINAL d-major E (coalesced, no transpose).
// Each lane owns codes {cg*32+lane}: dot[2][32] register accumulators, one
// shfl-broadcast of xb[d] per d-slice row, 32 conflict-free LDS+2 FMA each.
#define RSMEM2 (65536 + 4096 + 2048)    // sE [16][1024] + csq + scale/shift
__global__ void __launch_bounds__(256) k_refine(const float* __restrict__ x,
                                                const float* __restrict__ E) {
    extern __shared__ char rsm[];
    float* sE   = (float*)rsm;                 // [16][1024]
    float* scsq = (float*)(rsm + 65536);       // 1024
    float* ssc  = scsq + 1024;                 // 256
    float* ssh  = ssc + 256;                   // 256
    const int tid = threadIdx.x, lane = tid & 31, w = tid >> 5;
    const int nref = g_nref;
    if (nref == 0) return;

    for (int i = tid; i < KCODES; i += 256) scsq[i] = g_csq[i];
    ssc[tid] = g_scale[tid];
    ssh[tid] = g_shift[tid];
    __syncthreads();

    for (int base = blockIdx.x * 16; base < nref; base += gridDim.x * 16) {
        int row0 = -1, row1 = -1;
        float xb0[8], xb1[8];
        if (base + w * 2 < nref) {
            row0 = g_reflist[base + w * 2];
#pragma unroll
            for (int j = 0; j < 8; j++) {
                int d = j * 32 + lane;
                xb0[j] = x[(size_t)row0 * DDIM + d] * ssc[d] + ssh[d];
            }
        }
        if (base + w * 2 + 1 < nref) {
            row1 = g_reflist[base + w * 2 + 1];
#pragma unroll
            for (int j = 0; j < 8; j++) {
                int d = j * 32 + lane;
                xb1[j] = x[(size_t)row1 * DDIM + d] * ssc[d] + ssh[d];
            }
        }
        float dot0[32], dot1[32];
#pragma unroll
        for (int cg = 0; cg < 32; cg++) { dot0[cg] = 0.f; dot1[cg] = 0.f; }

#pragma unroll 1
        for (int tile = 0; tile < 16; tile++) {
            __syncthreads();
            const float4* esrc = (const float4*)(E + (size_t)tile * 16 * KCODES);
#pragma unroll
            for (int v = 0; v < 16; v++)
                ((float4*)sE)[tid + v * 256] = esrc[tid + v * 256];
            __syncthreads();
            if (row0 >= 0) {
#pragma unroll
                for (int dl = 0; dl < 16; dl++) {
                    int d = tile * 16 + dl;
                    float xv0 = __shfl_sync(0xffffffffu, xb0[d >> 5], d & 31);
                    float xv1 = __shfl_sync(0xffffffffu, xb1[d >> 5], d & 31);
                    const float* ep = sE + dl * 1024 + lane;
#pragma unroll
                    for (int cg = 0; cg < 32; cg++) {
                        float e = ep[cg * 32];
                        dot0[cg] = fmaf(xv0, e, dot0[cg]);
                        dot1[cg] = fmaf(xv1, e, dot1[cg]);
                    }
                }
            }
        }

        if (row0 >= 0) {
            unsigned long long b0 = 0xFFFFFFFFFFFFFFFFull;
            unsigned long long b1 = 0xFFFFFFFFFFFFFFFFull;
#pragma unroll
            for (int cg = 0; cg < 32; cg++) {
                int code = cg * 32 + lane;
                float q = scsq[code];
                unsigned long long p0 =
                    ((unsigned long long)mono(q - 2.f * dot0[cg]) << 32) | (unsigned)code;
                if (p0 < b0) b0 = p0;
                unsigned long long p1 =
                    ((unsigned long long)mono(q - 2.f * dot1[cg]) << 32) | (unsigned)code;
                if (p1 < b1) b1 = p1;
            }
#pragma unroll
            for (int o = 16; o; o >>= 1) {
                unsigned long long o0 = __shfl_xor_sync(0xffffffffu, b0, o);
                unsigned long long o1 = __shfl_xor_sync(0xffffffffu, b1, o);
                if (o0 < b0) b0 = o0;
                if (o1 < b1) b1 = o1;
            }
            if (lane == 0) {
                g_packed[row0] = b0;
                if (row1 >= 0) g_packed[row1] = b1;
            }
        }
        __syncthreads();
    }
}

// ---------------- K7: gather q, output, loss, counts, idx ------------------------
__global__ void k_quant(const int* __restrict__ mask,
                        float* __restrict__ outQ, float* __restrict__ outIdx) {
    int w = threadIdx.x >> 5, lane = threadIdx.x & 31;
    int row = blockIdx.x * 8 + w;
    int m = mask[row];
    unsigned long long pk = g_packed[row];
    int idx = (int)(pk & 0xffffffffull);
    const float4* qv = (const float4*)&g_ET[(size_t)idx * DDIM];
    float4* ov = (float4*)&outQ[(size_t)row * DDIM];
    float4 z = make_float4(0.f, 0.f, 0.f, 0.f);
#pragma unroll
    for (int t = 0; t < 2; t++) {
        int j = lane + t * 32;
        ov[j] = m ? qv[j] : z;
    }
    __shared__ float red[8];
    if (lane == 0) {
        float best = unmono((unsigned)(pk >> 32));
        red[w] = m ? (g_xsq[row] + best) : 0.f;
        outIdx[row] = m ? (float)idx : -1.f;
        if (m) atomicAdd(&g_counts[idx], 1.f);
    }
    __syncthreads();
    if (threadIdx.x == 0) {
        float t = 0.f;
        for (int i = 0; i < 8; i++) t += red[i];
        atomicAdd(&g_loss, (double)t);
    }
}

// ---------------- K8: finalize scalars -------------------------------------------
__global__ void k_final(float* __restrict__ out) {
    int t = threadIdx.x;  // 1024 threads
    float nv = fmaxf(g_cnt, 1.f);
    float p = g_counts[t] / nv;
    float h = -p * logf(p + 1e-10f);
    for (int o = 16; o; o >>= 1) h += __shfl_down_sync(0xffffffffu, h, o);
    __shared__ float red[32];
    if ((t & 31) == 0) red[t >> 5] = h;
    __syncthreads();
    if (t < 32) {
        float s = red[t];
        for (int o = 16; o; o >>= 1) s += __shfl_down_sync(0xffffffffu, s, o);
        if (t == 0) {
            float loss = (float)(g_loss / ((double)nv * (double)DDIM));
            out[OFF_DICT]   = loss;
            out[OFF_COMMIT] = loss;
            out[OFF_PERP]   = expf(s);
        }
    }
}

// ---------------- launch ------------------------------------------------------------
extern "C" void kernel_launch(void* const* d_in, const int* in_sizes, int n_in,
                              void* d_out, int out_size) {
    const float* x     = (const float*)d_in[0];
    const int*   mask  = (const int*)  d_in[1];
    const float* E     = (const float*)d_in[2];
    const float* gamma = (const float*)d_in[3];
    const float* beta  = (const float*)d_in[4];
    float* out = (float*)d_out;

    cudaFuncSetAttribute(k_coarse, cudaFuncAttributeMaxDynamicSharedMemorySize, SMEMSZ);
    cudaFuncSetAttribute(k_refine, cudaFuncAttributeMaxDynamicSharedMemorySize, RSMEM2);

    k_stats<<<256, dim3(64, 4)>>>(x, mask);                  // 1
    k_prep_e<<<32, dim3(32, 8)>>>(E);                        // 2
    k_reduce_stats<<<1, 256>>>(gamma, beta);                 // 3
    k_coarse<<<148, 256, SMEMSZ>>>(x);                       // 4  (ncu lands here)
    k_select<<<128, 256>>>();                                // 5
    k_refine<<<148, 256, RSMEM2>>>(x, E);                    // 6
    k_quant<<<BNROWS / 8, 256>>>(mask, out + OFF_Q, out + OFF_IDX);
    k_final<<<1, 1024>>>(out);
}

// round 11
// speedup vs baseline: 2.2878x; 1.0371x over previous
#include <cuda_runtime.h>
#include <cuda_fp16.h>
#include <cstdint>
#include <math.h>

// Problem dims
#define BNROWS 32768   // B*N
#define DDIM   256
#define KCODES 1024
#define THRESH 6.0f

// Output layout (float32, reference return order)
#define OFF_Q      0ull
#define OFF_DICT   8388608ull
#define OFF_COMMIT 8388609ull
#define OFF_IDX    8388610ull
#define OFF_PERP   8421378ull

// ---------------- scratch (device globals) -----------------------------------
__device__ float  g_partS [256][DDIM];
__device__ float  g_partS2[256][DDIM];
__device__ float  g_partC [256];
__device__ float  g_cnt;
__device__ __align__(16) float g_scale[DDIM];
__device__ __align__(16) float g_shift[DDIM];
__device__ __align__(16) __half g_eBh[(size_t)KCODES * DDIM]; // fp16(E^T)
__device__ __align__(16) float g_ET[(size_t)KCODES * DDIM];   // codebook^T [K][D]
__device__ __align__(16) float g_csq[KCODES];
__device__ float  g_xsq[BNROWS];
__device__ __align__(16) ulonglong2 g_tres[(size_t)BNROWS * 4]; // per (row, codeTile): {p1, m2}
__device__ unsigned long long g_packed[BNROWS];                 // (mono(d)<<32)|idx
__device__ int    g_reflist[BNROWS];
__device__ int    g_nref;
__device__ float  g_counts[KCODES];
__device__ double g_loss;
__device__ int    g_ticket;

// ---------------- helpers ------------------------------------------------------
__device__ __forceinline__ uint32_t s2u(const void* p) {
    uint32_t a;
    asm("{ .reg .u64 t; cvta.to.shared.u64 t, %1; cvt.u32.u64 %0, t; }" : "=r"(a) : "l"(p));
    return a;
}
__device__ __forceinline__ uint32_t swz(uint32_t off) { return off ^ ((off >> 3) & 0x70); }

__device__ __forceinline__ void cp16(uint32_t dst, const void* src) {
    asm volatile("cp.async.cg.shared.global [%0], [%1], 16;" :: "r"(dst), "l"(src) : "memory");
}
#define CP_COMMIT() asm volatile("cp.async.commit_group;" ::: "memory")
#define CP_WAIT(N)  asm volatile("cp.async.wait_group %0;" :: "n"(N) : "memory")

__device__ __forceinline__ void ldsm_x4(uint32_t* r, uint32_t addr) {
    asm volatile("ldmatrix.sync.aligned.m8n8.x4.shared.b16 {%0,%1,%2,%3}, [%4];"
                 : "=r"(r[0]), "=r"(r[1]), "=r"(r[2]), "=r"(r[3]) : "r"(addr));
}
__device__ __forceinline__ void mma16816(float* c, const uint32_t* a, const uint32_t* b) {
    asm volatile(
        "mma.sync.aligned.m16n8k16.row.col.f32.f16.f16.f32 "
        "{%0,%1,%2,%3}, {%4,%5,%6,%7}, {%8,%9}, {%0,%1,%2,%3};"
        : "+f"(c[0]), "+f"(c[1]), "+f"(c[2]), "+f"(c[3])
        : "r"(a[0]), "r"(a[1]), "r"(a[2]), "r"(a[3]), "r"(b[0]), "r"(b[1]));
}
__device__ __forceinline__ unsigned mono(float d) {
    unsigned u = __float_as_uint(d);
    return ((int)u < 0) ? ~u : (u | 0x80000000u);
}
__device__ __forceinline__ float unmono(unsigned k) {
    unsigned u = (k & 0x80000000u) ? (k & 0x7fffffffu) : ~k;
    return __uint_as_float(u);
}

// ---------------- K1: masked stats partials -------------------------------------
__global__ void k_stats(const float* __restrict__ x, const int* __restrict__ mask) {
    int d4 = threadIdx.x;   // 0..63
    int ty = threadIdx.y;   // 0..3
    int b  = blockIdx.x;
    int r0 = b * 128 + ty * 32;
    const float4* x4 = (const float4*)x;
    float4 s  = make_float4(0.f, 0.f, 0.f, 0.f);
    float4 s2 = make_float4(0.f, 0.f, 0.f, 0.f);
    float  c  = 0.f;
    for (int r = 0; r < 32; r++) {
        if (mask[r0 + r]) {
            float4 v = x4[(size_t)(r0 + r) * 64 + d4];
            s.x += v.x; s.y += v.y; s.z += v.z; s.w += v.w;
            s2.x += v.x * v.x; s2.y += v.y * v.y; s2.z += v.z * v.z; s2.w += v.w * v.w;
            c += 1.f;
        }
    }
    __shared__ float4 sS[4][64], sS2[4][64];
    __shared__ float  sC[4];
    sS[ty][d4] = s; sS2[ty][d4] = s2;
    if (d4 == 0) sC[ty] = c;
    __syncthreads();
    if (ty == 0) {
        for (int y = 1; y < 4; y++) {
            float4 a = sS[y][d4], a2 = sS2[y][d4];
            s.x += a.x; s.y += a.y; s.z += a.z; s.w += a.w;
            s2.x += a2.x; s2.y += a2.y; s2.z += a2.z; s2.w += a2.w;
        }
        ((float4*)g_partS [b])[d4] = s;
        ((float4*)g_partS2[b])[d4] = s2;
        if (d4 == 0) g_partC[b] = sC[0] + sC[1] + sC[2] + sC[3];
    }
}

// ---------------- K2: transpose E + fp16 + deterministic csq ---------------------
__global__ void k_prep_e(const float* __restrict__ E) {   // grid 32, block (32,8)
    int tx = threadIdx.x;  // code local
    int ty = threadIdx.y;  // d group
    int code = blockIdx.x * 32 + tx;
    float sq = 0.f;
    for (int d = ty; d < DDIM; d += 8) {
        float v = E[(size_t)d * KCODES + code];
        g_ET [(size_t)code * DDIM + d] = v;
        g_eBh[(size_t)code * DDIM + d] = __float2half_rn(v);
        sq = fmaf(v, v, sq);
    }
    __shared__ float ssq[8][32];
    ssq[ty][tx] = sq;
    __syncthreads();
    if (ty == 0) {
        float s = 0.f;
        for (int i = 0; i < 8; i++) s += ssq[i][tx];
        g_csq[code] = s;
    }
}

// ---------------- K3: reduce stats -> scale/shift; zero run state ----------------
__global__ void k_reduce_stats(const float* __restrict__ gamma, const float* __restrict__ beta) {
    int d = threadIdx.x;
    float s = 0.f, s2 = 0.f, cnt = 0.f;
#pragma unroll 8
    for (int b = 0; b < 256; b++) {
        s  += g_partS [b][d];
        s2 += g_partS2[b][d];
        cnt += g_partC[b];
    }
    for (int i = d; i < KCODES; i += 256) g_counts[i] = 0.f;
    if (d == 0) { g_cnt = cnt; g_loss = 0.0; g_ticket = 0; g_nref = 0; }
    float nv = fmaxf(cnt, 1.f);
    float mu  = s / nv;
    float var = s2 / nv - mu * mu;
    float sc  = rsqrtf(var + 1e-5f) * gamma[d];
    g_scale[d] = sc;
    g_shift[d] = beta[d] - mu * sc;
}

// ---------------- K4: persistent 1-pass fp16 HMMA coarse GEMM + best2 ------------
// 512 threads = 16 warps (4m x 4n), warp tile 32x32 -> 4 warps/SMSP to hide
// HMMA + ldsm latency (R10: 2 warps/SMSP left tensor pipe at 24.7%).
#define NTILES  1024
#define NSTG    5
#define B_OFF   65536
#define CSQ_OFF (B_OFF + NSTG * 16384)    // 147456
#define XSQ_OFF (CSQ_OFF + 4096)          // 151552
#define SP1_OFF (XSQ_OFF + 1024)          // 152576  u64[128][4]
#define SM2_OFF (SP1_OFF + 4096)          // 156672  u32[128][4]
#define TK_OFF  (SM2_OFF + 2048)          // 158720
#define SMEMSZ  (TK_OFF + 16)

__global__ void __launch_bounds__(512, 1) k_coarse(const float* __restrict__ x) {
    extern __shared__ char smem[];
    const uint32_t sbA = s2u(smem);
    const uint32_t sbB = sbA + B_OFF;
    const int tid  = threadIdx.x;
    const int lane = tid & 31;
    const int wid  = tid >> 5;
    const int wm   = wid >> 2;       // 0..3
    const int wn   = wid & 3;        // 0..3

    if (tid < 256)
        ((float4*)(smem + CSQ_OFF))[tid] = ((const float4*)g_csq)[tid];
    int* s_tk = (int*)(smem + TK_OFF);
    float* sxsq = (float*)(smem + XSQ_OFF);
    unsigned long long* sp1 = (unsigned long long*)(smem + SP1_OFF);
    unsigned* sm2 = (unsigned*)(smem + SM2_OFF);
    const float* scsq = (const float*)(smem + CSQ_OFF);

    const int colA = tid & 63;
    const float4 scv = ((const float4*)g_scale)[colA];
    const float4 shv = ((const float4*)g_shift)[colA];

    // A frags: rows wm*32 + mf*16 + aM
    const uint32_t aM  = (uint32_t)((lane & 7) + 8 * ((lane >> 3) & 1));
    const uint32_t aKG = (uint32_t)((lane >> 4) << 4);
    // B frags via ldsm_x4: rows wn*32 + np*16 + bN -> frags np*2, np*2+1
    const uint32_t bN  = (uint32_t)(((lane >> 4) << 3) + (lane & 7));
    const uint32_t bKG = (uint32_t)(((lane >> 3) & 1) << 4);

    int cachedRow = -1;
    for (;;) {
        __syncthreads();
        if (tid == 0) *s_tk = atomicAdd(&g_ticket, 1);
        __syncthreads();
        const int tk = *s_tk;
        if (tk >= NTILES) break;
        const int rowTile  = tk >> 2;
        const int codeTile = tk & 3;
        const int rowBase  = rowTile << 7;
        const int codeBase = codeTile << 8;

        // ---- B prologue: chunks (nsub=0, kc=0..3) into stages 0..3 ----
        {
            const char* bs = (const char*)(g_eBh + (size_t)codeBase * DDIM);
#pragma unroll
            for (int c0 = 0; c0 < 4; c0++) {
#pragma unroll
                for (int v = 0; v < 2; v++) {
                    int idx = tid + v * 512;   // 0..1023
                    int r = idx >> 3, j = idx & 7;
                    cp16(sbB + c0 * 16384 + swz((r << 7) + (j << 4)),
                         bs + (size_t)r * 512 + c0 * 128 + j * 16);
                }
                CP_COMMIT();
            }
        }

        // ---- A load/convert (only when row-tile changes) ----
        if (rowTile != cachedRow) {
            cachedRow = rowTile;
            const float4* xs = (const float4*)(x + (size_t)rowBase * DDIM);
            const int kc = colA >> 4;
            const int kb = (colA & 15) * 4;
#pragma unroll 4
            for (int i = 0; i < 16; i++) {
                int m = (tid >> 6) + i * 8;
                float4 v = xs[(size_t)m * 64 + colA];
                float b0 = v.x * scv.x + shv.x;
                float b1 = v.y * scv.y + shv.y;
                float b2 = v.z * scv.z + shv.z;
                float b3 = v.w * scv.w + shv.w;
                __half2 h01 = __floats2half2_rn(b0, b1);
                __half2 h23 = __floats2half2_rn(b2, b3);
                uint32_t so = swz((uint32_t)(m << 7) + (uint32_t)kb * 2);
                asm volatile("st.shared.v2.u32 [%0], {%1,%2};"
                             :: "r"(sbA + kc * 16384 + so),
                                "r"(*(uint32_t*)&h01), "r"(*(uint32_t*)&h23));
                float s = b0 * b0 + b1 * b1 + b2 * b2 + b3 * b3;
                for (int o = 16; o; o >>= 1) s += __shfl_down_sync(0xffffffffu, s, o);
                if (lane == 0) sxsq[m * 2 + (wid & 1)] = s;
            }
            __syncthreads();
            if (tid < 128) g_xsq[rowBase + tid] = sxsq[tid * 2] + sxsq[tid * 2 + 1];
        }

        float acc[2][4][4];
        unsigned long long p1[4];
        unsigned m2[4];
#pragma unroll
        for (int s = 0; s < 4; s++) { p1[s] = 0xFFFFFFFFFFFFFFFFull; m2[s] = 0xFFFFFFFFu; }

        // ---- mainloop: 8 chunks (2 subtiles x 4 k-chunks) ----
#pragma unroll 1
        for (int c = 0; c < 8; c++) {
            const int nsub = c >> 2;
            const int kc = c & 3;
            const int stage = (c >= NSTG) ? c - NSTG : c;

            if (c <= 4)      CP_WAIT(3);
            else if (c == 5) CP_WAIT(2);
            else if (c == 6) CP_WAIT(1);
            else             CP_WAIT(0);
            __syncthreads();

            if (kc == 0) {
#pragma unroll
                for (int mf = 0; mf < 2; mf++)
#pragma unroll
                    for (int nf = 0; nf < 4; nf++)
#pragma unroll
                        for (int t = 0; t < 4; t++) acc[mf][nf][t] = 0.f;
            }

            const uint32_t bbase = sbB + stage * 16384;
            const uint32_t ah = sbA + kc * 16384;
#pragma unroll
            for (int ks = 0; ks < 4; ks++) {
                uint32_t b[4][2];
#pragma unroll
                for (int np = 0; np < 2; np++) {
                    uint32_t bb[4];
                    ldsm_x4(bb, bbase + swz(((wn * 32 + np * 16 + bN) << 7) + ks * 32 + bKG));
                    b[np * 2][0] = bb[0]; b[np * 2][1] = bb[1];
                    b[np * 2 + 1][0] = bb[2]; b[np * 2 + 1][1] = bb[3];
                }
                uint32_t a[2][4];
#pragma unroll
                for (int mf = 0; mf < 2; mf++)
                    ldsm_x4(a[mf], ah + swz(((wm * 32 + mf * 16 + aM) << 7) + ks * 32 + aKG));
#pragma unroll
                for (int mf = 0; mf < 2; mf++)
#pragma unroll
                    for (int nf = 0; nf < 4; nf++)
                        mma16816(acc[mf][nf], a[mf], b[nf]);
            }

            if (kc == 3) {
                const float* csqp = scsq + codeBase + nsub * 128 + wn * 32 + 2 * (lane & 3);
#pragma unroll
                for (int nf = 0; nf < 4; nf++) {
                    float q0 = csqp[nf * 8];
                    float q1 = csqp[nf * 8 + 1];
                    int n0 = codeBase + nsub * 128 + wn * 32 + nf * 8 + 2 * (lane & 3);
#pragma unroll
                    for (int mf = 0; mf < 2; mf++) {
#pragma unroll
                        for (int h = 0; h < 2; h++) {
                            int s = mf * 2 + h;
#pragma unroll
                            for (int w = 0; w < 2; w++) {
                                float d = (w ? q1 : q0) - 2.f * acc[mf][nf][h * 2 + w];
                                unsigned mk = mono(d);
                                unsigned long long pk =
                                    ((unsigned long long)mk << 32) | (unsigned)(n0 + w);
                                if (pk < p1[s]) {
                                    m2[s] = min(m2[s], (unsigned)(p1[s] >> 32));
                                    p1[s] = pk;
                                } else {
                                    m2[s] = min(m2[s], mk);
                                }
                            }
                        }
                    }
                }
            }

            if (c + 4 < 8) {
                const int cc = c + 4;
                const int nsub2 = cc >> 2, kc2 = cc & 3;
                const int st2 = (stage + 4 >= NSTG) ? stage + 4 - NSTG : stage + 4;
                const char* bs = (const char*)(g_eBh + (size_t)(codeBase + nsub2 * 128) * DDIM);
#pragma unroll
                for (int v = 0; v < 2; v++) {
                    int idx = tid + v * 512;
                    int r = idx >> 3, j = idx & 7;
                    cp16(sbB + st2 * 16384 + swz((r << 7) + (j << 4)),
                         bs + (size_t)r * 512 + kc2 * 128 + j * 16);
                }
                CP_COMMIT();
            }
        }

        // ---- per-ticket (best1,idx,best2) reduce ----
        __syncthreads();
#pragma unroll
        for (int s = 0; s < 4; s++) {
            unsigned long long p = p1[s];
            unsigned m = m2[s];
#pragma unroll
            for (int off = 1; off <= 2; off <<= 1) {
                unsigned long long op = __shfl_xor_sync(0xffffffffu, p, off);
                unsigned om = __shfl_xor_sync(0xffffffffu, m, off);
                if (op < p) {
                    m = min(min(m, (unsigned)(p >> 32)), om);
                    p = op;
                } else {
                    m = min(min(m, (unsigned)(op >> 32)), om);
                }
            }
            if ((lane & 3) == 0) {
                int row = wm * 32 + (s >> 1) * 16 + (lane >> 2) + (s & 1) * 8;
                sp1[row * 4 + wn] = p;
                sm2[row * 4 + wn] = m;
            }
        }
        __syncthreads();
        if (tid < 128) {
            unsigned long long p = sp1[tid * 4];
            unsigned m = sm2[tid * 4];
#pragma unroll
            for (int t = 1; t < 4; t++) {
                unsigned long long op = sp1[tid * 4 + t];
                unsigned om = sm2[tid * 4 + t];
                if (op < p) {
                    m = min(min(m, (unsigned)(p >> 32)), om);
                    p = op;
                } else {
                    m = min(min(m, (unsigned)(op >> 32)), om);
                }
            }
            ulonglong2 r;
            r.x = p; r.y = (unsigned long long)m;
            g_tres[(size_t)(rowBase + tid) * 4 + codeTile] = r;
        }
    }
}

// ---------------- K5: select winners / build refine list -------------------------
__global__ void k_select() {
    int row = blockIdx.x * 256 + threadIdx.x;
    const ulonglong2* tr = &g_tres[(size_t)row * 4];
    ulonglong2 r0 = tr[0];
    unsigned long long p = r0.x;
    unsigned m = (unsigned)r0.y;
#pragma unroll
    for (int t = 1; t < 4; t++) {
        ulonglong2 rt = tr[t];
        unsigned long long op = rt.x;
        unsigned om = (unsigned)rt.y;
        if (op < p) {
            m = min(min(m, (unsigned)(p >> 32)), om);
            p = op;
        } else {
            m = min(min(m, (unsigned)(op >> 32)), om);
        }
    }
    g_packed[row] = p;
    float b1 = unmono((unsigned)(p >> 32));
    float b2 = unmono(m);
    if (b2 - b1 < THRESH) {
        int pos = atomicAdd(&g_nref, 1);
        g_reflist[pos] = row;
    }
}

// ---------------- K6: exact fp32 refine v3 (lane-per-code, no reductions) --------
#define RSMEM2 (65536 + 4096 + 2048)    // sE [16][1024] + csq + scale/shift
__global__ void __launch_bounds__(256) k_refine(const float* __restrict__ x,
                                                const float* __restrict__ E) {
    extern __shared__ char rsm[];
    float* sE   = (float*)rsm;                 // [16][1024]
    float* scsq = (float*)(rsm + 65536);       // 1024
    float* ssc  = scsq + 1024;                 // 256
    float* ssh  = ssc + 256;                   // 256
    const int tid = threadIdx.x, lane = tid & 31, w = tid >> 5;
    const int nref = g_nref;
    if (nref == 0) return;

    for (int i = tid; i < KCODES; i += 256) scsq[i] = g_csq[i];
    ssc[tid] = g_scale[tid];
    ssh[tid] = g_shift[tid];
    __syncthreads();

    for (int base = blockIdx.x * 16; base < nref; base += gridDim.x * 16) {
        int row0 = -1, row1 = -1;
        float xb0[8], xb1[8];
        if (base + w * 2 < nref) {
            row0 = g_reflist[base + w * 2];
#pragma unroll
            for (int j = 0; j < 8; j++) {
                int d = j * 32 + lane;
                xb0[j] = x[(size_t)row0 * DDIM + d] * ssc[d] + ssh[d];
            }
        }
        if (base + w * 2 + 1 < nref) {
            row1 = g_reflist[base + w * 2 + 1];
#pragma unroll
            for (int j = 0; j < 8; j++) {
                int d = j * 32 + lane;
                xb1[j] = x[(size_t)row1 * DDIM + d] * ssc[d] + ssh[d];
            }
        }
        float dot0[32], dot1[32];
#pragma unroll
        for (int cg = 0; cg < 32; cg++) { dot0[cg] = 0.f; dot1[cg] = 0.f; }

#pragma unroll 1
        for (int tile = 0; tile < 16; tile++) {
            __syncthreads();
            const float4* esrc = (const float4*)(E + (size_t)tile * 16 * KCODES);
#pragma unroll
            for (int v = 0; v < 16; v++)
                ((float4*)sE)[tid + v * 256] = esrc[tid + v * 256];
            __syncthreads();
            if (row0 >= 0) {
#pragma unroll
                for (int dl = 0; dl < 16; dl++) {
                    int d = tile * 16 + dl;
                    float xv0 = __shfl_sync(0xffffffffu, xb0[d >> 5], d & 31);
                    float xv1 = __shfl_sync(0xffffffffu, xb1[d >> 5], d & 31);
                    const float* ep = sE + dl * 1024 + lane;
#pragma unroll
                    for (int cg = 0; cg < 32; cg++) {
                        float e = ep[cg * 32];
                        dot0[cg] = fmaf(xv0, e, dot0[cg]);
                        dot1[cg] = fmaf(xv1, e, dot1[cg]);
                    }
                }
            }
        }

        if (row0 >= 0) {
            unsigned long long b0 = 0xFFFFFFFFFFFFFFFFull;
            unsigned long long b1 = 0xFFFFFFFFFFFFFFFFull;
#pragma unroll
            for (int cg = 0; cg < 32; cg++) {
                int code = cg * 32 + lane;
                float q = scsq[code];
                unsigned long long p0 =
                    ((unsigned long long)mono(q - 2.f * dot0[cg]) << 32) | (unsigned)code;
                if (p0 < b0) b0 = p0;
                unsigned long long p1 =
                    ((unsigned long long)mono(q - 2.f * dot1[cg]) << 32) | (unsigned)code;
                if (p1 < b1) b1 = p1;
            }
#pragma unroll
            for (int o = 16; o; o >>= 1) {
                unsigned long long o0 = __shfl_xor_sync(0xffffffffu, b0, o);
                unsigned long long o1 = __shfl_xor_sync(0xffffffffu, b1, o);
                if (o0 < b0) b0 = o0;
                if (o1 < b1) b1 = o1;
            }
            if (lane == 0) {
                g_packed[row0] = b0;
                if (row1 >= 0) g_packed[row1] = b1;
            }
        }
        __syncthreads();
    }
}

// ---------------- K7: gather q, output, loss, counts, idx ------------------------
__global__ void k_quant(const int* __restrict__ mask,
                        float* __restrict__ outQ, float* __restrict__ outIdx) {
    int w = threadIdx.x >> 5, lane = threadIdx.x & 31;
    int row = blockIdx.x * 8 + w;
    int m = mask[row];
    unsigned long long pk = g_packed[row];
    int idx = (int)(pk & 0xffffffffull);
    const float4* qv = (const float4*)&g_ET[(size_t)idx * DDIM];
    float4* ov = (float4*)&outQ[(size_t)row * DDIM];
    float4 z = make_float4(0.f, 0.f, 0.f, 0.f);
#pragma unroll
    for (int t = 0; t < 2; t++) {
        int j = lane + t * 32;
        ov[j] = m ? qv[j] : z;
    }
    __shared__ float red[8];
    if (lane == 0) {
        float best = unmono((unsigned)(pk >> 32));
        red[w] = m ? (g_xsq[row] + best) : 0.f;
        outIdx[row] = m ? (float)idx : -1.f;
        if (m) atomicAdd(&g_counts[idx], 1.f);
    }
    __syncthreads();
    if (threadIdx.x == 0) {
        float t = 0.f;
        for (int i = 0; i < 8; i++) t += red[i];
        atomicAdd(&g_loss, (double)t);
    }
}

// ---------------- K8: finalize scalars -------------------------------------------
__global__ void k_final(float* __restrict__ out) {
    int t = threadIdx.x;  // 1024 threads
    float nv = fmaxf(g_cnt, 1.f);
    float p = g_counts[t] / nv;
    float h = -p * logf(p + 1e-10f);
    for (int o = 16; o; o >>= 1) h += __shfl_down_sync(0xffffffffu, h, o);
    __shared__ float red[32];
    if ((t & 31) == 0) red[t >> 5] = h;
    __syncthreads();
    if (t < 32) {
        float s = red[t];
        for (int o = 16; o; o >>= 1) s += __shfl_down_sync(0xffffffffu, s, o);
        if (t == 0) {
            float loss = (float)(g_loss / ((double)nv * (double)DDIM));
            out[OFF_DICT]   = loss;
            out[OFF_COMMIT] = loss;
            out[OFF_PERP]   = expf(s);
        }
    }
}

// ---------------- launch ------------------------------------------------------------
extern "C" void kernel_launch(void* const* d_in, const int* in_sizes, int n_in,
                              void* d_out, int out_size) {
    const float* x     = (const float*)d_in[0];
    const int*   mask  = (const int*)  d_in[1];
    const float* E     = (const float*)d_in[2];
    const float* gamma = (const float*)d_in[3];
    const float* beta  = (const float*)d_in[4];
    float* out = (float*)d_out;

    cudaFuncSetAttribute(k_coarse, cudaFuncAttributeMaxDynamicSharedMemorySize, SMEMSZ);
    cudaFuncSetAttribute(k_refine, cudaFuncAttributeMaxDynamicSharedMemorySize, RSMEM2);

    k_stats<<<256, dim3(64, 4)>>>(x, mask);                  // 1
    k_prep_e<<<32, dim3(32, 8)>>>(E);                        // 2
    k_reduce_stats<<<1, 256>>>(gamma, beta);                 // 3
    k_coarse<<<148, 512, SMEMSZ>>>(x);                       // 4  (ncu lands here)
    k_select<<<128, 256>>>();                                // 5
    k_refine<<<148, 256, RSMEM2>>>(x, E);                    // 6
    k_quant<<<BNROWS / 8, 256>>>(mask, out + OFF_Q, out + OFF_IDX);
    k_final<<<1, 1024>>>(out);
}

// round 12
// speedup vs baseline: 2.6214x; 1.1458x over previous
#include <cuda_runtime.h>
#include <cuda_fp16.h>
#include <cstdint>
#include <math.h>

// Problem dims
#define BNROWS 32768   // B*N
#define DDIM   256
#define KCODES 1024
#define THRESH 6.0f

// Output layout (float32, reference return order)
#define OFF_Q      0ull
#define OFF_DICT   8388608ull
#define OFF_COMMIT 8388609ull
#define OFF_IDX    8388610ull
#define OFF_PERP   8421378ull

// ---------------- scratch (device globals) -----------------------------------
__device__ float  g_partS [256][DDIM];
__device__ float  g_partS2[256][DDIM];
__device__ float  g_partC [256];
__device__ float  g_cnt;
__device__ __align__(16) float g_scale[DDIM];
__device__ __align__(16) float g_shift[DDIM];
__device__ __align__(16) __half g_eB2[(size_t)KCODES * 512]; // [e_h(256) | e_l(256)] per code
__device__ __align__(16) float g_ET[(size_t)KCODES * DDIM];  // codebook^T [K][D]
__device__ __align__(16) float g_csq[KCODES];
__device__ float  g_xsq[BNROWS];
__device__ __align__(16) ulonglong2 g_tres[(size_t)BNROWS * 4]; // per (row, codeTile): {p1, m2}
__device__ unsigned long long g_packed[BNROWS];                 // (mono(d)<<32)|idx
__device__ int    g_reflist[BNROWS];
__device__ int    g_nref;
__device__ float  g_counts[KCODES];
__device__ double g_loss;
__device__ int    g_ticket;

// ---------------- helpers ------------------------------------------------------
__device__ __forceinline__ uint32_t s2u(const void* p) {
    uint32_t a;
    asm("{ .reg .u64 t; cvta.to.shared.u64 t, %1; cvt.u32.u64 %0, t; }" : "=r"(a) : "l"(p));
    return a;
}
__device__ __forceinline__ uint32_t swz(uint32_t off) { return off ^ ((off >> 3) & 0x70); }

__device__ __forceinline__ void cp16(uint32_t dst, const void* src) {
    asm volatile("cp.async.cg.shared.global [%0], [%1], 16;" :: "r"(dst), "l"(src) : "memory");
}
#define CP_COMMIT() asm volatile("cp.async.commit_group;" ::: "memory")
#define CP_WAIT(N)  asm volatile("cp.async.wait_group %0;" :: "n"(N) : "memory")

__device__ __forceinline__ void ldsm_x4(uint32_t* r, uint32_t addr) {
    asm volatile("ldmatrix.sync.aligned.m8n8.x4.shared.b16 {%0,%1,%2,%3}, [%4];"
                 : "=r"(r[0]), "=r"(r[1]), "=r"(r[2]), "=r"(r[3]) : "r"(addr));
}
__device__ __forceinline__ void mma16816(float* c, const uint32_t* a, const uint32_t* b) {
    asm volatile(
        "mma.sync.aligned.m16n8k16.row.col.f32.f16.f16.f32 "
        "{%0,%1,%2,%3}, {%4,%5,%6,%7}, {%8,%9}, {%0,%1,%2,%3};"
        : "+f"(c[0]), "+f"(c[1]), "+f"(c[2]), "+f"(c[3])
        : "r"(a[0]), "r"(a[1]), "r"(a[2]), "r"(a[3]), "r"(b[0]), "r"(b[1]));
}
__device__ __forceinline__ unsigned mono(float d) {
    unsigned u = __float_as_uint(d);
    return ((int)u < 0) ? ~u : (u | 0x80000000u);
}
__device__ __forceinline__ float unmono(unsigned k) {
    unsigned u = (k & 0x80000000u) ? (k & 0x7fffffffu) : ~k;
    return __uint_as_float(u);
}

// ---------------- K1: masked stats partials -------------------------------------
__global__ void k_stats(const float* __restrict__ x, const int* __restrict__ mask) {
    int d4 = threadIdx.x;   // 0..63
    int ty = threadIdx.y;   // 0..3
    int b  = blockIdx.x;
    int r0 = b * 128 + ty * 32;
    const float4* x4 = (const float4*)x;
    float4 s  = make_float4(0.f, 0.f, 0.f, 0.f);
    float4 s2 = make_float4(0.f, 0.f, 0.f, 0.f);
    float  c  = 0.f;
    for (int r = 0; r < 32; r++) {
        if (mask[r0 + r]) {
            float4 v = x4[(size_t)(r0 + r) * 64 + d4];
            s.x += v.x; s.y += v.y; s.z += v.z; s.w += v.w;
            s2.x += v.x * v.x; s2.y += v.y * v.y; s2.z += v.z * v.z; s2.w += v.w * v.w;
            c += 1.f;
        }
    }
    __shared__ float4 sS[4][64], sS2[4][64];
    __shared__ float  sC[4];
    sS[ty][d4] = s; sS2[ty][d4] = s2;
    if (d4 == 0) sC[ty] = c;
    __syncthreads();
    if (ty == 0) {
        for (int y = 1; y < 4; y++) {
            float4 a = sS[y][d4], a2 = sS2[y][d4];
            s.x += a.x; s.y += a.y; s.z += a.z; s.w += a.w;
            s2.x += a2.x; s2.y += a2.y; s2.z += a2.z; s2.w += a2.w;
        }
        ((float4*)g_partS [b])[d4] = s;
        ((float4*)g_partS2[b])[d4] = s2;
        if (d4 == 0) g_partC[b] = sC[0] + sC[1] + sC[2] + sC[3];
    }
}

// ---------------- K2: transpose E + fp16 hi/lo + deterministic csq ---------------
__global__ void k_prep_e(const float* __restrict__ E) {   // grid 32, block (32,8)
    int tx = threadIdx.x;  // code local
    int ty = threadIdx.y;  // d group
    int code = blockIdx.x * 32 + tx;
    float sq = 0.f;
    for (int d = ty; d < DDIM; d += 8) {
        float v = E[(size_t)d * KCODES + code];
        g_ET[(size_t)code * DDIM + d] = v;
        __half h = __float2half_rn(v);
        g_eB2[(size_t)code * 512 + d]       = h;
        g_eB2[(size_t)code * 512 + 256 + d] = __float2half_rn(v - __half2float(h));
        sq = fmaf(v, v, sq);
    }
    __shared__ float ssq[8][32];
    ssq[ty][tx] = sq;
    __syncthreads();
    if (ty == 0) {
        float s = 0.f;
        for (int i = 0; i < 8; i++) s += ssq[i][tx];
        g_csq[code] = s;
    }
}

// ---------------- K3: reduce stats -> scale/shift; zero run state ----------------
__global__ void k_reduce_stats(const float* __restrict__ gamma, const float* __restrict__ beta) {
    int d = threadIdx.x;
    float s = 0.f, s2 = 0.f, cnt = 0.f;
#pragma unroll 8
    for (int b = 0; b < 256; b++) {
        s  += g_partS [b][d];
        s2 += g_partS2[b][d];
        cnt += g_partC[b];
    }
    for (int i = d; i < KCODES; i += 256) g_counts[i] = 0.f;
    if (d == 0) { g_cnt = cnt; g_loss = 0.0; g_ticket = 0; g_nref = 0; }
    float nv = fmaxf(cnt, 1.f);
    float mu  = s / nv;
    float var = s2 / nv - mu * mu;
    float sc  = rsqrtf(var + 1e-5f) * gamma[d];
    g_scale[d] = sc;
    g_shift[d] = beta[d] - mu * sc;
}

// ---------------- K4: persistent 1-pass fp16 HMMA coarse GEMM + best2 ------------
#define NTILES  1024
#define NSTG    5
#define B_OFF   65536
#define CSQ_OFF (B_OFF + NSTG * 16384)    // 147456
#define XSQ_OFF (CSQ_OFF + 4096)          // 151552
#define SP1_OFF (XSQ_OFF + 1024)          // 152576  u64[128][4]
#define SM2_OFF (SP1_OFF + 4096)          // 156672  u32[128][4]
#define TK_OFF  (SM2_OFF + 2048)          // 158720
#define SMEMSZ  (TK_OFF + 16)

__global__ void __launch_bounds__(512, 1) k_coarse(const float* __restrict__ x) {
    extern __shared__ char smem[];
    const uint32_t sbA = s2u(smem);
    const uint32_t sbB = sbA + B_OFF;
    const int tid  = threadIdx.x;
    const int lane = tid & 31;
    const int wid  = tid >> 5;
    const int wm   = wid >> 2;       // 0..3
    const int wn   = wid & 3;        // 0..3

    if (tid < 256)
        ((float4*)(smem + CSQ_OFF))[tid] = ((const float4*)g_csq)[tid];
    int* s_tk = (int*)(smem + TK_OFF);
    float* sxsq = (float*)(smem + XSQ_OFF);
    unsigned long long* sp1 = (unsigned long long*)(smem + SP1_OFF);
    unsigned* sm2 = (unsigned*)(smem + SM2_OFF);
    const float* scsq = (const float*)(smem + CSQ_OFF);

    const int colA = tid & 63;
    const float4 scv = ((const float4*)g_scale)[colA];
    const float4 shv = ((const float4*)g_shift)[colA];

    const uint32_t aM  = (uint32_t)((lane & 7) + 8 * ((lane >> 3) & 1));
    const uint32_t aKG = (uint32_t)((lane >> 4) << 4);
    const uint32_t bN  = (uint32_t)(((lane >> 4) << 3) + (lane & 7));
    const uint32_t bKG = (uint32_t)(((lane >> 3) & 1) << 4);

    int cachedRow = -1;
    for (;;) {
        __syncthreads();
        if (tid == 0) *s_tk = atomicAdd(&g_ticket, 1);
        __syncthreads();
        const int tk = *s_tk;
        if (tk >= NTILES) break;
        const int rowTile  = tk >> 2;
        const int codeTile = tk & 3;
        const int rowBase  = rowTile << 7;
        const int codeBase = codeTile << 8;

        // ---- B prologue: chunks (nsub=0, kc=0..3) into stages 0..3 (eh half) ----
        {
            const char* bs = (const char*)(g_eB2 + (size_t)codeBase * 512);
#pragma unroll
            for (int c0 = 0; c0 < 4; c0++) {
#pragma unroll
                for (int v = 0; v < 2; v++) {
                    int idx = tid + v * 512;   // 0..1023
                    int r = idx >> 3, j = idx & 7;
                    cp16(sbB + c0 * 16384 + swz((r << 7) + (j << 4)),
                         bs + (size_t)r * 1024 + c0 * 128 + j * 16);
                }
                CP_COMMIT();
            }
        }

        // ---- A load/convert (only when row-tile changes) ----
        if (rowTile != cachedRow) {
            cachedRow = rowTile;
            const float4* xs = (const float4*)(x + (size_t)rowBase * DDIM);
            const int kc = colA >> 4;
            const int kb = (colA & 15) * 4;
#pragma unroll 4
            for (int i = 0; i < 16; i++) {
                int m = (tid >> 6) + i * 8;
                float4 v = xs[(size_t)m * 64 + colA];
                float b0 = v.x * scv.x + shv.x;
                float b1 = v.y * scv.y + shv.y;
                float b2 = v.z * scv.z + shv.z;
                float b3 = v.w * scv.w + shv.w;
                __half2 h01 = __floats2half2_rn(b0, b1);
                __half2 h23 = __floats2half2_rn(b2, b3);
                uint32_t so = swz((uint32_t)(m << 7) + (uint32_t)kb * 2);
                asm volatile("st.shared.v2.u32 [%0], {%1,%2};"
                             :: "r"(sbA + kc * 16384 + so),
                                "r"(*(uint32_t*)&h01), "r"(*(uint32_t*)&h23));
                float s = b0 * b0 + b1 * b1 + b2 * b2 + b3 * b3;
                for (int o = 16; o; o >>= 1) s += __shfl_down_sync(0xffffffffu, s, o);
                if (lane == 0) sxsq[m * 2 + (wid & 1)] = s;
            }
            __syncthreads();
            if (tid < 128) g_xsq[rowBase + tid] = sxsq[tid * 2] + sxsq[tid * 2 + 1];
        }

        float acc[2][4][4];
        unsigned long long p1[4];
        unsigned m2[4];
#pragma unroll
        for (int s = 0; s < 4; s++) { p1[s] = 0xFFFFFFFFFFFFFFFFull; m2[s] = 0xFFFFFFFFu; }

        // ---- mainloop: 8 chunks (2 subtiles x 4 k-chunks) ----
#pragma unroll 1
        for (int c = 0; c < 8; c++) {
            const int nsub = c >> 2;
            const int kc = c & 3;
            const int stage = (c >= NSTG) ? c - NSTG : c;

            if (c <= 4)      CP_WAIT(3);
            else if (c == 5) CP_WAIT(2);
            else if (c == 6) CP_WAIT(1);
            else             CP_WAIT(0);
            __syncthreads();

            if (kc == 0) {
#pragma unroll
                for (int mf = 0; mf < 2; mf++)
#pragma unroll
                    for (int nf = 0; nf < 4; nf++)
#pragma unroll
                        for (int t = 0; t < 4; t++) acc[mf][nf][t] = 0.f;
            }

            const uint32_t bbase = sbB + stage * 16384;
            const uint32_t ah = sbA + kc * 16384;
#pragma unroll
            for (int ks = 0; ks < 4; ks++) {
                uint32_t b[4][2];
#pragma unroll
                for (int np = 0; np < 2; np++) {
                    uint32_t bb[4];
                    ldsm_x4(bb, bbase + swz(((wn * 32 + np * 16 + bN) << 7) + ks * 32 + bKG));
                    b[np * 2][0] = bb[0]; b[np * 2][1] = bb[1];
                    b[np * 2 + 1][0] = bb[2]; b[np * 2 + 1][1] = bb[3];
                }
                uint32_t a[2][4];
#pragma unroll
                for (int mf = 0; mf < 2; mf++)
                    ldsm_x4(a[mf], ah + swz(((wm * 32 + mf * 16 + aM) << 7) + ks * 32 + aKG));
#pragma unroll
                for (int mf = 0; mf < 2; mf++)
#pragma unroll
                    for (int nf = 0; nf < 4; nf++)
                        mma16816(acc[mf][nf], a[mf], b[nf]);
            }

            if (kc == 3) {
                const float* csqp = scsq + codeBase + nsub * 128 + wn * 32 + 2 * (lane & 3);
#pragma unroll
                for (int nf = 0; nf < 4; nf++) {
                    float q0 = csqp[nf * 8];
                    float q1 = csqp[nf * 8 + 1];
                    int n0 = codeBase + nsub * 128 + wn * 32 + nf * 8 + 2 * (lane & 3);
#pragma unroll
                    for (int mf = 0; mf < 2; mf++) {
#pragma unroll
                        for (int h = 0; h < 2; h++) {
                            int s = mf * 2 + h;
#pragma unroll
                            for (int w = 0; w < 2; w++) {
                                float d = (w ? q1 : q0) - 2.f * acc[mf][nf][h * 2 + w];
                                unsigned mk = mono(d);
                                unsigned long long pk =
                                    ((unsigned long long)mk << 32) | (unsigned)(n0 + w);
                                if (pk < p1[s]) {
                                    m2[s] = min(m2[s], (unsigned)(p1[s] >> 32));
                                    p1[s] = pk;
                                } else {
                                    m2[s] = min(m2[s], mk);
                                }
                            }
                        }
                    }
                }
            }

            if (c + 4 < 8) {
                const int cc = c + 4;
                const int nsub2 = cc >> 2, kc2 = cc & 3;
                const int st2 = (stage + 4 >= NSTG) ? stage + 4 - NSTG : stage + 4;
                const char* bs = (const char*)(g_eB2 + (size_t)(codeBase + nsub2 * 128) * 512);
#pragma unroll
                for (int v = 0; v < 2; v++) {
                    int idx = tid + v * 512;
                    int r = idx >> 3, j = idx & 7;
                    cp16(sbB + st2 * 16384 + swz((r << 7) + (j << 4)),
                         bs + (size_t)r * 1024 + kc2 * 128 + j * 16);
                }
                CP_COMMIT();
            }
        }

        // ---- per-ticket (best1,idx,best2) reduce ----
        __syncthreads();
#pragma unroll
        for (int s = 0; s < 4; s++) {
            unsigned long long p = p1[s];
            unsigned m = m2[s];
#pragma unroll
            for (int off = 1; off <= 2; off <<= 1) {
                unsigned long long op = __shfl_xor_sync(0xffffffffu, p, off);
                unsigned om = __shfl_xor_sync(0xffffffffu, m, off);
                if (op < p) {
                    m = min(min(m, (unsigned)(p >> 32)), om);
                    p = op;
                } else {
                    m = min(min(m, (unsigned)(op >> 32)), om);
                }
            }
            if ((lane & 3) == 0) {
                int row = wm * 32 + (s >> 1) * 16 + (lane >> 2) + (s & 1) * 8;
                sp1[row * 4 + wn] = p;
                sm2[row * 4 + wn] = m;
            }
        }
        __syncthreads();
        if (tid < 128) {
            unsigned long long p = sp1[tid * 4];
            unsigned m = sm2[tid * 4];
#pragma unroll
            for (int t = 1; t < 4; t++) {
                unsigned long long op = sp1[tid * 4 + t];
                unsigned om = sm2[tid * 4 + t];
                if (op < p) {
                    m = min(min(m, (unsigned)(p >> 32)), om);
                    p = op;
                } else {
                    m = min(min(m, (unsigned)(op >> 32)), om);
                }
            }
            ulonglong2 r;
            r.x = p; r.y = (unsigned long long)m;
            g_tres[(size_t)(rowBase + tid) * 4 + codeTile] = r;
        }
    }
}

// ---------------- K5: select winners / build refine list -------------------------
__global__ void k_select() {
    int row = blockIdx.x * 256 + threadIdx.x;
    const ulonglong2* tr = &g_tres[(size_t)row * 4];
    ulonglong2 r0 = tr[0];
    unsigned long long p = r0.x;
    unsigned m = (unsigned)r0.y;
#pragma unroll
    for (int t = 1; t < 4; t++) {
        ulonglong2 rt = tr[t];
        unsigned long long op = rt.x;
        unsigned om = (unsigned)rt.y;
        if (op < p) {
            m = min(min(m, (unsigned)(p >> 32)), om);
            p = op;
        } else {
            m = min(min(m, (unsigned)(op >> 32)), om);
        }
    }
    float b1 = unmono((unsigned)(p >> 32));
    float b2 = unmono(m);
    bool refine = (b2 - b1 < THRESH);
    g_packed[row] = refine ? 0xFFFFFFFFFFFFFFFFull : p;
    if (refine) {
        int pos = atomicAdd(&g_nref, 1);
        g_reflist[pos] = row;
    }
}

// ---------------- K6: fp16x3 HMMA refine of flagged rows (gathered tiles) --------
// Tiles: rowTileR = 128 gathered rows (padded), codeTile = 256 codes. Static
// block->ticket stride-148 mapping. A = xh|xl built from gathered x rows.
// B = [eh|el] streamed, 16 chunks (2 nsub x {eh kc0-3 dual, el kc0-3 single}).
// Result merged into g_packed via atomicMin (k_select pre-set flagged rows to max).
#define RB_OFF   131072                 // A: xh 64KB + xl 64KB
#define RCSQ_OFF (RB_OFF + NSTG * 16384)   // 212992
#define RSP_OFF  (RCSQ_OFF + 4096)         // 217088  u64[128][4]
#define RROW_OFF (RSP_OFF + 4096)          // 221184  int[128]
#define RSMEMSZ  (RROW_OFF + 512)          // 221696

__global__ void __launch_bounds__(512, 1) k_refmma(const float* __restrict__ x) {
    extern __shared__ char smem[];
    const uint32_t sbA = s2u(smem);
    const uint32_t sbB = sbA + RB_OFF;
    const int tid  = threadIdx.x;
    const int lane = tid & 31;
    const int wid  = tid >> 5;
    const int wm   = wid >> 2;
    const int wn   = wid & 3;

    const int nref = g_nref;
    const int ntick = ((nref + 127) >> 7) << 2;
    if (ntick == 0) return;

    if (tid < 256)
        ((float4*)(smem + RCSQ_OFF))[tid] = ((const float4*)g_csq)[tid];
    unsigned long long* sp1 = (unsigned long long*)(smem + RSP_OFF);
    int* srow = (int*)(smem + RROW_OFF);
    const float* scsq = (const float*)(smem + RCSQ_OFF);

    const int colA = tid & 63;
    const float4 scv = ((const float4*)g_scale)[colA];
    const float4 shv = ((const float4*)g_shift)[colA];

    const uint32_t aM  = (uint32_t)((lane & 7) + 8 * ((lane >> 3) & 1));
    const uint32_t aKG = (uint32_t)((lane >> 4) << 4);
    const uint32_t bN  = (uint32_t)(((lane >> 4) << 3) + (lane & 7));
    const uint32_t bKG = (uint32_t)(((lane >> 3) & 1) << 4);

#pragma unroll 1
    for (int tk = blockIdx.x; tk < ntick; tk += 148) {
        const int rowBaseR = (tk >> 2) << 7;
        const int codeBase = (tk & 3) << 8;

        __syncthreads();
        if (tid < 128)
            srow[tid] = (rowBaseR + tid < nref) ? g_reflist[rowBaseR + tid] : -1;
        __syncthreads();

        // ---- B prologue: stages 0..3 = (nsub=0, eh, kc=0..3) ----
        {
            const char* bs = (const char*)(g_eB2 + (size_t)codeBase * 512);
#pragma unroll
            for (int c0 = 0; c0 < 4; c0++) {
#pragma unroll
                for (int v = 0; v < 2; v++) {
                    int idx = tid + v * 512;
                    int r = idx >> 3, j = idx & 7;
                    cp16(sbB + c0 * 16384 + swz((r << 7) + (j << 4)),
                         bs + (size_t)r * 1024 + c0 * 128 + j * 16);
                }
                CP_COMMIT();
            }
        }

        // ---- A gather/convert: hi + lo ----
        {
            const float4* xs = (const float4*)x;
            const int kc = colA >> 4;
            const int kb = (colA & 15) * 4;
#pragma unroll 4
            for (int i = 0; i < 16; i++) {
                int m = (tid >> 6) + i * 8;
                int grow = srow[m];
                if (grow < 0) grow = 0;
                float4 v = xs[(size_t)grow * 64 + colA];
                float b0 = v.x * scv.x + shv.x;
                float b1 = v.y * scv.y + shv.y;
                float b2 = v.z * scv.z + shv.z;
                float b3 = v.w * scv.w + shv.w;
                __half2 h01 = __floats2half2_rn(b0, b1);
                __half2 h23 = __floats2half2_rn(b2, b3);
                __half2 l01 = __floats2half2_rn(b0 - __low2float(h01), b1 - __high2float(h01));
                __half2 l23 = __floats2half2_rn(b2 - __low2float(h23), b3 - __high2float(h23));
                uint32_t so = swz((uint32_t)(m << 7) + (uint32_t)kb * 2);
                asm volatile("st.shared.v2.u32 [%0], {%1,%2};"
                             :: "r"(sbA + kc * 16384 + so),
                                "r"(*(uint32_t*)&h01), "r"(*(uint32_t*)&h23));
                asm volatile("st.shared.v2.u32 [%0], {%1,%2};"
                             :: "r"(sbA + 65536 + kc * 16384 + so),
                                "r"(*(uint32_t*)&l01), "r"(*(uint32_t*)&l23));
            }
        }

        unsigned long long p1[4];
#pragma unroll
        for (int s = 0; s < 4; s++) p1[s] = 0xFFFFFFFFFFFFFFFFull;

        float acc[2][4][4];

        // ---- mainloop: 16 chunks (2 nsub x {eh kc0-3, el kc0-3}) ----
#pragma unroll 1
        for (int c = 0; c < 16; c++) {
            const int nsub = c >> 3;
            const int within = c & 7;
            const int cls = within >> 2;     // 0 = eh (dual), 1 = el (single)
            const int kc = c & 3;
            const int stage = c % NSTG;

            if (c <= 12)      CP_WAIT(3);
            else if (c == 13) CP_WAIT(2);
            else if (c == 14) CP_WAIT(1);
            else              CP_WAIT(0);
            __syncthreads();

            if (within == 0) {
#pragma unroll
                for (int mf = 0; mf < 2; mf++)
#pragma unroll
                    for (int nf = 0; nf < 4; nf++)
#pragma unroll
                        for (int t = 0; t < 4; t++) acc[mf][nf][t] = 0.f;
            }

            const uint32_t bbase = sbB + stage * 16384;
            const uint32_t ah = sbA + kc * 16384;
            const uint32_t al = ah + 65536;
#pragma unroll
            for (int ks = 0; ks < 4; ks++) {
                uint32_t b[4][2];
#pragma unroll
                for (int np = 0; np < 2; np++) {
                    uint32_t bb[4];
                    ldsm_x4(bb, bbase + swz(((wn * 32 + np * 16 + bN) << 7) + ks * 32 + bKG));
                    b[np * 2][0] = bb[0]; b[np * 2][1] = bb[1];
                    b[np * 2 + 1][0] = bb[2]; b[np * 2 + 1][1] = bb[3];
                }
                uint32_t a[2][4];
#pragma unroll
                for (int mf = 0; mf < 2; mf++)
                    ldsm_x4(a[mf], ah + swz(((wm * 32 + mf * 16 + aM) << 7) + ks * 32 + aKG));
#pragma unroll
                for (int mf = 0; mf < 2; mf++)
#pragma unroll
                    for (int nf = 0; nf < 4; nf++)
                        mma16816(acc[mf][nf], a[mf], b[nf]);
                if (cls == 0) {
                    uint32_t a2[2][4];
#pragma unroll
                    for (int mf = 0; mf < 2; mf++)
                        ldsm_x4(a2[mf], al + swz(((wm * 32 + mf * 16 + aM) << 7) + ks * 32 + aKG));
#pragma unroll
                    for (int mf = 0; mf < 2; mf++)
#pragma unroll
                        for (int nf = 0; nf < 4; nf++)
                            mma16816(acc[mf][nf], a2[mf], b[nf]);
                }
            }

            if (within == 7) {
                const float* csqp = scsq + codeBase + nsub * 128 + wn * 32 + 2 * (lane & 3);
#pragma unroll
                for (int nf = 0; nf < 4; nf++) {
                    float q0 = csqp[nf * 8];
                    float q1 = csqp[nf * 8 + 1];
                    int n0 = codeBase + nsub * 128 + wn * 32 + nf * 8 + 2 * (lane & 3);
#pragma unroll
                    for (int mf = 0; mf < 2; mf++) {
#pragma unroll
                        for (int h = 0; h < 2; h++) {
                            int s = mf * 2 + h;
#pragma unroll
                            for (int w = 0; w < 2; w++) {
                                float d = (w ? q1 : q0) - 2.f * acc[mf][nf][h * 2 + w];
                                unsigned long long pk =
                                    ((unsigned long long)mono(d) << 32) | (unsigned)(n0 + w);
                                if (pk < p1[s]) p1[s] = pk;
                            }
                        }
                    }
                }
            }

            if (c + 4 < 16) {
                const int cc = c + 4;
                const int nsub2 = cc >> 3, cls2 = (cc >> 2) & 1, kc2 = cc & 3;
                const int st2 = cc % NSTG;
                const char* bs = (const char*)(g_eB2 + (size_t)(codeBase + nsub2 * 128) * 512);
#pragma unroll
                for (int v = 0; v < 2; v++) {
                    int idx = tid + v * 512;
                    int r = idx >> 3, j = idx & 7;
                    cp16(sbB + st2 * 16384 + swz((r << 7) + (j << 4)),
                         bs + (size_t)r * 1024 + cls2 * 512 + kc2 * 128 + j * 16);
                }
                CP_COMMIT();
            }
        }

        // ---- reduce + merge ----
        __syncthreads();
#pragma unroll
        for (int s = 0; s < 4; s++) {
            unsigned long long p = p1[s];
#pragma unroll
            for (int off = 1; off <= 2; off <<= 1) {
                unsigned long long op = __shfl_xor_sync(0xffffffffu, p, off);
                if (op < p) p = op;
            }
            if ((lane & 3) == 0) {
                int row = wm * 32 + (s >> 1) * 16 + (lane >> 2) + (s & 1) * 8;
                sp1[row * 4 + wn] = p;
            }
        }
        __syncthreads();
        if (tid < 128) {
            int grow = srow[tid];
            if (grow >= 0) {
                unsigned long long p = sp1[tid * 4];
#pragma unroll
                for (int t = 1; t < 4; t++) {
                    unsigned long long op = sp1[tid * 4 + t];
                    if (op < p) p = op;
                }
                atomicMin(&g_packed[grow], p);
            }
        }
    }
}

// ---------------- K7: gather q, output, loss, counts, idx ------------------------
__global__ void k_quant(const int* __restrict__ mask,
                        float* __restrict__ outQ, float* __restrict__ outIdx) {
    int w = threadIdx.x >> 5, lane = threadIdx.x & 31;
    int row = blockIdx.x * 8 + w;
    int m = mask[row];
    unsigned long long pk = g_packed[row];
    int idx = (int)(pk & 0xffffffffull);
    const float4* qv = (const float4*)&g_ET[(size_t)idx * DDIM];
    float4* ov = (float4*)&outQ[(size_t)row * DDIM];
    float4 z = make_float4(0.f, 0.f, 0.f, 0.f);
#pragma unroll
    for (int t = 0; t < 2; t++) {
        int j = lane + t * 32;
        ov[j] = m ? qv[j] : z;
    }
    __shared__ float red[8];
    if (lane == 0) {
        float best = unmono((unsigned)(pk >> 32));
        red[w] = m ? (g_xsq[row] + best) : 0.f;
        outIdx[row] = m ? (float)idx : -1.f;
        if (m) atomicAdd(&g_counts[idx], 1.f);
    }
    __syncthreads();
    if (threadIdx.x == 0) {
        float t = 0.f;
        for (int i = 0; i < 8; i++) t += red[i];
        atomicAdd(&g_loss, (double)t);
    }
}

// ---------------- K8: finalize scalars -------------------------------------------
__global__ void k_final(float* __restrict__ out) {
    int t = threadIdx.x;  // 1024 threads
    float nv = fmaxf(g_cnt, 1.f);
    float p = g_counts[t] / nv;
    float h = -p * logf(p + 1e-10f);
    for (int o = 16; o; o >>= 1) h += __shfl_down_sync(0xffffffffu, h, o);
    __shared__ float red[32];
    if ((t & 31) == 0) red[t >> 5] = h;
    __syncthreads();
    if (t < 32) {
        float s = red[t];
        for (int o = 16; o; o >>= 1) s += __shfl_down_sync(0xffffffffu, s, o);
        if (t == 0) {
            float loss = (float)(g_loss / ((double)nv * (double)DDIM));
            out[OFF_DICT]   = loss;
            out[OFF_COMMIT] = loss;
            out[OFF_PERP]   = expf(s);
        }
    }
}

// ---------------- launch ------------------------------------------------------------
extern "C" void kernel_launch(void* const* d_in, const int* in_sizes, int n_in,
                              void* d_out, int out_size) {
    const float* x     = (const float*)d_in[0];
    const int*   mask  = (const int*)  d_in[1];
    const float* E     = (const float*)d_in[2];
    const float* gamma = (const float*)d_in[3];
    const float* beta  = (const float*)d_in[4];
    float* out = (float*)d_out;

    cudaFuncSetAttribute(k_coarse, cudaFuncAttributeMaxDynamicSharedMemorySize, SMEMSZ);
    cudaFuncSetAttribute(k_refmma, cudaFuncAttributeMaxDynamicSharedMemorySize, RSMEMSZ);

    k_stats<<<256, dim3(64, 4)>>>(x, mask);                  // 1
    k_prep_e<<<32, dim3(32, 8)>>>(E);                        // 2
    k_reduce_stats<<<1, 256>>>(gamma, beta);                 // 3
    k_coarse<<<148, 512, SMEMSZ>>>(x);                       // 4  (ncu lands here)
    k_select<<<128, 256>>>();                                // 5
    k_refmma<<<148, 512, RSMEMSZ>>>(x);                      // 6
    k_quant<<<BNROWS / 8, 256>>>(mask, out + OFF_Q, out + OFF_IDX);
    k_final<<<1, 1024>>>(out);
}

// round 13
// speedup vs baseline: 2.7809x; 1.0608x over previous
#include <cuda_runtime.h>
#include <cuda_fp16.h>
#include <cstdint>
#include <math.h>

// Problem dims
#define BNROWS 32768   // B*N
#define DDIM   256
#define KCODES 1024
#define THRESH 6.0f

// Output layout (float32, reference return order)
#define OFF_Q      0ull
#define OFF_DICT   8388608ull
#define OFF_COMMIT 8388609ull
#define OFF_IDX    8388610ull
#define OFF_PERP   8421378ull

// ---------------- scratch (device globals) -----------------------------------
__device__ float  g_partS [256][DDIM];
__device__ float  g_partS2[256][DDIM];
__device__ float  g_partC [256];
__device__ float  g_cnt;
__device__ __align__(16) float g_scale[DDIM];
__device__ __align__(16) float g_shift[DDIM];
__device__ __align__(16) __half g_eB2[(size_t)KCODES * 512]; // [e_h(256) | e_l(256)] per code
__device__ __align__(16) float g_ET[(size_t)KCODES * DDIM];  // codebook^T [K][D]
__device__ __align__(16) float g_csq[KCODES];
__device__ float  g_xsq[BNROWS];
__device__ __align__(16) ulonglong2 g_tres[(size_t)BNROWS * 4]; // per (row, codeTile): {p1, m2}
__device__ unsigned long long g_packed[BNROWS];                 // (mono(d)<<32)|idx
__device__ int    g_reflist[BNROWS];
__device__ int    g_nref;
__device__ float  g_counts[KCODES];
__device__ double g_loss;
__device__ int    g_ticket;

// ---------------- helpers ------------------------------------------------------
__device__ __forceinline__ uint32_t s2u(const void* p) {
    uint32_t a;
    asm("{ .reg .u64 t; cvta.to.shared.u64 t, %1; cvt.u32.u64 %0, t; }" : "=r"(a) : "l"(p));
    return a;
}
__device__ __forceinline__ uint32_t swz(uint32_t off) { return off ^ ((off >> 3) & 0x70); }

__device__ __forceinline__ void cp16(uint32_t dst, const void* src) {
    asm volatile("cp.async.cg.shared.global [%0], [%1], 16;" :: "r"(dst), "l"(src) : "memory");
}
#define CP_COMMIT() asm volatile("cp.async.commit_group;" ::: "memory")
#define CP_WAIT(N)  asm volatile("cp.async.wait_group %0;" :: "n"(N) : "memory")

__device__ __forceinline__ void ldsm_x4(uint32_t* r, uint32_t addr) {
    asm volatile("ldmatrix.sync.aligned.m8n8.x4.shared.b16 {%0,%1,%2,%3}, [%4];"
                 : "=r"(r[0]), "=r"(r[1]), "=r"(r[2]), "=r"(r[3]) : "r"(addr));
}
__device__ __forceinline__ void mma16816(float* c, const uint32_t* a, const uint32_t* b) {
    asm volatile(
        "mma.sync.aligned.m16n8k16.row.col.f32.f16.f16.f32 "
        "{%0,%1,%2,%3}, {%4,%5,%6,%7}, {%8,%9}, {%0,%1,%2,%3};"
        : "+f"(c[0]), "+f"(c[1]), "+f"(c[2]), "+f"(c[3])
        : "r"(a[0]), "r"(a[1]), "r"(a[2]), "r"(a[3]), "r"(b[0]), "r"(b[1]));
}
__device__ __forceinline__ unsigned mono(float d) {
    unsigned u = __float_as_uint(d);
    return ((int)u < 0) ? ~u : (u | 0x80000000u);
}
__device__ __forceinline__ float unmono(unsigned k) {
    unsigned u = (k & 0x80000000u) ? (k & 0x7fffffffu) : ~k;
    return __uint_as_float(u);
}

// ---------------- K1: masked stats partials -------------------------------------
__global__ void k_stats(const float* __restrict__ x, const int* __restrict__ mask) {
    int d4 = threadIdx.x;   // 0..63
    int ty = threadIdx.y;   // 0..3
    int b  = blockIdx.x;
    int r0 = b * 128 + ty * 32;
    const float4* x4 = (const float4*)x;
    float4 s  = make_float4(0.f, 0.f, 0.f, 0.f);
    float4 s2 = make_float4(0.f, 0.f, 0.f, 0.f);
    float  c  = 0.f;
    for (int r = 0; r < 32; r++) {
        if (mask[r0 + r]) {
            float4 v = x4[(size_t)(r0 + r) * 64 + d4];
            s.x += v.x; s.y += v.y; s.z += v.z; s.w += v.w;
            s2.x += v.x * v.x; s2.y += v.y * v.y; s2.z += v.z * v.z; s2.w += v.w * v.w;
            c += 1.f;
        }
    }
    __shared__ float4 sS[4][64], sS2[4][64];
    __shared__ float  sC[4];
    sS[ty][d4] = s; sS2[ty][d4] = s2;
    if (d4 == 0) sC[ty] = c;
    __syncthreads();
    if (ty == 0) {
        for (int y = 1; y < 4; y++) {
            float4 a = sS[y][d4], a2 = sS2[y][d4];
            s.x += a.x; s.y += a.y; s.z += a.z; s.w += a.w;
            s2.x += a2.x; s2.y += a2.y; s2.z += a2.z; s2.w += a2.w;
        }
        ((float4*)g_partS [b])[d4] = s;
        ((float4*)g_partS2[b])[d4] = s2;
        if (d4 == 0) g_partC[b] = sC[0] + sC[1] + sC[2] + sC[3];
    }
}

// ---------------- K2: transpose E + fp16 hi/lo + deterministic csq ---------------
__global__ void k_prep_e(const float* __restrict__ E) {   // grid 32, block (32,8)
    int tx = threadIdx.x;  // code local
    int ty = threadIdx.y;  // d group
    int code = blockIdx.x * 32 + tx;
    float sq = 0.f;
    for (int d = ty; d < DDIM; d += 8) {
        float v = E[(size_t)d * KCODES + code];
        g_ET[(size_t)code * DDIM + d] = v;
        __half h = __float2half_rn(v);
        g_eB2[(size_t)code * 512 + d]       = h;
        g_eB2[(size_t)code * 512 + 256 + d] = __float2half_rn(v - __half2float(h));
        sq = fmaf(v, v, sq);
    }
    __shared__ float ssq[8][32];
    ssq[ty][tx] = sq;
    __syncthreads();
    if (ty == 0) {
        float s = 0.f;
        for (int i = 0; i < 8; i++) s += ssq[i][tx];
        g_csq[code] = s;
    }
}

// ---------------- K3: reduce stats -> scale/shift; zero run state ----------------
__global__ void k_reduce_stats(const float* __restrict__ gamma, const float* __restrict__ beta) {
    int d = threadIdx.x;
    float s = 0.f, s2 = 0.f, cnt = 0.f;
#pragma unroll 8
    for (int b = 0; b < 256; b++) {
        s  += g_partS [b][d];
        s2 += g_partS2[b][d];
        cnt += g_partC[b];
    }
    for (int i = d; i < KCODES; i += 256) g_counts[i] = 0.f;
    if (d == 0) { g_cnt = cnt; g_loss = 0.0; g_ticket = 0; g_nref = 0; }
    float nv = fmaxf(cnt, 1.f);
    float mu  = s / nv;
    float var = s2 / nv - mu * mu;
    float sc  = rsqrtf(var + 1e-5f) * gamma[d];
    g_scale[d] = sc;
    g_shift[d] = beta[d] - mu * sc;
}

// ---------------- K4: persistent coarse GEMM, 2 CTAs/SM ---------------------------
// Tile 64 rows x 256 codes, 256 threads (8 warps 2m x 4n, warp tile 32x32).
// A = 32KB (4 kc chunks), B = 4 x 16KB stages -> ~104KB smem -> 2 CTAs/SM so
// one CTA's syncs/epilogue overlap the other's HMMA. 2048 tickets, code-major.
#define NTILES   2048
#define CA_BOFF  32768
#define CA_CSQ   (CA_BOFF + 4 * 16384)   // 98304
#define CA_XSQ   (CA_CSQ + 4096)         // 102400
#define CA_SP1   (CA_XSQ + 512)          // 102912
#define CA_SM2   (CA_SP1 + 2048)         // 104960
#define CA_TK    (CA_SM2 + 1024)         // 105984
#define SMEMSZ   (CA_TK + 16)            // 106000

__global__ void __launch_bounds__(256, 2) k_coarse(const float* __restrict__ x) {
    extern __shared__ char smem[];
    const uint32_t sbA = s2u(smem);
    const uint32_t sbB = sbA + CA_BOFF;
    const int tid  = threadIdx.x;
    const int lane = tid & 31;
    const int wid  = tid >> 5;
    const int wm   = wid >> 2;       // 0..1
    const int wn   = wid & 3;        // 0..3

    ((float4*)(smem + CA_CSQ))[tid] = ((const float4*)g_csq)[tid];
    int* s_tk = (int*)(smem + CA_TK);
    float* sxsq = (float*)(smem + CA_XSQ);
    unsigned long long* sp1 = (unsigned long long*)(smem + CA_SP1);  // [64][4]
    unsigned* sm2 = (unsigned*)(smem + CA_SM2);                      // [64][4]
    const float* scsq = (const float*)(smem + CA_CSQ);

    const int colA = tid & 63;
    const float4 scv = ((const float4*)g_scale)[colA];
    const float4 shv = ((const float4*)g_shift)[colA];

    const uint32_t aM  = (uint32_t)((lane & 7) + 8 * ((lane >> 3) & 1));
    const uint32_t aKG = (uint32_t)((lane >> 4) << 4);
    const uint32_t bN  = (uint32_t)(((lane >> 4) << 3) + (lane & 7));
    const uint32_t bKG = (uint32_t)(((lane >> 3) & 1) << 4);

    int cachedRow = -1;
    for (;;) {
        __syncthreads();
        if (tid == 0) *s_tk = atomicAdd(&g_ticket, 1);
        __syncthreads();
        const int tk = *s_tk;
        if (tk >= NTILES) break;
        const int rowTile  = tk >> 2;
        const int codeTile = tk & 3;
        const int rowBase  = rowTile << 6;    // 64 rows
        const int codeBase = codeTile << 8;

        // ---- B prologue: chunks 0..2 (nsub=0, kc=0..2) into stages 0..2 ----
        {
            const char* bs = (const char*)(g_eB2 + (size_t)codeBase * 512);
#pragma unroll
            for (int c0 = 0; c0 < 3; c0++) {
#pragma unroll
                for (int v = 0; v < 4; v++) {
                    int idx = tid + v * 256;   // 0..1023
                    int r = idx >> 3, j = idx & 7;
                    cp16(sbB + c0 * 16384 + swz((r << 7) + (j << 4)),
                         bs + (size_t)r * 1024 + c0 * 128 + j * 16);
                }
                CP_COMMIT();
            }
        }

        // ---- A load/convert (only when row-tile changes): 64 rows ----
        if (rowTile != cachedRow) {
            cachedRow = rowTile;
            const float4* xs = (const float4*)(x + (size_t)rowBase * DDIM);
            const int kc = colA >> 4;
            const int kb = (colA & 15) * 4;
#pragma unroll 4
            for (int i = 0; i < 16; i++) {
                int m = (tid >> 6) + i * 4;
                float4 v = xs[(size_t)m * 64 + colA];
                float b0 = v.x * scv.x + shv.x;
                float b1 = v.y * scv.y + shv.y;
                float b2 = v.z * scv.z + shv.z;
                float b3 = v.w * scv.w + shv.w;
                __half2 h01 = __floats2half2_rn(b0, b1);
                __half2 h23 = __floats2half2_rn(b2, b3);
                uint32_t so = swz((uint32_t)(m << 7) + (uint32_t)kb * 2);
                asm volatile("st.shared.v2.u32 [%0], {%1,%2};"
                             :: "r"(sbA + kc * 8192 + so),
                                "r"(*(uint32_t*)&h01), "r"(*(uint32_t*)&h23));
                float s = b0 * b0 + b1 * b1 + b2 * b2 + b3 * b3;
                for (int o = 16; o; o >>= 1) s += __shfl_down_sync(0xffffffffu, s, o);
                if (lane == 0) sxsq[m * 2 + (wid & 1)] = s;
            }
            __syncthreads();
            if (tid < 64) g_xsq[rowBase + tid] = sxsq[tid * 2] + sxsq[tid * 2 + 1];
        }

        float acc[2][4][4];
        unsigned long long p1[4];
        unsigned m2[4];
#pragma unroll
        for (int s = 0; s < 4; s++) { p1[s] = 0xFFFFFFFFFFFFFFFFull; m2[s] = 0xFFFFFFFFu; }

        // ---- mainloop: 8 chunks (2 subtiles x 4 k-chunks), 4-stage ring ----
#pragma unroll 1
        for (int c = 0; c < 8; c++) {
            const int nsub = c >> 2;
            const int kc = c & 3;
            const int stage = c & 3;

            if (c <= 5)      CP_WAIT(2);
            else if (c == 6) CP_WAIT(1);
            else             CP_WAIT(0);
            __syncthreads();

            if (kc == 0) {
#pragma unroll
                for (int mf = 0; mf < 2; mf++)
#pragma unroll
                    for (int nf = 0; nf < 4; nf++)
#pragma unroll
                        for (int t = 0; t < 4; t++) acc[mf][nf][t] = 0.f;
            }

            const uint32_t bbase = sbB + stage * 16384;
            const uint32_t ah = sbA + kc * 8192;
#pragma unroll
            for (int ks = 0; ks < 4; ks++) {
                uint32_t b[4][2];
#pragma unroll
                for (int np = 0; np < 2; np++) {
                    uint32_t bb[4];
                    ldsm_x4(bb, bbase + swz(((wn * 32 + np * 16 + bN) << 7) + ks * 32 + bKG));
                    b[np * 2][0] = bb[0]; b[np * 2][1] = bb[1];
                    b[np * 2 + 1][0] = bb[2]; b[np * 2 + 1][1] = bb[3];
                }
                uint32_t a[2][4];
#pragma unroll
                for (int mf = 0; mf < 2; mf++)
                    ldsm_x4(a[mf], ah + swz(((wm * 32 + mf * 16 + aM) << 7) + ks * 32 + aKG));
#pragma unroll
                for (int mf = 0; mf < 2; mf++)
#pragma unroll
                    for (int nf = 0; nf < 4; nf++)
                        mma16816(acc[mf][nf], a[mf], b[nf]);
            }

            if (kc == 3) {
                const float* csqp = scsq + codeBase + nsub * 128 + wn * 32 + 2 * (lane & 3);
#pragma unroll
                for (int nf = 0; nf < 4; nf++) {
                    float q0 = csqp[nf * 8];
                    float q1 = csqp[nf * 8 + 1];
                    int n0 = codeBase + nsub * 128 + wn * 32 + nf * 8 + 2 * (lane & 3);
#pragma unroll
                    for (int mf = 0; mf < 2; mf++) {
#pragma unroll
                        for (int h = 0; h < 2; h++) {
                            int s = mf * 2 + h;
#pragma unroll
                            for (int w = 0; w < 2; w++) {
                                float d = (w ? q1 : q0) - 2.f * acc[mf][nf][h * 2 + w];
                                unsigned mk = mono(d);
                                unsigned long long pk =
                                    ((unsigned long long)mk << 32) | (unsigned)(n0 + w);
                                if (pk < p1[s]) {
                                    m2[s] = min(m2[s], (unsigned)(p1[s] >> 32));
                                    p1[s] = pk;
                                } else {
                                    m2[s] = min(m2[s], mk);
                                }
                            }
                        }
                    }
                }
            }

            if (c + 3 < 8) {
                const int cc = c + 3;
                const int nsub2 = cc >> 2, kc2 = cc & 3;
                const int st2 = cc & 3;
                const char* bs = (const char*)(g_eB2 + (size_t)(codeBase + nsub2 * 128) * 512);
#pragma unroll
                for (int v = 0; v < 4; v++) {
                    int idx = tid + v * 256;
                    int r = idx >> 3, j = idx & 7;
                    cp16(sbB + st2 * 16384 + swz((r << 7) + (j << 4)),
                         bs + (size_t)r * 1024 + kc2 * 128 + j * 16);
                }
                CP_COMMIT();
            }
        }

        // ---- per-ticket (best1,idx,best2) reduce ----
        __syncthreads();
#pragma unroll
        for (int s = 0; s < 4; s++) {
            unsigned long long p = p1[s];
            unsigned m = m2[s];
#pragma unroll
            for (int off = 1; off <= 2; off <<= 1) {
                unsigned long long op = __shfl_xor_sync(0xffffffffu, p, off);
                unsigned om = __shfl_xor_sync(0xffffffffu, m, off);
                if (op < p) {
                    m = min(min(m, (unsigned)(p >> 32)), om);
                    p = op;
                } else {
                    m = min(min(m, (unsigned)(op >> 32)), om);
                }
            }
            if ((lane & 3) == 0) {
                int row = wm * 32 + (s >> 1) * 16 + (lane >> 2) + (s & 1) * 8;
                sp1[row * 4 + wn] = p;
                sm2[row * 4 + wn] = m;
            }
        }
        __syncthreads();
        if (tid < 64) {
            unsigned long long p = sp1[tid * 4];
            unsigned m = sm2[tid * 4];
#pragma unroll
            for (int t = 1; t < 4; t++) {
                unsigned long long op = sp1[tid * 4 + t];
                unsigned om = sm2[tid * 4 + t];
                if (op < p) {
                    m = min(min(m, (unsigned)(p >> 32)), om);
                    p = op;
                } else {
                    m = min(min(m, (unsigned)(op >> 32)), om);
                }
            }
            ulonglong2 r;
            r.x = p; r.y = (unsigned long long)m;
            g_tres[(size_t)(rowBase + tid) * 4 + codeTile] = r;
        }
    }
}

// ---------------- K5: select winners / build refine list -------------------------
__global__ void k_select() {
    int row = blockIdx.x * 256 + threadIdx.x;
    const ulonglong2* tr = &g_tres[(size_t)row * 4];
    ulonglong2 r0 = tr[0];
    unsigned long long p = r0.x;
    unsigned m = (unsigned)r0.y;
#pragma unroll
    for (int t = 1; t < 4; t++) {
        ulonglong2 rt = tr[t];
        unsigned long long op = rt.x;
        unsigned om = (unsigned)rt.y;
        if (op < p) {
            m = min(min(m, (unsigned)(p >> 32)), om);
            p = op;
        } else {
            m = min(min(m, (unsigned)(op >> 32)), om);
        }
    }
    float b1 = unmono((unsigned)(p >> 32));
    float b2 = unmono(m);
    bool refine = (b2 - b1 < THRESH);
    g_packed[row] = refine ? 0xFFFFFFFFFFFFFFFFull : p;
    if (refine) {
        int pos = atomicAdd(&g_nref, 1);
        g_reflist[pos] = row;
    }
}

// ---------------- K6: fp16x3 HMMA refine of flagged rows (gathered tiles) --------
#define NSTG     5
#define RB_OFF   131072                    // A: xh 64KB + xl 64KB
#define RCSQ_OFF (RB_OFF + NSTG * 16384)   // 212992
#define RSP_OFF  (RCSQ_OFF + 4096)         // 217088  u64[128][4]
#define RROW_OFF (RSP_OFF + 4096)          // 221184  int[128]
#define RSMEMSZ  (RROW_OFF + 512)          // 221696

__global__ void __launch_bounds__(512, 1) k_refmma(const float* __restrict__ x) {
    extern __shared__ char smem[];
    const uint32_t sbA = s2u(smem);
    const uint32_t sbB = sbA + RB_OFF;
    const int tid  = threadIdx.x;
    const int lane = tid & 31;
    const int wid  = tid >> 5;
    const int wm   = wid >> 2;
    const int wn   = wid & 3;

    const int nref = g_nref;
    const int ntick = ((nref + 127) >> 7) << 2;
    if (ntick == 0) return;

    if (tid < 256)
        ((float4*)(smem + RCSQ_OFF))[tid] = ((const float4*)g_csq)[tid];
    unsigned long long* sp1 = (unsigned long long*)(smem + RSP_OFF);
    int* srow = (int*)(smem + RROW_OFF);
    const float* scsq = (const float*)(smem + RCSQ_OFF);

    const int colA = tid & 63;
    const float4 scv = ((const float4*)g_scale)[colA];
    const float4 shv = ((const float4*)g_shift)[colA];

    const uint32_t aM  = (uint32_t)((lane & 7) + 8 * ((lane >> 3) & 1));
    const uint32_t aKG = (uint32_t)((lane >> 4) << 4);
    const uint32_t bN  = (uint32_t)(((lane >> 4) << 3) + (lane & 7));
    const uint32_t bKG = (uint32_t)(((lane >> 3) & 1) << 4);

#pragma unroll 1
    for (int tk = blockIdx.x; tk < ntick; tk += 148) {
        const int rowBaseR = (tk >> 2) << 7;
        const int codeBase = (tk & 3) << 8;

        __syncthreads();
        if (tid < 128)
            srow[tid] = (rowBaseR + tid < nref) ? g_reflist[rowBaseR + tid] : -1;
        __syncthreads();

        // ---- B prologue: stages 0..3 = (nsub=0, eh, kc=0..3) ----
        {
            const char* bs = (const char*)(g_eB2 + (size_t)codeBase * 512);
#pragma unroll
            for (int c0 = 0; c0 < 4; c0++) {
#pragma unroll
                for (int v = 0; v < 2; v++) {
                    int idx = tid + v * 512;
                    int r = idx >> 3, j = idx & 7;
                    cp16(sbB + c0 * 16384 + swz((r << 7) + (j << 4)),
                         bs + (size_t)r * 1024 + c0 * 128 + j * 16);
                }
                CP_COMMIT();
            }
        }

        // ---- A gather/convert: hi + lo ----
        {
            const float4* xs = (const float4*)x;
            const int kc = colA >> 4;
            const int kb = (colA & 15) * 4;
#pragma unroll 4
            for (int i = 0; i < 16; i++) {
                int m = (tid >> 6) + i * 8;
                int grow = srow[m];
                if (grow < 0) grow = 0;
                float4 v = xs[(size_t)grow * 64 + colA];
                float b0 = v.x * scv.x + shv.x;
                float b1 = v.y * scv.y + shv.y;
                float b2 = v.z * scv.z + shv.z;
                float b3 = v.w * scv.w + shv.w;
                __half2 h01 = __floats2half2_rn(b0, b1);
                __half2 h23 = __floats2half2_rn(b2, b3);
                __half2 l01 = __floats2half2_rn(b0 - __low2float(h01), b1 - __high2float(h01));
                __half2 l23 = __floats2half2_rn(b2 - __low2float(h23), b3 - __high2float(h23));
                uint32_t so = swz((uint32_t)(m << 7) + (uint32_t)kb * 2);
                asm volatile("st.shared.v2.u32 [%0], {%1,%2};"
                             :: "r"(sbA + kc * 16384 + so),
                                "r"(*(uint32_t*)&h01), "r"(*(uint32_t*)&h23));
                asm volatile("st.shared.v2.u32 [%0], {%1,%2};"
                             :: "r"(sbA + 65536 + kc * 16384 + so),
                                "r"(*(uint32_t*)&l01), "r"(*(uint32_t*)&l23));
            }
        }

        unsigned long long p1[4];
#pragma unroll
        for (int s = 0; s < 4; s++) p1[s] = 0xFFFFFFFFFFFFFFFFull;

        float acc[2][4][4];

        // ---- mainloop: 16 chunks (2 nsub x {eh kc0-3, el kc0-3}) ----
#pragma unroll 1
        for (int c = 0; c < 16; c++) {
            const int nsub = c >> 3;
            const int within = c & 7;
            const int cls = within >> 2;     // 0 = eh (dual), 1 = el (single)
            const int kc = c & 3;
            const int stage = c % NSTG;

            if (c <= 12)      CP_WAIT(3);
            else if (c == 13) CP_WAIT(2);
            else if (c == 14) CP_WAIT(1);
            else              CP_WAIT(0);
            __syncthreads();

            if (within == 0) {
#pragma unroll
                for (int mf = 0; mf < 2; mf++)
#pragma unroll
                    for (int nf = 0; nf < 4; nf++)
#pragma unroll
                        for (int t = 0; t < 4; t++) acc[mf][nf][t] = 0.f;
            }

            const uint32_t bbase = sbB + stage * 16384;
            const uint32_t ah = sbA + kc * 16384;
            const uint32_t al = ah + 65536;
#pragma unroll
            for (int ks = 0; ks < 4; ks++) {
                uint32_t b[4][2];
#pragma unroll
                for (int np = 0; np < 2; np++) {
                    uint32_t bb[4];
                    ldsm_x4(bb, bbase + swz(((wn * 32 + np * 16 + bN) << 7) + ks * 32 + bKG));
                    b[np * 2][0] = bb[0]; b[np * 2][1] = bb[1];
                    b[np * 2 + 1][0] = bb[2]; b[np * 2 + 1][1] = bb[3];
                }
                uint32_t a[2][4];
#pragma unroll
                for (int mf = 0; mf < 2; mf++)
                    ldsm_x4(a[mf], ah + swz(((wm * 32 + mf * 16 + aM) << 7) + ks * 32 + aKG));
#pragma unroll
                for (int mf = 0; mf < 2; mf++)
#pragma unroll
                    for (int nf = 0; nf < 4; nf++)
                        mma16816(acc[mf][nf], a[mf], b[nf]);
                if (cls == 0) {
                    uint32_t a2[2][4];
#pragma unroll
                    for (int mf = 0; mf < 2; mf++)
                        ldsm_x4(a2[mf], al + swz(((wm * 32 + mf * 16 + aM) << 7) + ks * 32 + aKG));
#pragma unroll
                    for (int mf = 0; mf < 2; mf++)
#pragma unroll
                        for (int nf = 0; nf < 4; nf++)
                            mma16816(acc[mf][nf], a2[mf], b[nf]);
                }
            }

            if (within == 7) {
                const float* csqp = scsq + codeBase + nsub * 128 + wn * 32 + 2 * (lane & 3);
#pragma unroll
                for (int nf = 0; nf < 4; nf++) {
                    float q0 = csqp[nf * 8];
                    float q1 = csqp[nf * 8 + 1];
                    int n0 = codeBase + nsub * 128 + wn * 32 + nf * 8 + 2 * (lane & 3);
#pragma unroll
                    for (int mf = 0; mf < 2; mf++) {
#pragma unroll
                        for (int h = 0; h < 2; h++) {
                            int s = mf * 2 + h;
#pragma unroll
                            for (int w = 0; w < 2; w++) {
                                float d = (w ? q1 : q0) - 2.f * acc[mf][nf][h * 2 + w];
                                unsigned long long pk =
                                    ((unsigned long long)mono(d) << 32) | (unsigned)(n0 + w);
                                if (pk < p1[s]) p1[s] = pk;
                            }
                        }
                    }
                }
            }

            if (c + 4 < 16) {
                const int cc = c + 4;
                const int nsub2 = cc >> 3, cls2 = (cc >> 2) & 1, kc2 = cc & 3;
                const int st2 = cc % NSTG;
                const char* bs = (const char*)(g_eB2 + (size_t)(codeBase + nsub2 * 128) * 512);
#pragma unroll
                for (int v = 0; v < 2; v++) {
                    int idx = tid + v * 512;
                    int r = idx >> 3, j = idx & 7;
                    cp16(sbB + st2 * 16384 + swz((r << 7) + (j << 4)),
                         bs + (size_t)r * 1024 + cls2 * 512 + kc2 * 128 + j * 16);
                }
                CP_COMMIT();
            }
        }

        // ---- reduce + merge ----
        __syncthreads();
#pragma unroll
        for (int s = 0; s < 4; s++) {
            unsigned long long p = p1[s];
#pragma unroll
            for (int off = 1; off <= 2; off <<= 1) {
                unsigned long long op = __shfl_xor_sync(0xffffffffu, p, off);
                if (op < p) p = op;
            }
            if ((lane & 3) == 0) {
                int row = wm * 32 + (s >> 1) * 16 + (lane >> 2) + (s & 1) * 8;
                sp1[row * 4 + wn] = p;
            }
        }
        __syncthreads();
        if (tid < 128) {
            int grow = srow[tid];
            if (grow >= 0) {
                unsigned long long p = sp1[tid * 4];
#pragma unroll
                for (int t = 1; t < 4; t++) {
                    unsigned long long op = sp1[tid * 4 + t];
                    if (op < p) p = op;
                }
                atomicMin(&g_packed[grow], p);
            }
        }
    }
}

// ---------------- K7: gather q, output, loss, counts, idx ------------------------
__global__ void k_quant(const int* __restrict__ mask,
                        float* __restrict__ outQ, float* __restrict__ outIdx) {
    int w = threadIdx.x >> 5, lane = threadIdx.x & 31;
    int row = blockIdx.x * 8 + w;
    int m = mask[row];
    unsigned long long pk = g_packed[row];
    int idx = (int)(pk & 0xffffffffull);
    const float4* qv = (const float4*)&g_ET[(size_t)idx * DDIM];
    float4* ov = (float4*)&outQ[(size_t)row * DDIM];
    float4 z = make_float4(0.f, 0.f, 0.f, 0.f);
#pragma unroll
    for (int t = 0; t < 2; t++) {
        int j = lane + t * 32;
        ov[j] = m ? qv[j] : z;
    }
    __shared__ float red[8];
    if (lane == 0) {
        float best = unmono((unsigned)(pk >> 32));
        red[w] = m ? (g_xsq[row] + best) : 0.f;
        outIdx[row] = m ? (float)idx : -1.f;
        if (m) atomicAdd(&g_counts[idx], 1.f);
    }
    __syncthreads();
    if (threadIdx.x == 0) {
        float t = 0.f;
        for (int i = 0; i < 8; i++) t += red[i];
        atomicAdd(&g_loss, (double)t);
    }
}

// ---------------- K8: finalize scalars -------------------------------------------
__global__ void k_final(float* __restrict__ out) {
    int t = threadIdx.x;  // 1024 threads
    float nv = fmaxf(g_cnt, 1.f);
    float p = g_counts[t] / nv;
    float h = -p * logf(p + 1e-10f);
    for (int o = 16; o; o >>= 1) h += __shfl_down_sync(0xffffffffu, h, o);
    __shared__ float red[32];
    if ((t & 31) == 0) red[t >> 5] = h;
    __syncthreads();
    if (t < 32) {
        float s = red[t];
        for (int o = 16; o; o >>= 1) s += __shfl_down_sync(0xffffffffu, s, o);
        if (t == 0) {
            float loss = (float)(g_loss / ((double)nv * (double)DDIM));
            out[OFF_DICT]   = loss;
            out[OFF_COMMIT] = loss;
            out[OFF_PERP]   = expf(s);
        }
    }
}

// ---------------- launch ------------------------------------------------------------
extern "C" void kernel_launch(void* const* d_in, const int* in_sizes, int n_in,
                              void* d_out, int out_size) {
    const float* x     = (const float*)d_in[0];
    const int*   mask  = (const int*)  d_in[1];
    const float* E     = (const float*)d_in[2];
    const float* gamma = (const float*)d_in[3];
    const float* beta  = (const float*)d_in[4];
    float* out = (float*)d_out;

    cudaFuncSetAttribute(k_coarse, cudaFuncAttributeMaxDynamicSharedMemorySize, SMEMSZ);
    cudaFuncSetAttribute(k_refmma, cudaFuncAttributeMaxDynamicSharedMemorySize, RSMEMSZ);

    k_stats<<<256, dim3(64, 4)>>>(x, mask);                  // 1
    k_prep_e<<<32, dim3(32, 8)>>>(E);                        // 2
    k_reduce_stats<<<1, 256>>>(gamma, beta);                 // 3
    k_coarse<<<296, 256, SMEMSZ>>>(x);                       // 4  (ncu lands here)
    k_select<<<128, 256>>>();                                // 5
    k_refmma<<<148, 512, RSMEMSZ>>>(x);                      // 6
    k_quant<<<BNROWS / 8, 256>>>(mask, out + OFF_Q, out + OFF_IDX);
    k_final<<<1, 1024>>>(out);
}

// round 14
// speedup vs baseline: 2.8207x; 1.0143x over previous
#include <cuda_runtime.h>
#include <cuda_fp16.h>
#include <cstdint>
#include <math.h>

// Problem dims
#define BNROWS 32768   // B*N
#define DDIM   256
#define KCODES 1024
#define THRESH 6.0f

// Output layout (float32, reference return order)
#define OFF_Q      0ull
#define OFF_DICT   8388608ull
#define OFF_COMMIT 8388609ull
#define OFF_IDX    8388610ull
#define OFF_PERP   8421378ull

// ---------------- scratch (device globals) -----------------------------------
__device__ float  g_partS [256][DDIM];
__device__ float  g_partS2[256][DDIM];
__device__ float  g_partC [256];
__device__ float  g_cnt;
__device__ __align__(16) float g_scale[DDIM];
__device__ __align__(16) float g_shift[DDIM];
__device__ __align__(16) __half g_eB2[(size_t)KCODES * 512]; // [e_h(256) | e_l(256)] per code
__device__ __align__(16) float g_ET[(size_t)KCODES * DDIM];  // codebook^T [K][D]
__device__ __align__(16) float g_csq[KCODES];
__device__ float  g_xsq[BNROWS];
__device__ __align__(16) ulonglong2 g_tres[(size_t)BNROWS * 4]; // per (row, codeTile): {p1, m2}
__device__ unsigned long long g_packed[BNROWS];                 // (mono(d)<<32)|idx
__device__ int    g_reflist[BNROWS];
__device__ int    g_nref;
__device__ float  g_counts[KCODES];
__device__ double g_loss;
__device__ int    g_ticket;

// ---------------- helpers ------------------------------------------------------
__device__ __forceinline__ uint32_t s2u(const void* p) {
    uint32_t a;
    asm("{ .reg .u64 t; cvta.to.shared.u64 t, %1; cvt.u32.u64 %0, t; }" : "=r"(a) : "l"(p));
    return a;
}
__device__ __forceinline__ uint32_t swz(uint32_t off) { return off ^ ((off >> 3) & 0x70); }

__device__ __forceinline__ void cp16(uint32_t dst, const void* src) {
    asm volatile("cp.async.cg.shared.global [%0], [%1], 16;" :: "r"(dst), "l"(src) : "memory");
}
#define CP_COMMIT() asm volatile("cp.async.commit_group;" ::: "memory")
#define CP_WAIT(N)  asm volatile("cp.async.wait_group %0;" :: "n"(N) : "memory")

__device__ __forceinline__ void ldsm_x4(uint32_t* r, uint32_t addr) {
    asm volatile("ldmatrix.sync.aligned.m8n8.x4.shared.b16 {%0,%1,%2,%3}, [%4];"
                 : "=r"(r[0]), "=r"(r[1]), "=r"(r[2]), "=r"(r[3]) : "r"(addr));
}
__device__ __forceinline__ void mma16816(float* c, const uint32_t* a, const uint32_t* b) {
    asm volatile(
        "mma.sync.aligned.m16n8k16.row.col.f32.f16.f16.f32 "
        "{%0,%1,%2,%3}, {%4,%5,%6,%7}, {%8,%9}, {%0,%1,%2,%3};"
        : "+f"(c[0]), "+f"(c[1]), "+f"(c[2]), "+f"(c[3])
        : "r"(a[0]), "r"(a[1]), "r"(a[2]), "r"(a[3]), "r"(b[0]), "r"(b[1]));
}
__device__ __forceinline__ unsigned mono(float d) {
    unsigned u = __float_as_uint(d);
    return ((int)u < 0) ? ~u : (u | 0x80000000u);
}
__device__ __forceinline__ float unmono(unsigned k) {
    unsigned u = (k & 0x80000000u) ? (k & 0x7fffffffu) : ~k;
    return __uint_as_float(u);
}

// ---------------- K1: masked stats partials -------------------------------------
__global__ void k_stats(const float* __restrict__ x, const int* __restrict__ mask) {
    int d4 = threadIdx.x;   // 0..63
    int ty = threadIdx.y;   // 0..3
    int b  = blockIdx.x;
    int r0 = b * 128 + ty * 32;
    const float4* x4 = (const float4*)x;
    float4 s  = make_float4(0.f, 0.f, 0.f, 0.f);
    float4 s2 = make_float4(0.f, 0.f, 0.f, 0.f);
    float  c  = 0.f;
    for (int r = 0; r < 32; r++) {
        if (mask[r0 + r]) {
            float4 v = x4[(size_t)(r0 + r) * 64 + d4];
            s.x += v.x; s.y += v.y; s.z += v.z; s.w += v.w;
            s2.x += v.x * v.x; s2.y += v.y * v.y; s2.z += v.z * v.z; s2.w += v.w * v.w;
            c += 1.f;
        }
    }
    __shared__ float4 sS[4][64], sS2[4][64];
    __shared__ float  sC[4];
    sS[ty][d4] = s; sS2[ty][d4] = s2;
    if (d4 == 0) sC[ty] = c;
    __syncthreads();
    if (ty == 0) {
        for (int y = 1; y < 4; y++) {
            float4 a = sS[y][d4], a2 = sS2[y][d4];
            s.x += a.x; s.y += a.y; s.z += a.z; s.w += a.w;
            s2.x += a2.x; s2.y += a2.y; s2.z += a2.z; s2.w += a2.w;
        }
        ((float4*)g_partS [b])[d4] = s;
        ((float4*)g_partS2[b])[d4] = s2;
        if (d4 == 0) g_partC[b] = sC[0] + sC[1] + sC[2] + sC[3];
    }
}

// ---------------- K2: transpose E + fp16 hi/lo + deterministic csq ---------------
__global__ void k_prep_e(const float* __restrict__ E) {   // grid 32, block (32,8)
    int tx = threadIdx.x;  // code local
    int ty = threadIdx.y;  // d group
    int code = blockIdx.x * 32 + tx;
    float sq = 0.f;
    for (int d = ty; d < DDIM; d += 8) {
        float v = E[(size_t)d * KCODES + code];
        g_ET[(size_t)code * DDIM + d] = v;
        __half h = __float2half_rn(v);
        g_eB2[(size_t)code * 512 + d]       = h;
        g_eB2[(size_t)code * 512 + 256 + d] = __float2half_rn(v - __half2float(h));
        sq = fmaf(v, v, sq);
    }
    __shared__ float ssq[8][32];
    ssq[ty][tx] = sq;
    __syncthreads();
    if (ty == 0) {
        float s = 0.f;
        for (int i = 0; i < 8; i++) s += ssq[i][tx];
        g_csq[code] = s;
    }
}

// ---------------- K3: reduce stats -> scale/shift; zero run state ----------------
__global__ void k_reduce_stats(const float* __restrict__ gamma, const float* __restrict__ beta) {
    int d = threadIdx.x;
    float s = 0.f, s2 = 0.f, cnt = 0.f;
#pragma unroll 8
    for (int b = 0; b < 256; b++) {
        s  += g_partS [b][d];
        s2 += g_partS2[b][d];
        cnt += g_partC[b];
    }
    for (int i = d; i < KCODES; i += 256) g_counts[i] = 0.f;
    if (d == 0) { g_cnt = cnt; g_loss = 0.0; g_ticket = 0; g_nref = 0; }
    float nv = fmaxf(cnt, 1.f);
    float mu  = s / nv;
    float var = s2 / nv - mu * mu;
    float sc  = rsqrtf(var + 1e-5f) * gamma[d];
    g_scale[d] = sc;
    g_shift[d] = beta[d] - mu * sc;
}

// ---------------- K4: persistent coarse GEMM, 2 CTAs/SM, rowTile tickets ----------
// Ticket = one rowTile (64 rows); CTA converts A once, then loops all 4 codeTiles
// (256 codes each). 512 tickets. Tile math identical to R13.
#define NROWT    512
#define CA_BOFF  32768
#define CA_CSQ   (CA_BOFF + 4 * 16384)   // 98304
#define CA_XSQ   (CA_CSQ + 4096)         // 102400
#define CA_SP1   (CA_XSQ + 512)          // 102912
#define CA_SM2   (CA_SP1 + 2048)         // 104960
#define CA_TK    (CA_SM2 + 1024)         // 105984
#define SMEMSZ   (CA_TK + 16)            // 106000

__global__ void __launch_bounds__(256, 2) k_coarse(const float* __restrict__ x) {
    extern __shared__ char smem[];
    const uint32_t sbA = s2u(smem);
    const uint32_t sbB = sbA + CA_BOFF;
    const int tid  = threadIdx.x;
    const int lane = tid & 31;
    const int wid  = tid >> 5;
    const int wm   = wid >> 2;       // 0..1
    const int wn   = wid & 3;        // 0..3

    ((float4*)(smem + CA_CSQ))[tid] = ((const float4*)g_csq)[tid];
    int* s_tk = (int*)(smem + CA_TK);
    float* sxsq = (float*)(smem + CA_XSQ);
    unsigned long long* sp1 = (unsigned long long*)(smem + CA_SP1);  // [64][4]
    unsigned* sm2 = (unsigned*)(smem + CA_SM2);                      // [64][4]
    const float* scsq = (const float*)(smem + CA_CSQ);

    const int colA = tid & 63;
    const float4 scv = ((const float4*)g_scale)[colA];
    const float4 shv = ((const float4*)g_shift)[colA];

    const uint32_t aM  = (uint32_t)((lane & 7) + 8 * ((lane >> 3) & 1));
    const uint32_t aKG = (uint32_t)((lane >> 4) << 4);
    const uint32_t bN  = (uint32_t)(((lane >> 4) << 3) + (lane & 7));
    const uint32_t bKG = (uint32_t)(((lane >> 3) & 1) << 4);

    for (;;) {
        __syncthreads();
        if (tid == 0) *s_tk = atomicAdd(&g_ticket, 1);
        __syncthreads();
        const int rowTile = *s_tk;
        if (rowTile >= NROWT) break;
        const int rowBase = rowTile << 6;    // 64 rows

        // ---- A load/convert: once per rowTile ----
        {
            const float4* xs = (const float4*)(x + (size_t)rowBase * DDIM);
            const int kc = colA >> 4;
            const int kb = (colA & 15) * 4;
#pragma unroll 4
            for (int i = 0; i < 16; i++) {
                int m = (tid >> 6) + i * 4;
                float4 v = xs[(size_t)m * 64 + colA];
                float b0 = v.x * scv.x + shv.x;
                float b1 = v.y * scv.y + shv.y;
                float b2 = v.z * scv.z + shv.z;
                float b3 = v.w * scv.w + shv.w;
                __half2 h01 = __floats2half2_rn(b0, b1);
                __half2 h23 = __floats2half2_rn(b2, b3);
                uint32_t so = swz((uint32_t)(m << 7) + (uint32_t)kb * 2);
                asm volatile("st.shared.v2.u32 [%0], {%1,%2};"
                             :: "r"(sbA + kc * 8192 + so),
                                "r"(*(uint32_t*)&h01), "r"(*(uint32_t*)&h23));
                float s = b0 * b0 + b1 * b1 + b2 * b2 + b3 * b3;
                for (int o = 16; o; o >>= 1) s += __shfl_down_sync(0xffffffffu, s, o);
                if (lane == 0) sxsq[m * 2 + (wid & 1)] = s;
            }
            __syncthreads();
            if (tid < 64) g_xsq[rowBase + tid] = sxsq[tid * 2] + sxsq[tid * 2 + 1];
        }

        // ---- loop over 4 code tiles with resident A ----
#pragma unroll 1
        for (int codeTile = 0; codeTile < 4; codeTile++) {
            const int codeBase = codeTile << 8;

            // B prologue: chunks 0..2 into stages 0..2
            {
                const char* bs = (const char*)(g_eB2 + (size_t)codeBase * 512);
#pragma unroll
                for (int c0 = 0; c0 < 3; c0++) {
#pragma unroll
                    for (int v = 0; v < 4; v++) {
                        int idx = tid + v * 256;   // 0..1023
                        int r = idx >> 3, j = idx & 7;
                        cp16(sbB + c0 * 16384 + swz((r << 7) + (j << 4)),
                             bs + (size_t)r * 1024 + c0 * 128 + j * 16);
                    }
                    CP_COMMIT();
                }
            }

            float acc[2][4][4];
            unsigned long long p1[4];
            unsigned m2[4];
#pragma unroll
            for (int s = 0; s < 4; s++) { p1[s] = 0xFFFFFFFFFFFFFFFFull; m2[s] = 0xFFFFFFFFu; }

            // mainloop: 8 chunks (2 subtiles x 4 k-chunks), 4-stage ring
#pragma unroll 1
            for (int c = 0; c < 8; c++) {
                const int nsub = c >> 2;
                const int kc = c & 3;
                const int stage = c & 3;

                if (c <= 5)      CP_WAIT(2);
                else if (c == 6) CP_WAIT(1);
                else             CP_WAIT(0);
                __syncthreads();

                if (kc == 0) {
#pragma unroll
                    for (int mf = 0; mf < 2; mf++)
#pragma unroll
                        for (int nf = 0; nf < 4; nf++)
#pragma unroll
                            for (int t = 0; t < 4; t++) acc[mf][nf][t] = 0.f;
                }

                const uint32_t bbase = sbB + stage * 16384;
                const uint32_t ah = sbA + kc * 8192;
#pragma unroll
                for (int ks = 0; ks < 4; ks++) {
                    uint32_t b[4][2];
#pragma unroll
                    for (int np = 0; np < 2; np++) {
                        uint32_t bb[4];
                        ldsm_x4(bb, bbase + swz(((wn * 32 + np * 16 + bN) << 7) + ks * 32 + bKG));
                        b[np * 2][0] = bb[0]; b[np * 2][1] = bb[1];
                        b[np * 2 + 1][0] = bb[2]; b[np * 2 + 1][1] = bb[3];
                    }
                    uint32_t a[2][4];
#pragma unroll
                    for (int mf = 0; mf < 2; mf++)
                        ldsm_x4(a[mf], ah + swz(((wm * 32 + mf * 16 + aM) << 7) + ks * 32 + aKG));
#pragma unroll
                    for (int mf = 0; mf < 2; mf++)
#pragma unroll
                        for (int nf = 0; nf < 4; nf++)
                            mma16816(acc[mf][nf], a[mf], b[nf]);
                }

                if (kc == 3) {
                    const float* csqp = scsq + codeBase + nsub * 128 + wn * 32 + 2 * (lane & 3);
#pragma unroll
                    for (int nf = 0; nf < 4; nf++) {
                        float q0 = csqp[nf * 8];
                        float q1 = csqp[nf * 8 + 1];
                        int n0 = codeBase + nsub * 128 + wn * 32 + nf * 8 + 2 * (lane & 3);
#pragma unroll
                        for (int mf = 0; mf < 2; mf++) {
#pragma unroll
                            for (int h = 0; h < 2; h++) {
                                int s = mf * 2 + h;
#pragma unroll
                                for (int w = 0; w < 2; w++) {
                                    float d = (w ? q1 : q0) - 2.f * acc[mf][nf][h * 2 + w];
                                    unsigned mk = mono(d);
                                    unsigned long long pk =
                                        ((unsigned long long)mk << 32) | (unsigned)(n0 + w);
                                    if (pk < p1[s]) {
                                        m2[s] = min(m2[s], (unsigned)(p1[s] >> 32));
                                        p1[s] = pk;
                                    } else {
                                        m2[s] = min(m2[s], mk);
                                    }
                                }
                            }
                        }
                    }
                }

                if (c + 3 < 8) {
                    const int cc = c + 3;
                    const int nsub2 = cc >> 2, kc2 = cc & 3;
                    const int st2 = cc & 3;
                    const char* bs = (const char*)(g_eB2 + (size_t)(codeBase + nsub2 * 128) * 512);
#pragma unroll
                    for (int v = 0; v < 4; v++) {
                        int idx = tid + v * 256;
                        int r = idx >> 3, j = idx & 7;
                        cp16(sbB + st2 * 16384 + swz((r << 7) + (j << 4)),
                             bs + (size_t)r * 1024 + kc2 * 128 + j * 16);
                    }
                    CP_COMMIT();
                }
            }

            // per-codeTile (best1,idx,best2) reduce
            __syncthreads();
#pragma unroll
            for (int s = 0; s < 4; s++) {
                unsigned long long p = p1[s];
                unsigned m = m2[s];
#pragma unroll
                for (int off = 1; off <= 2; off <<= 1) {
                    unsigned long long op = __shfl_xor_sync(0xffffffffu, p, off);
                    unsigned om = __shfl_xor_sync(0xffffffffu, m, off);
                    if (op < p) {
                        m = min(min(m, (unsigned)(p >> 32)), om);
                        p = op;
                    } else {
                        m = min(min(m, (unsigned)(op >> 32)), om);
                    }
                }
                if ((lane & 3) == 0) {
                    int row = wm * 32 + (s >> 1) * 16 + (lane >> 2) + (s & 1) * 8;
                    sp1[row * 4 + wn] = p;
                    sm2[row * 4 + wn] = m;
                }
            }
            __syncthreads();
            if (tid < 64) {
                unsigned long long p = sp1[tid * 4];
                unsigned m = sm2[tid * 4];
#pragma unroll
                for (int t = 1; t < 4; t++) {
                    unsigned long long op = sp1[tid * 4 + t];
                    unsigned om = sm2[tid * 4 + t];
                    if (op < p) {
                        m = min(min(m, (unsigned)(p >> 32)), om);
                        p = op;
                    } else {
                        m = min(min(m, (unsigned)(op >> 32)), om);
                    }
                }
                ulonglong2 r;
                r.x = p; r.y = (unsigned long long)m;
                g_tres[(size_t)(rowBase + tid) * 4 + codeTile] = r;
            }
        }
    }
}

// ---------------- K5: select winners / build refine list -------------------------
__global__ void k_select() {
    int row = blockIdx.x * 256 + threadIdx.x;
    const ulonglong2* tr = &g_tres[(size_t)row * 4];
    ulonglong2 r0 = tr[0];
    unsigned long long p = r0.x;
    unsigned m = (unsigned)r0.y;
#pragma unroll
    for (int t = 1; t < 4; t++) {
        ulonglong2 rt = tr[t];
        unsigned long long op = rt.x;
        unsigned om = (unsigned)rt.y;
        if (op < p) {
            m = min(min(m, (unsigned)(p >> 32)), om);
            p = op;
        } else {
            m = min(min(m, (unsigned)(op >> 32)), om);
        }
    }
    float b1 = unmono((unsigned)(p >> 32));
    float b2 = unmono(m);
    bool refine = (b2 - b1 < THRESH);
    g_packed[row] = refine ? 0xFFFFFFFFFFFFFFFFull : p;
    if (refine) {
        int pos = atomicAdd(&g_nref, 1);
        g_reflist[pos] = row;
    }
}

// ---------------- K6: fp16x3 HMMA refine of flagged rows (gathered tiles) --------
#define NSTG     5
#define RB_OFF   131072                    // A: xh 64KB + xl 64KB
#define RCSQ_OFF (RB_OFF + NSTG * 16384)   // 212992
#define RSP_OFF  (RCSQ_OFF + 4096)         // 217088  u64[128][4]
#define RROW_OFF (RSP_OFF + 4096)          // 221184  int[128]
#define RSMEMSZ  (RROW_OFF + 512)          // 221696

__global__ void __launch_bounds__(512, 1) k_refmma(const float* __restrict__ x) {
    extern __shared__ char smem[];
    const uint32_t sbA = s2u(smem);
    const uint32_t sbB = sbA + RB_OFF;
    const int tid  = threadIdx.x;
    const int lane = tid & 31;
    const int wid  = tid >> 5;
    const int wm   = wid >> 2;
    const int wn   = wid & 3;

    const int nref = g_nref;
    const int ntick = ((nref + 127) >> 7) << 2;
    if (ntick == 0) return;

    if (tid < 256)
        ((float4*)(smem + RCSQ_OFF))[tid] = ((const float4*)g_csq)[tid];
    unsigned long long* sp1 = (unsigned long long*)(smem + RSP_OFF);
    int* srow = (int*)(smem + RROW_OFF);
    const float* scsq = (const float*)(smem + RCSQ_OFF);

    const int colA = tid & 63;
    const float4 scv = ((const float4*)g_scale)[colA];
    const float4 shv = ((const float4*)g_shift)[colA];

    const uint32_t aM  = (uint32_t)((lane & 7) + 8 * ((lane >> 3) & 1));
    const uint32_t aKG = (uint32_t)((lane >> 4) << 4);
    const uint32_t bN  = (uint32_t)(((lane >> 4) << 3) + (lane & 7));
    const uint32_t bKG = (uint32_t)(((lane >> 3) & 1) << 4);

#pragma unroll 1
    for (int tk = blockIdx.x; tk < ntick; tk += 148) {
        const int rowBaseR = (tk >> 2) << 7;
        const int codeBase = (tk & 3) << 8;

        __syncthreads();
        if (tid < 128)
            srow[tid] = (rowBaseR + tid < nref) ? g_reflist[rowBaseR + tid] : -1;
        __syncthreads();

        // ---- B prologue: stages 0..3 = (nsub=0, eh, kc=0..3) ----
        {
            const char* bs = (const char*)(g_eB2 + (size_t)codeBase * 512);
#pragma unroll
            for (int c0 = 0; c0 < 4; c0++) {
#pragma unroll
                for (int v = 0; v < 2; v++) {
                    int idx = tid + v * 512;
                    int r = idx >> 3, j = idx & 7;
                    cp16(sbB + c0 * 16384 + swz((r << 7) + (j << 4)),
                         bs + (size_t)r * 1024 + c0 * 128 + j * 16);
                }
                CP_COMMIT();
            }
        }

        // ---- A gather/convert: hi + lo ----
        {
            const float4* xs = (const float4*)x;
            const int kc = colA >> 4;
            const int kb = (colA & 15) * 4;
#pragma unroll 4
            for (int i = 0; i < 16; i++) {
                int m = (tid >> 6) + i * 8;
                int grow = srow[m];
                if (grow < 0) grow = 0;
                float4 v = xs[(size_t)grow * 64 + colA];
                float b0 = v.x * scv.x + shv.x;
                float b1 = v.y * scv.y + shv.y;
                float b2 = v.z * scv.z + shv.z;
                float b3 = v.w * scv.w + shv.w;
                __half2 h01 = __floats2half2_rn(b0, b1);
                __half2 h23 = __floats2half2_rn(b2, b3);
                __half2 l01 = __floats2half2_rn(b0 - __low2float(h01), b1 - __high2float(h01));
                __half2 l23 = __floats2half2_rn(b2 - __low2float(h23), b3 - __high2float(h23));
                uint32_t so = swz((uint32_t)(m << 7) + (uint32_t)kb * 2);
                asm volatile("st.shared.v2.u32 [%0], {%1,%2};"
                             :: "r"(sbA + kc * 16384 + so),
                                "r"(*(uint32_t*)&h01), "r"(*(uint32_t*)&h23));
                asm volatile("st.shared.v2.u32 [%0], {%1,%2};"
                             :: "r"(sbA + 65536 + kc * 16384 + so),
                                "r"(*(uint32_t*)&l01), "r"(*(uint32_t*)&l23));
            }
        }

        unsigned long long p1[4];
#pragma unroll
        for (int s = 0; s < 4; s++) p1[s] = 0xFFFFFFFFFFFFFFFFull;

        float acc[2][4][4];

        // ---- mainloop: 16 chunks (2 nsub x {eh kc0-3, el kc0-3}) ----
#pragma unroll 1
        for (int c = 0; c < 16; c++) {
            const int nsub = c >> 3;
            const int within = c & 7;
            const int cls = within >> 2;     // 0 = eh (dual), 1 = el (single)
            const int kc = c & 3;
            const int stage = c % NSTG;

            if (c <= 12)      CP_WAIT(3);
            else if (c == 13) CP_WAIT(2);
            else if (c == 14) CP_WAIT(1);
            else              CP_WAIT(0);
            __syncthreads();

            if (within == 0) {
#pragma unroll
                for (int mf = 0; mf < 2; mf++)
#pragma unroll
                    for (int nf = 0; nf < 4; nf++)
#pragma unroll
                        for (int t = 0; t < 4; t++) acc[mf][nf][t] = 0.f;
            }

            const uint32_t bbase = sbB + stage * 16384;
            const uint32_t ah = sbA + kc * 16384;
            const uint32_t al = ah + 65536;
#pragma unroll
            for (int ks = 0; ks < 4; ks++) {
                uint32_t b[4][2];
#pragma unroll
                for (int np = 0; np < 2; np++) {
                    uint32_t bb[4];
                    ldsm_x4(bb, bbase + swz(((wn * 32 + np * 16 + bN) << 7) + ks * 32 + bKG));
                    b[np * 2][0] = bb[0]; b[np * 2][1] = bb[1];
                    b[np * 2 + 1][0] = bb[2]; b[np * 2 + 1][1] = bb[3];
                }
                uint32_t a[2][4];
#pragma unroll
                for (int mf = 0; mf < 2; mf++)
                    ldsm_x4(a[mf], ah + swz(((wm * 32 + mf * 16 + aM) << 7) + ks * 32 + aKG));
#pragma unroll
                for (int mf = 0; mf < 2; mf++)
#pragma unroll
                    for (int nf = 0; nf < 4; nf++)
                        mma16816(acc[mf][nf], a[mf], b[nf]);
                if (cls == 0) {
                    uint32_t a2[2][4];
#pragma unroll
                    for (int mf = 0; mf < 2; mf++)
                        ldsm_x4(a2[mf], al + swz(((wm * 32 + mf * 16 + aM) << 7) + ks * 32 + aKG));
#pragma unroll
                    for (int mf = 0; mf < 2; mf++)
#pragma unroll
                        for (int nf = 0; nf < 4; nf++)
                            mma16816(acc[mf][nf], a2[mf], b[nf]);
                }
            }

            if (within == 7) {
                const float* csqp = scsq + codeBase + nsub * 128 + wn * 32 + 2 * (lane & 3);
#pragma unroll
                for (int nf = 0; nf < 4; nf++) {
                    float q0 = csqp[nf * 8];
                    float q1 = csqp[nf * 8 + 1];
                    int n0 = codeBase + nsub * 128 + wn * 32 + nf * 8 + 2 * (lane & 3);
#pragma unroll
                    for (int mf = 0; mf < 2; mf++) {
#pragma unroll
                        for (int h = 0; h < 2; h++) {
                            int s = mf * 2 + h;
#pragma unroll
                            for (int w = 0; w < 2; w++) {
                                float d = (w ? q1 : q0) - 2.f * acc[mf][nf][h * 2 + w];
                                unsigned long long pk =
                                    ((unsigned long long)mono(d) << 32) | (unsigned)(n0 + w);
                                if (pk < p1[s]) p1[s] = pk;
                            }
                        }
                    }
                }
            }

            if (c + 4 < 16) {
                const int cc = c + 4;
                const int nsub2 = cc >> 3, cls2 = (cc >> 2) & 1, kc2 = cc & 3;
                const int st2 = cc % NSTG;
                const char* bs = (const char*)(g_eB2 + (size_t)(codeBase + nsub2 * 128) * 512);
#pragma unroll
                for (int v = 0; v < 2; v++) {
                    int idx = tid + v * 512;
                    int r = idx >> 3, j = idx & 7;
                    cp16(sbB + st2 * 16384 + swz((r << 7) + (j << 4)),
                         bs + (size_t)r * 1024 + cls2 * 512 + kc2 * 128 + j * 16);
                }
                CP_COMMIT();
            }
        }

        // ---- reduce + merge ----
        __syncthreads();
#pragma unroll
        for (int s = 0; s < 4; s++) {
            unsigned long long p = p1[s];
#pragma unroll
            for (int off = 1; off <= 2; off <<= 1) {
                unsigned long long op = __shfl_xor_sync(0xffffffffu, p, off);
                if (op < p) p = op;
            }
            if ((lane & 3) == 0) {
                int row = wm * 32 + (s >> 1) * 16 + (lane >> 2) + (s & 1) * 8;
                sp1[row * 4 + wn] = p;
            }
        }
        __syncthreads();
        if (tid < 128) {
            int grow = srow[tid];
            if (grow >= 0) {
                unsigned long long p = sp1[tid * 4];
#pragma unroll
                for (int t = 1; t < 4; t++) {
                    unsigned long long op = sp1[tid * 4 + t];
                    if (op < p) p = op;
                }
                atomicMin(&g_packed[grow], p);
            }
        }
    }
}

// ---------------- K7: gather q, output, loss, counts, idx ------------------------
__global__ void k_quant(const int* __restrict__ mask,
                        float* __restrict__ outQ, float* __restrict__ outIdx) {
    int w = threadIdx.x >> 5, lane = threadIdx.x & 31;
    int row = blockIdx.x * 8 + w;
    int m = mask[row];
    unsigned long long pk = g_packed[row];
    int idx = (int)(pk & 0xffffffffull);
    const float4* qv = (const float4*)&g_ET[(size_t)idx * DDIM];
    float4* ov = (float4*)&outQ[(size_t)row * DDIM];
    float4 z = make_float4(0.f, 0.f, 0.f, 0.f);
#pragma unroll
    for (int t = 0; t < 2; t++) {
        int j = lane + t * 32;
        ov[j] = m ? qv[j] : z;
    }
    __shared__ float red[8];
    if (lane == 0) {
        float best = unmono((unsigned)(pk >> 32));
        red[w] = m ? (g_xsq[row] + best) : 0.f;
        outIdx[row] = m ? (float)idx : -1.f;
        if (m) atomicAdd(&g_counts[idx], 1.f);
    }
    __syncthreads();
    if (threadIdx.x == 0) {
        float t = 0.f;
        for (int i = 0; i < 8; i++) t += red[i];
        atomicAdd(&g_loss, (double)t);
    }
}

// ---------------- K8: finalize scalars -------------------------------------------
__global__ void k_final(float* __restrict__ out) {
    int t = threadIdx.x;  // 1024 threads
    float nv = fmaxf(g_cnt, 1.f);
    float p = g_counts[t] / nv;
    float h = -p * logf(p + 1e-10f);
    for (int o = 16; o; o >>= 1) h += __shfl_down_sync(0xffffffffu, h, o);
    __shared__ float red[32];
    if ((t & 31) == 0) red[t >> 5] = h;
    __syncthreads();
    if (t < 32) {
        float s = red[t];
        for (int o = 16; o; o >>= 1) s += __shfl_down_sync(0xffffffffu, s, o);
        if (t == 0) {
            float loss = (float)(g_loss / ((double)nv * (double)DDIM));
            out[OFF_DICT]   = loss;
            out[OFF_COMMIT] = loss;
            out[OFF_PERP]   = expf(s);
        }
    }
}

// ---------------- launch ------------------------------------------------------------
extern "C" void kernel_launch(void* const* d_in, const int* in_sizes, int n_in,
                              void* d_out, int out_size) {
    const float* x     = (const float*)d_in[0];
    const int*   mask  = (const int*)  d_in[1];
    const float* E     = (const float*)d_in[2];
    const float* gamma = (const float*)d_in[3];
    const float* beta  = (const float*)d_in[4];
    float* out = (float*)d_out;

    cudaFuncSetAttribute(k_coarse, cudaFuncAttributeMaxDynamicSharedMemorySize, SMEMSZ);
    cudaFuncSetAttribute(k_refmma, cudaFuncAttributeMaxDynamicSharedMemorySize, RSMEMSZ);

    k_stats<<<256, dim3(64, 4)>>>(x, mask);                  // 1
    k_prep_e<<<32, dim3(32, 8)>>>(E);                        // 2
    k_reduce_stats<<<1, 256>>>(gamma, beta);                 // 3
    k_coarse<<<296, 256, SMEMSZ>>>(x);                       // 4  (ncu lands here)
    k_select<<<128, 256>>>();                                // 5
    k_refmma<<<148, 512, RSMEMSZ>>>(x);                      // 6
    k_quant<<<BNROWS / 8, 256>>>(mask, out + OFF_Q, out + OFF_IDX);
    k_final<<<1, 1024>>>(out);
}

// round 15
// speedup vs baseline: 2.8442x; 1.0083x over previous
#include <cuda_runtime.h>
#include <cuda_fp16.h>
#include <cstdint>
#include <math.h>

// Problem dims
#define BNROWS 32768   // B*N
#define DDIM   256
#define KCODES 1024
#define THRESH 6.0f

// Output layout (float32, reference return order)
#define OFF_Q      0ull
#define OFF_DICT   8388608ull
#define OFF_COMMIT 8388609ull
#define OFF_IDX    8388610ull
#define OFF_PERP   8421378ull

// ---------------- scratch (device globals) -----------------------------------
__device__ float  g_partS [256][DDIM];
__device__ float  g_partS2[256][DDIM];
__device__ float  g_partC [256];
__device__ float  g_cnt;
__device__ __align__(16) float g_scale[DDIM];
__device__ __align__(16) float g_shift[DDIM];
__device__ __align__(16) __half g_eB2[(size_t)KCODES * 512]; // [e_h(256) | e_l(256)] per code
__device__ __align__(16) float g_ET[(size_t)KCODES * DDIM];  // codebook^T [K][D]
__device__ __align__(16) float g_csq[KCODES];
__device__ float  g_xsq[BNROWS];
__device__ __align__(16) ulonglong2 g_tres[(size_t)BNROWS * 4]; // per (row, codeTile): {p1, m2}
__device__ unsigned long long g_packed[BNROWS];                 // (mono(d)<<32)|idx
__device__ int    g_reflist[BNROWS];
__device__ int    g_nref;
__device__ float  g_counts[KCODES];
__device__ double g_loss;
__device__ int    g_ticket;

// ---------------- helpers ------------------------------------------------------
__device__ __forceinline__ uint32_t s2u(const void* p) {
    uint32_t a;
    asm("{ .reg .u64 t; cvta.to.shared.u64 t, %1; cvt.u32.u64 %0, t; }" : "=r"(a) : "l"(p));
    return a;
}
__device__ __forceinline__ uint32_t swz(uint32_t off) { return off ^ ((off >> 3) & 0x70); }

__device__ __forceinline__ void cp16(uint32_t dst, const void* src) {
    asm volatile("cp.async.cg.shared.global [%0], [%1], 16;" :: "r"(dst), "l"(src) : "memory");
}
#define CP_COMMIT() asm volatile("cp.async.commit_group;" ::: "memory")
#define CP_WAIT(N)  asm volatile("cp.async.wait_group %0;" :: "n"(N) : "memory")

__device__ __forceinline__ void ldsm_x4(uint32_t* r, uint32_t addr) {
    asm volatile("ldmatrix.sync.aligned.m8n8.x4.shared.b16 {%0,%1,%2,%3}, [%4];"
                 : "=r"(r[0]), "=r"(r[1]), "=r"(r[2]), "=r"(r[3]) : "r"(addr));
}
__device__ __forceinline__ void mma16816(float* c, const uint32_t* a, const uint32_t* b) {
    asm volatile(
        "mma.sync.aligned.m16n8k16.row.col.f32.f16.f16.f32 "
        "{%0,%1,%2,%3}, {%4,%5,%6,%7}, {%8,%9}, {%0,%1,%2,%3};"
        : "+f"(c[0]), "+f"(c[1]), "+f"(c[2]), "+f"(c[3])
        : "r"(a[0]), "r"(a[1]), "r"(a[2]), "r"(a[3]), "r"(b[0]), "r"(b[1]));
}
__device__ __forceinline__ unsigned mono(float d) {
    unsigned u = __float_as_uint(d);
    return ((int)u < 0) ? ~u : (u | 0x80000000u);
}
__device__ __forceinline__ float unmono(unsigned k) {
    unsigned u = (k & 0x80000000u) ? (k & 0x7fffffffu) : ~k;
    return __uint_as_float(u);
}

// ---------------- K1: masked stats partials -------------------------------------
__global__ void k_stats(const float* __restrict__ x, const int* __restrict__ mask) {
    int d4 = threadIdx.x;   // 0..63
    int ty = threadIdx.y;   // 0..3
    int b  = blockIdx.x;
    int r0 = b * 128 + ty * 32;
    const float4* x4 = (const float4*)x;
    float4 s  = make_float4(0.f, 0.f, 0.f, 0.f);
    float4 s2 = make_float4(0.f, 0.f, 0.f, 0.f);
    float  c  = 0.f;
    for (int r = 0; r < 32; r++) {
        if (mask[r0 + r]) {
            float4 v = x4[(size_t)(r0 + r) * 64 + d4];
            s.x += v.x; s.y += v.y; s.z += v.z; s.w += v.w;
            s2.x += v.x * v.x; s2.y += v.y * v.y; s2.z += v.z * v.z; s2.w += v.w * v.w;
            c += 1.f;
        }
    }
    __shared__ float4 sS[4][64], sS2[4][64];
    __shared__ float  sC[4];
    sS[ty][d4] = s; sS2[ty][d4] = s2;
    if (d4 == 0) sC[ty] = c;
    __syncthreads();
    if (ty == 0) {
        for (int y = 1; y < 4; y++) {
            float4 a = sS[y][d4], a2 = sS2[y][d4];
            s.x += a.x; s.y += a.y; s.z += a.z; s.w += a.w;
            s2.x += a2.x; s2.y += a2.y; s2.z += a2.z; s2.w += a2.w;
        }
        ((float4*)g_partS [b])[d4] = s;
        ((float4*)g_partS2[b])[d4] = s2;
        if (d4 == 0) g_partC[b] = sC[0] + sC[1] + sC[2] + sC[3];
    }
}

// ---------------- K2: transpose E + fp16 hi/lo + deterministic csq ---------------
__global__ void k_prep_e(const float* __restrict__ E) {   // grid 32, block (32,8)
    int tx = threadIdx.x;  // code local
    int ty = threadIdx.y;  // d group
    int code = blockIdx.x * 32 + tx;
    float sq = 0.f;
    for (int d = ty; d < DDIM; d += 8) {
        float v = E[(size_t)d * KCODES + code];
        g_ET[(size_t)code * DDIM + d] = v;
        __half h = __float2half_rn(v);
        g_eB2[(size_t)code * 512 + d]       = h;
        g_eB2[(size_t)code * 512 + 256 + d] = __float2half_rn(v - __half2float(h));
        sq = fmaf(v, v, sq);
    }
    __shared__ float ssq[8][32];
    ssq[ty][tx] = sq;
    __syncthreads();
    if (ty == 0) {
        float s = 0.f;
        for (int i = 0; i < 8; i++) s += ssq[i][tx];
        g_csq[code] = s;
    }
}

// ---------------- K3: reduce stats -> scale/shift; zero run state ----------------
__global__ void k_reduce_stats(const float* __restrict__ gamma, const float* __restrict__ beta) {
    int d = threadIdx.x;
    float s = 0.f, s2 = 0.f, cnt = 0.f;
#pragma unroll 8
    for (int b = 0; b < 256; b++) {
        s  += g_partS [b][d];
        s2 += g_partS2[b][d];
        cnt += g_partC[b];
    }
    for (int i = d; i < KCODES; i += 256) g_counts[i] = 0.f;
    if (d == 0) { g_cnt = cnt; g_loss = 0.0; g_ticket = 0; g_nref = 0; }
    float nv = fmaxf(cnt, 1.f);
    float mu  = s / nv;
    float var = s2 / nv - mu * mu;
    float sc  = rsqrtf(var + 1e-5f) * gamma[d];
    g_scale[d] = sc;
    g_shift[d] = beta[d] - mu * sc;
}

// ---------------- K4: persistent coarse GEMM, 2 CTAs/SM, rowTile tickets ----------
// swz(row*128 + k) == row*128 + (k ^ ((row&7)<<4)) for k<128: ldsm addresses
// collapse to precomputed base + (kterm ^ xr) -> 2 ALU ops per ldsm.
#define NROWT    512
#define CA_BOFF  32768
#define CA_CSQ   (CA_BOFF + 4 * 16384)   // 98304
#define CA_XSQ   (CA_CSQ + 4096)         // 102400
#define CA_SP1   (CA_XSQ + 512)          // 102912
#define CA_SM2   (CA_SP1 + 2048)         // 104960
#define CA_TK    (CA_SM2 + 1024)         // 105984
#define SMEMSZ   (CA_TK + 16)            // 106000

__global__ void __launch_bounds__(256, 2) k_coarse(const float* __restrict__ x) {
    extern __shared__ char smem[];
    const uint32_t sbA = s2u(smem);
    const uint32_t sbB = sbA + CA_BOFF;
    const int tid  = threadIdx.x;
    const int lane = tid & 31;
    const int wid  = tid >> 5;
    const int wm   = wid >> 2;       // 0..1
    const int wn   = wid & 3;        // 0..3

    ((float4*)(smem + CA_CSQ))[tid] = ((const float4*)g_csq)[tid];
    int* s_tk = (int*)(smem + CA_TK);
    float* sxsq = (float*)(smem + CA_XSQ);
    unsigned long long* sp1 = (unsigned long long*)(smem + CA_SP1);  // [64][4]
    unsigned* sm2 = (unsigned*)(smem + CA_SM2);                      // [64][4]
    const float* scsq = (const float*)(smem + CA_CSQ);

    const int colA = tid & 63;
    const float4 scv = ((const float4*)g_scale)[colA];
    const float4 shv = ((const float4*)g_shift)[colA];

    const uint32_t aM  = (uint32_t)((lane & 7) + 8 * ((lane >> 3) & 1));
    const uint32_t aKG = (uint32_t)((lane >> 4) << 4);
    const uint32_t bN  = (uint32_t)(((lane >> 4) << 3) + (lane & 7));
    const uint32_t bKG = (uint32_t)(((lane >> 3) & 1) << 4);

    // precomputed ldsm row bases + swizzle XOR masks
    uint32_t aBase[2], aXor[2], bBase[2], bXor[2];
#pragma unroll
    for (int mf = 0; mf < 2; mf++) {
        uint32_t r = wm * 32 + mf * 16 + aM;
        aBase[mf] = r << 7;
        aXor[mf]  = (r & 7) << 4;
    }
#pragma unroll
    for (int np = 0; np < 2; np++) {
        uint32_t r = wn * 32 + np * 16 + bN;
        bBase[np] = r << 7;
        bXor[np]  = (r & 7) << 4;
    }
    // per-thread B cp.async offsets (ticket-invariant)
    uint32_t bDst[4], bSrc[4];
#pragma unroll
    for (int v = 0; v < 4; v++) {
        uint32_t idx = (uint32_t)tid + v * 256;
        uint32_t r = idx >> 3, j = idx & 7;
        bDst[v] = (r << 7) + ((j << 4) ^ ((r & 7) << 4));
        bSrc[v] = r * 1024 + j * 16;
    }

    for (;;) {
        __syncthreads();
        if (tid == 0) *s_tk = atomicAdd(&g_ticket, 1);
        __syncthreads();
        const int rowTile = *s_tk;
        if (rowTile >= NROWT) break;
        const int rowBase = rowTile << 6;    // 64 rows

        // ---- A load/convert: once per rowTile ----
        {
            const float4* xs = (const float4*)(x + (size_t)rowBase * DDIM);
            const int kc = colA >> 4;
            const int kb = (colA & 15) * 4;
#pragma unroll 4
            for (int i = 0; i < 16; i++) {
                int m = (tid >> 6) + i * 4;
                float4 v = xs[(size_t)m * 64 + colA];
                float b0 = v.x * scv.x + shv.x;
                float b1 = v.y * scv.y + shv.y;
                float b2 = v.z * scv.z + shv.z;
                float b3 = v.w * scv.w + shv.w;
                __half2 h01 = __floats2half2_rn(b0, b1);
                __half2 h23 = __floats2half2_rn(b2, b3);
                uint32_t so = swz((uint32_t)(m << 7) + (uint32_t)kb * 2);
                asm volatile("st.shared.v2.u32 [%0], {%1,%2};"
                             :: "r"(sbA + kc * 8192 + so),
                                "r"(*(uint32_t*)&h01), "r"(*(uint32_t*)&h23));
                float s = b0 * b0 + b1 * b1 + b2 * b2 + b3 * b3;
                for (int o = 16; o; o >>= 1) s += __shfl_down_sync(0xffffffffu, s, o);
                if (lane == 0) sxsq[m * 2 + (wid & 1)] = s;
            }
            __syncthreads();
            if (tid < 64) g_xsq[rowBase + tid] = sxsq[tid * 2] + sxsq[tid * 2 + 1];
        }

        // ---- loop over 4 code tiles with resident A ----
#pragma unroll 1
        for (int codeTile = 0; codeTile < 4; codeTile++) {
            const int codeBase = codeTile << 8;
            const char* bsrc = (const char*)(g_eB2 + (size_t)codeBase * 512);

            // B prologue: chunks 0..2 into stages 0..2
#pragma unroll
            for (int c0 = 0; c0 < 3; c0++) {
#pragma unroll
                for (int v = 0; v < 4; v++)
                    cp16(sbB + c0 * 16384 + bDst[v], bsrc + bSrc[v] + c0 * 128);
                CP_COMMIT();
            }

            float acc[2][4][4];
            unsigned long long p1[4];
            unsigned m2[4];
#pragma unroll
            for (int s = 0; s < 4; s++) { p1[s] = 0xFFFFFFFFFFFFFFFFull; m2[s] = 0xFFFFFFFFu; }

            // mainloop: 8 chunks (2 subtiles x 4 k-chunks), 4-stage ring
#pragma unroll 1
            for (int c = 0; c < 8; c++) {
                const int nsub = c >> 2;
                const int kc = c & 3;
                const int stage = c & 3;

                if (c <= 5)      CP_WAIT(2);
                else if (c == 6) CP_WAIT(1);
                else             CP_WAIT(0);
                __syncthreads();

                if (kc == 0) {
#pragma unroll
                    for (int mf = 0; mf < 2; mf++)
#pragma unroll
                        for (int nf = 0; nf < 4; nf++)
#pragma unroll
                            for (int t = 0; t < 4; t++) acc[mf][nf][t] = 0.f;
                }

                const uint32_t bb0 = sbB + stage * 16384 + bBase[0];
                const uint32_t bb1 = sbB + stage * 16384 + bBase[1];
                const uint32_t aa0 = sbA + kc * 8192 + aBase[0];
                const uint32_t aa1 = sbA + kc * 8192 + aBase[1];
#pragma unroll
                for (int ks = 0; ks < 4; ks++) {
                    const uint32_t kA = ks * 32 + aKG;
                    const uint32_t kB = ks * 32 + bKG;
                    uint32_t b[4][2];
                    {
                        uint32_t t0[4], t1[4];
                        ldsm_x4(t0, bb0 + (kB ^ bXor[0]));
                        ldsm_x4(t1, bb1 + (kB ^ bXor[1]));
                        b[0][0] = t0[0]; b[0][1] = t0[1]; b[1][0] = t0[2]; b[1][1] = t0[3];
                        b[2][0] = t1[0]; b[2][1] = t1[1]; b[3][0] = t1[2]; b[3][1] = t1[3];
                    }
                    uint32_t a[2][4];
                    ldsm_x4(a[0], aa0 + (kA ^ aXor[0]));
                    ldsm_x4(a[1], aa1 + (kA ^ aXor[1]));
#pragma unroll
                    for (int mf = 0; mf < 2; mf++)
#pragma unroll
                        for (int nf = 0; nf < 4; nf++)
                            mma16816(acc[mf][nf], a[mf], b[nf]);
                }

                if (kc == 3) {
                    const float* csqp = scsq + codeBase + nsub * 128 + wn * 32 + 2 * (lane & 3);
#pragma unroll
                    for (int nf = 0; nf < 4; nf++) {
                        float q0 = csqp[nf * 8];
                        float q1 = csqp[nf * 8 + 1];
                        int n0 = codeBase + nsub * 128 + wn * 32 + nf * 8 + 2 * (lane & 3);
#pragma unroll
                        for (int mf = 0; mf < 2; mf++) {
#pragma unroll
                            for (int h = 0; h < 2; h++) {
                                int s = mf * 2 + h;
#pragma unroll
                                for (int w = 0; w < 2; w++) {
                                    float d = (w ? q1 : q0) - 2.f * acc[mf][nf][h * 2 + w];
                                    unsigned mk = mono(d);
                                    unsigned long long pk =
                                        ((unsigned long long)mk << 32) | (unsigned)(n0 + w);
                                    if (pk < p1[s]) {
                                        m2[s] = min(m2[s], (unsigned)(p1[s] >> 32));
                                        p1[s] = pk;
                                    } else {
                                        m2[s] = min(m2[s], mk);
                                    }
                                }
                            }
                        }
                    }
                }

                if (c + 3 < 8) {
                    const int cc = c + 3;
                    const int kc2 = cc & 3;
                    const int st2 = cc & 3;
                    const char* bs2 = bsrc + (size_t)((cc >> 2) * 128) * 1024;
#pragma unroll
                    for (int v = 0; v < 4; v++)
                        cp16(sbB + st2 * 16384 + bDst[v], bs2 + bSrc[v] + kc2 * 128);
                    CP_COMMIT();
                }
            }

            // per-codeTile (best1,idx,best2) reduce
            __syncthreads();
#pragma unroll
            for (int s = 0; s < 4; s++) {
                unsigned long long p = p1[s];
                unsigned m = m2[s];
#pragma unroll
                for (int off = 1; off <= 2; off <<= 1) {
                    unsigned long long op = __shfl_xor_sync(0xffffffffu, p, off);
                    unsigned om = __shfl_xor_sync(0xffffffffu, m, off);
                    if (op < p) {
                        m = min(min(m, (unsigned)(p >> 32)), om);
                        p = op;
                    } else {
                        m = min(min(m, (unsigned)(op >> 32)), om);
                    }
                }
                if ((lane & 3) == 0) {
                    int row = wm * 32 + (s >> 1) * 16 + (lane >> 2) + (s & 1) * 8;
                    sp1[row * 4 + wn] = p;
                    sm2[row * 4 + wn] = m;
                }
            }
            __syncthreads();
            if (tid < 64) {
                unsigned long long p = sp1[tid * 4];
                unsigned m = sm2[tid * 4];
#pragma unroll
                for (int t = 1; t < 4; t++) {
                    unsigned long long op = sp1[tid * 4 + t];
                    unsigned om = sm2[tid * 4 + t];
                    if (op < p) {
                        m = min(min(m, (unsigned)(p >> 32)), om);
                        p = op;
                    } else {
                        m = min(min(m, (unsigned)(op >> 32)), om);
                    }
                }
                ulonglong2 r;
                r.x = p; r.y = (unsigned long long)m;
                g_tres[(size_t)(rowBase + tid) * 4 + codeTile] = r;
            }
        }
    }
}

// ---------------- K5: select winners / build refine list -------------------------
__global__ void k_select() {
    int row = blockIdx.x * 256 + threadIdx.x;
    const ulonglong2* tr = &g_tres[(size_t)row * 4];
    ulonglong2 r0 = tr[0];
    unsigned long long p = r0.x;
    unsigned m = (unsigned)r0.y;
#pragma unroll
    for (int t = 1; t < 4; t++) {
        ulonglong2 rt = tr[t];
        unsigned long long op = rt.x;
        unsigned om = (unsigned)rt.y;
        if (op < p) {
            m = min(min(m, (unsigned)(p >> 32)), om);
            p = op;
        } else {
            m = min(min(m, (unsigned)(op >> 32)), om);
        }
    }
    float b1 = unmono((unsigned)(p >> 32));
    float b2 = unmono(m);
    bool refine = (b2 - b1 < THRESH);
    g_packed[row] = refine ? 0xFFFFFFFFFFFFFFFFull : p;
    if (refine) {
        int pos = atomicAdd(&g_nref, 1);
        g_reflist[pos] = row;
    }
}

// ---------------- K6: fp16x3 HMMA refine of flagged rows (gathered tiles) --------
#define NSTG     5
#define RB_OFF   131072                    // A: xh 64KB + xl 64KB
#define RCSQ_OFF (RB_OFF + NSTG * 16384)   // 212992
#define RSP_OFF  (RCSQ_OFF + 4096)         // 217088  u64[128][4]
#define RROW_OFF (RSP_OFF + 4096)          // 221184  int[128]
#define RSMEMSZ  (RROW_OFF + 512)          // 221696

__global__ void __launch_bounds__(512, 1) k_refmma(const float* __restrict__ x) {
    extern __shared__ char smem[];
    const uint32_t sbA = s2u(smem);
    const uint32_t sbB = sbA + RB_OFF;
    const int tid  = threadIdx.x;
    const int lane = tid & 31;
    const int wid  = tid >> 5;
    const int wm   = wid >> 2;
    const int wn   = wid & 3;

    const int nref = g_nref;
    const int ntick = ((nref + 127) >> 7) << 2;
    if (ntick == 0) return;

    if (tid < 256)
        ((float4*)(smem + RCSQ_OFF))[tid] = ((const float4*)g_csq)[tid];
    unsigned long long* sp1 = (unsigned long long*)(smem + RSP_OFF);
    int* srow = (int*)(smem + RROW_OFF);
    const float* scsq = (const float*)(smem + RCSQ_OFF);

    const int colA = tid & 63;
    const float4 scv = ((const float4*)g_scale)[colA];
    const float4 shv = ((const float4*)g_shift)[colA];

    const uint32_t aM  = (uint32_t)((lane & 7) + 8 * ((lane >> 3) & 1));
    const uint32_t aKG = (uint32_t)((lane >> 4) << 4);
    const uint32_t bN  = (uint32_t)(((lane >> 4) << 3) + (lane & 7));
    const uint32_t bKG = (uint32_t)(((lane >> 3) & 1) << 4);

    uint32_t aBase[4], aXor[4], bBase[2], bXor[2];
#pragma unroll
    for (int mf = 0; mf < 4; mf++) {
        uint32_t r = wm * 32 + (mf & 1) * 16 + aM;   // only mf<2 used; pad safe
        aBase[mf] = r << 7;
        aXor[mf]  = (r & 7) << 4;
    }
#pragma unroll
    for (int np = 0; np < 2; np++) {
        uint32_t r = wn * 32 + np * 16 + bN;
        bBase[np] = r << 7;
        bXor[np]  = (r & 7) << 4;
    }
    uint32_t bDst[2], bSrc[2];
#pragma unroll
    for (int v = 0; v < 2; v++) {
        uint32_t idx = (uint32_t)tid + v * 512;
        uint32_t r = idx >> 3, j = idx & 7;
        bDst[v] = (r << 7) + ((j << 4) ^ ((r & 7) << 4));
        bSrc[v] = r * 1024 + j * 16;
    }

#pragma unroll 1
    for (int tk = blockIdx.x; tk < ntick; tk += 148) {
        const int rowBaseR = (tk >> 2) << 7;
        const int codeBase = (tk & 3) << 8;
        const char* bsrc = (const char*)(g_eB2 + (size_t)codeBase * 512);

        __syncthreads();
        if (tid < 128)
            srow[tid] = (rowBaseR + tid < nref) ? g_reflist[rowBaseR + tid] : -1;
        __syncthreads();

        // ---- B prologue: stages 0..3 = (nsub=0, eh, kc=0..3) ----
#pragma unroll
        for (int c0 = 0; c0 < 4; c0++) {
#pragma unroll
            for (int v = 0; v < 2; v++)
                cp16(sbB + c0 * 16384 + bDst[v], bsrc + bSrc[v] + c0 * 128);
            CP_COMMIT();
        }

        // ---- A gather/convert: hi + lo ----
        {
            const float4* xs = (const float4*)x;
            const int kc = colA >> 4;
            const int kb = (colA & 15) * 4;
#pragma unroll 4
            for (int i = 0; i < 16; i++) {
                int m = (tid >> 6) + i * 8;
                int grow = srow[m];
                if (grow < 0) grow = 0;
                float4 v = xs[(size_t)grow * 64 + colA];
                float b0 = v.x * scv.x + shv.x;
                float b1 = v.y * scv.y + shv.y;
                float b2 = v.z * scv.z + shv.z;
                float b3 = v.w * scv.w + shv.w;
                __half2 h01 = __floats2half2_rn(b0, b1);
                __half2 h23 = __floats2half2_rn(b2, b3);
                __half2 l01 = __floats2half2_rn(b0 - __low2float(h01), b1 - __high2float(h01));
                __half2 l23 = __floats2half2_rn(b2 - __low2float(h23), b3 - __high2float(h23));
                uint32_t so = swz((uint32_t)(m << 7) + (uint32_t)kb * 2);
                asm volatile("st.shared.v2.u32 [%0], {%1,%2};"
                             :: "r"(sbA + kc * 16384 + so),
                                "r"(*(uint32_t*)&h01), "r"(*(uint32_t*)&h23));
                asm volatile("st.shared.v2.u32 [%0], {%1,%2};"
                             :: "r"(sbA + 65536 + kc * 16384 + so),
                                "r"(*(uint32_t*)&l01), "r"(*(uint32_t*)&l23));
            }
        }

        unsigned long long p1[4];
#pragma unroll
        for (int s = 0; s < 4; s++) p1[s] = 0xFFFFFFFFFFFFFFFFull;

        float acc[2][4][4];

        // ---- mainloop: 16 chunks (2 nsub x {eh kc0-3, el kc0-3}) ----
#pragma unroll 1
        for (int c = 0; c < 16; c++) {
            const int nsub = c >> 3;
            const int within = c & 7;
            const int cls = within >> 2;     // 0 = eh (dual), 1 = el (single)
            const int kc = c & 3;
            const int stage = c % NSTG;

            if (c <= 12)      CP_WAIT(3);
            else if (c == 13) CP_WAIT(2);
            else if (c == 14) CP_WAIT(1);
            else              CP_WAIT(0);
            __syncthreads();

            if (within == 0) {
#pragma unroll
                for (int mf = 0; mf < 2; mf++)
#pragma unroll
                    for (int nf = 0; nf < 4; nf++)
#pragma unroll
                        for (int t = 0; t < 4; t++) acc[mf][nf][t] = 0.f;
            }

            const uint32_t bb0 = sbB + stage * 16384 + bBase[0];
            const uint32_t bb1 = sbB + stage * 16384 + bBase[1];
            const uint32_t aa0 = sbA + kc * 16384 + aBase[0];
            const uint32_t aa1 = sbA + kc * 16384 + aBase[1];
#pragma unroll
            for (int ks = 0; ks < 4; ks++) {
                const uint32_t kA = ks * 32 + aKG;
                const uint32_t kB = ks * 32 + bKG;
                uint32_t b[4][2];
                {
                    uint32_t t0[4], t1[4];
                    ldsm_x4(t0, bb0 + (kB ^ bXor[0]));
                    ldsm_x4(t1, bb1 + (kB ^ bXor[1]));
                    b[0][0] = t0[0]; b[0][1] = t0[1]; b[1][0] = t0[2]; b[1][1] = t0[3];
                    b[2][0] = t1[0]; b[2][1] = t1[1]; b[3][0] = t1[2]; b[3][1] = t1[3];
                }
                uint32_t a[2][4];
                ldsm_x4(a[0], aa0 + (kA ^ aXor[0]));
                ldsm_x4(a[1], aa1 + (kA ^ aXor[1]));
#pragma unroll
                for (int mf = 0; mf < 2; mf++)
#pragma unroll
                    for (int nf = 0; nf < 4; nf++)
                        mma16816(acc[mf][nf], a[mf], b[nf]);
                if (cls == 0) {
                    uint32_t a2[2][4];
                    ldsm_x4(a2[0], aa0 + 65536 + (kA ^ aXor[0]));
                    ldsm_x4(a2[1], aa1 + 65536 + (kA ^ aXor[1]));
#pragma unroll
                    for (int mf = 0; mf < 2; mf++)
#pragma unroll
                        for (int nf = 0; nf < 4; nf++)
                            mma16816(acc[mf][nf], a2[mf], b[nf]);
                }
            }

            if (within == 7) {
                const float* csqp = scsq + codeBase + nsub * 128 + wn * 32 + 2 * (lane & 3);
#pragma unroll
                for (int nf = 0; nf < 4; nf++) {
                    float q0 = csqp[nf * 8];
                    float q1 = csqp[nf * 8 + 1];
                    int n0 = codeBase + nsub * 128 + wn * 32 + nf * 8 + 2 * (lane & 3);
#pragma unroll
                    for (int mf = 0; mf < 2; mf++) {
#pragma unroll
                        for (int h = 0; h < 2; h++) {
                            int s = mf * 2 + h;
#pragma unroll
                            for (int w = 0; w < 2; w++) {
                                float d = (w ? q1 : q0) - 2.f * acc[mf][nf][h * 2 + w];
                                unsigned long long pk =
                                    ((unsigned long long)mono(d) << 32) | (unsigned)(n0 + w);
                                if (pk < p1[s]) p1[s] = pk;
                            }
                        }
                    }
                }
            }

            if (c + 4 < 16) {
                const int cc = c + 4;
                const int nsub2 = cc >> 3, cls2 = (cc >> 2) & 1, kc2 = cc & 3;
                const int st2 = cc % NSTG;
                const char* bs2 = bsrc + (size_t)(nsub2 * 128) * 1024;
#pragma unroll
                for (int v = 0; v < 2; v++)
                    cp16(sbB + st2 * 16384 + bDst[v], bs2 + bSrc[v] + cls2 * 512 + kc2 * 128);
                CP_COMMIT();
            }
        }

        // ---- reduce + merge ----
        __syncthreads();
#pragma unroll
        for (int s = 0; s < 4; s++) {
            unsigned long long p = p1[s];
#pragma unroll
            for (int off = 1; off <= 2; off <<= 1) {
                unsigned long long op = __shfl_xor_sync(0xffffffffu, p, off);
                if (op < p) p = op;
            }
            if ((lane & 3) == 0) {
                int row = wm * 32 + (s >> 1) * 16 + (lane >> 2) + (s & 1) * 8;
                sp1[row * 4 + wn] = p;
            }
        }
        __syncthreads();
        if (tid < 128) {
            int grow = srow[tid];
            if (grow >= 0) {
                unsigned long long p = sp1[tid * 4];
#pragma unroll
                for (int t = 1; t < 4; t++) {
                    unsigned long long op = sp1[tid * 4 + t];
                    if (op < p) p = op;
                }
                atomicMin(&g_packed[grow], p);
            }
        }
    }
}

// ---------------- K7: gather q, output, loss, counts, idx ------------------------
__global__ void k_quant(const int* __restrict__ mask,
                        float* __restrict__ outQ, float* __restrict__ outIdx) {
    int w = threadIdx.x >> 5, lane = threadIdx.x & 31;
    int row = blockIdx.x * 8 + w;
    int m = mask[row];
    unsigned long long pk = g_packed[row];
    int idx = (int)(pk & 0xffffffffull);
    const float4* qv = (const float4*)&g_ET[(size_t)idx * DDIM];
    float4* ov = (float4*)&outQ[(size_t)row * DDIM];
    float4 z = make_float4(0.f, 0.f, 0.f, 0.f);
#pragma unroll
    for (int t = 0; t < 2; t++) {
        int j = lane + t * 32;
        ov[j] = m ? qv[j] : z;
    }
    __shared__ float red[8];
    if (lane == 0) {
        float best = unmono((unsigned)(pk >> 32));
        red[w] = m ? (g_xsq[row] + best) : 0.f;
        outIdx[row] = m ? (float)idx : -1.f;
        if (m) atomicAdd(&g_counts[idx], 1.f);
    }
    __syncthreads();
    if (threadIdx.x == 0) {
        float t = 0.f;
        for (int i = 0; i < 8; i++) t += red[i];
        atomicAdd(&g_loss, (double)t);
    }
}

// ---------------- K8: finalize scalars -------------------------------------------
__global__ void k_final(float* __restrict__ out) {
    int t = threadIdx.x;  // 1024 threads
    float nv = fmaxf(g_cnt, 1.f);
    float p = g_counts[t] / nv;
    float h = -p * logf(p + 1e-10f);
    for (int o = 16; o; o >>= 1) h += __shfl_down_sync(0xffffffffu, h, o);
    __shared__ float red[32];
    if ((t & 31) == 0) red[t >> 5] = h;
    __syncthreads();
    if (t < 32) {
        float s = red[t];
        for (int o = 16; o; o >>= 1) s += __shfl_down_sync(0xffffffffu, s, o);
        if (t == 0) {
            float loss = (float)(g_loss / ((double)nv * (double)DDIM));
            out[OFF_DICT]   = loss;
            out[OFF_COMMIT] = loss;
            out[OFF_PERP]   = expf(s);
        }
    }
}

// ---------------- launch ------------------------------------------------------------
extern "C" void kernel_launch(void* const* d_in, const int* in_sizes, int n_in,
                              void* d_out, int out_size) {
    const float* x     = (const float*)d_in[0];
    const int*   mask  = (const int*)  d_in[1];
    const float* E     = (const float*)d_in[2];
    const float* gamma = (const float*)d_in[3];
    const float* beta  = (const float*)d_in[4];
    float* out = (float*)d_out;

    cudaFuncSetAttribute(k_coarse, cudaFuncAttributeMaxDynamicSharedMemorySize, SMEMSZ);
    cudaFuncSetAttribute(k_refmma, cudaFuncAttributeMaxDynamicSharedMemorySize, RSMEMSZ);

    k_stats<<<256, dim3(64, 4)>>>(x, mask);                  // 1
    k_prep_e<<<32, dim3(32, 8)>>>(E);                        // 2
    k_reduce_stats<<<1, 256>>>(gamma, beta);                 // 3
    k_coarse<<<296, 256, SMEMSZ>>>(x);                       // 4  (ncu lands here)
    k_select<<<128, 256>>>();                                // 5
    k_refmma<<<148, 512, RSMEMSZ>>>(x);                      // 6
    k_quant<<<BNROWS / 8, 256>>>(mask, out + OFF_Q, out + OFF_IDX);
    k_final<<<1, 1024>>>(out);
}

// round 16
// speedup vs baseline: 2.8875x; 1.0152x over previous
#include <cuda_runtime.h>
#include <cuda_fp16.h>
#include <cstdint>
#include <math.h>

// Problem dims
#define BNROWS 32768   // B*N
#define DDIM   256
#define KCODES 1024
#define THRESH 6.0f

// Output layout (float32, reference return order)
#define OFF_Q      0ull
#define OFF_DICT   8388608ull
#define OFF_COMMIT 8388609ull
#define OFF_IDX    8388610ull
#define OFF_PERP   8421378ull

// ---------------- scratch (device globals) -----------------------------------
__device__ float  g_partS [256][DDIM];
__device__ float  g_partS2[256][DDIM];
__device__ float  g_partC [256];
__device__ float  g_cnt;
__device__ __align__(16) float g_scale[DDIM];
__device__ __align__(16) float g_shift[DDIM];
__device__ __align__(16) __half g_eB2[(size_t)KCODES * 512]; // [e_h(256) | e_l(256)] per code
__device__ __align__(16) float g_ET[(size_t)KCODES * DDIM];  // codebook^T [K][D]
__device__ __align__(16) float g_csq[KCODES];
__device__ float  g_xsq[BNROWS];
__device__ __align__(16) ulonglong2 g_tres[(size_t)BNROWS * 4]; // per (row, codeTile): {p1, m2}
__device__ unsigned long long g_packed[BNROWS];                 // (mono(d)<<32)|idx
__device__ int    g_reflist[BNROWS];
__device__ int    g_nref;
__device__ float  g_counts[KCODES];
__device__ double g_loss;
__device__ int    g_ticket;

// ---------------- helpers ------------------------------------------------------
__device__ __forceinline__ uint32_t s2u(const void* p) {
    uint32_t a;
    asm("{ .reg .u64 t; cvta.to.shared.u64 t, %1; cvt.u32.u64 %0, t; }" : "=r"(a) : "l"(p));
    return a;
}
__device__ __forceinline__ uint32_t swz(uint32_t off) { return off ^ ((off >> 3) & 0x70); }

__device__ __forceinline__ void cp16(uint32_t dst, const void* src) {
    asm volatile("cp.async.cg.shared.global [%0], [%1], 16;" :: "r"(dst), "l"(src) : "memory");
}
#define CP_COMMIT() asm volatile("cp.async.commit_group;" ::: "memory")
#define CP_WAIT(N)  asm volatile("cp.async.wait_group %0;" :: "n"(N) : "memory")

__device__ __forceinline__ void ldsm_x4(uint32_t* r, uint32_t addr) {
    asm volatile("ldmatrix.sync.aligned.m8n8.x4.shared.b16 {%0,%1,%2,%3}, [%4];"
                 : "=r"(r[0]), "=r"(r[1]), "=r"(r[2]), "=r"(r[3]) : "r"(addr));
}
__device__ __forceinline__ void mma16816(float* c, const uint32_t* a, const uint32_t* b) {
    asm volatile(
        "mma.sync.aligned.m16n8k16.row.col.f32.f16.f16.f32 "
        "{%0,%1,%2,%3}, {%4,%5,%6,%7}, {%8,%9}, {%0,%1,%2,%3};"
        : "+f"(c[0]), "+f"(c[1]), "+f"(c[2]), "+f"(c[3])
        : "r"(a[0]), "r"(a[1]), "r"(a[2]), "r"(a[3]), "r"(b[0]), "r"(b[1]));
}
__device__ __forceinline__ unsigned mono(float d) {
    unsigned u = __float_as_uint(d);
    return ((int)u < 0) ? ~u : (u | 0x80000000u);
}
__device__ __forceinline__ float unmono(unsigned k) {
    unsigned u = (k & 0x80000000u) ? (k & 0x7fffffffu) : ~k;
    return __uint_as_float(u);
}

// ---------------- K1: masked stats partials -------------------------------------
__global__ void k_stats(const float* __restrict__ x, const int* __restrict__ mask) {
    int d4 = threadIdx.x;   // 0..63
    int ty = threadIdx.y;   // 0..3
    int b  = blockIdx.x;
    int r0 = b * 128 + ty * 32;
    const float4* x4 = (const float4*)x;
    float4 s  = make_float4(0.f, 0.f, 0.f, 0.f);
    float4 s2 = make_float4(0.f, 0.f, 0.f, 0.f);
    float  c  = 0.f;
    for (int r = 0; r < 32; r++) {
        if (mask[r0 + r]) {
            float4 v = x4[(size_t)(r0 + r) * 64 + d4];
            s.x += v.x; s.y += v.y; s.z += v.z; s.w += v.w;
            s2.x += v.x * v.x; s2.y += v.y * v.y; s2.z += v.z * v.z; s2.w += v.w * v.w;
            c += 1.f;
        }
    }
    __shared__ float4 sS[4][64], sS2[4][64];
    __shared__ float  sC[4];
    sS[ty][d4] = s; sS2[ty][d4] = s2;
    if (d4 == 0) sC[ty] = c;
    __syncthreads();
    if (ty == 0) {
        for (int y = 1; y < 4; y++) {
            float4 a = sS[y][d4], a2 = sS2[y][d4];
            s.x += a.x; s.y += a.y; s.z += a.z; s.w += a.w;
            s2.x += a2.x; s2.y += a2.y; s2.z += a2.z; s2.w += a2.w;
        }
        ((float4*)g_partS [b])[d4] = s;
        ((float4*)g_partS2[b])[d4] = s2;
        if (d4 == 0) g_partC[b] = sC[0] + sC[1] + sC[2] + sC[3];
    }
}

// ---------------- K2: transpose E + fp16 hi/lo + deterministic csq ---------------
__global__ void k_prep_e(const float* __restrict__ E) {   // grid 32, block (32,8)
    int tx = threadIdx.x;  // code local
    int ty = threadIdx.y;  // d group
    int code = blockIdx.x * 32 + tx;
    float sq = 0.f;
    for (int d = ty; d < DDIM; d += 8) {
        float v = E[(size_t)d * KCODES + code];
        g_ET[(size_t)code * DDIM + d] = v;
        __half h = __float2half_rn(v);
        g_eB2[(size_t)code * 512 + d]       = h;
        g_eB2[(size_t)code * 512 + 256 + d] = __float2half_rn(v - __half2float(h));
        sq = fmaf(v, v, sq);
    }
    __shared__ float ssq[8][32];
    ssq[ty][tx] = sq;
    __syncthreads();
    if (ty == 0) {
        float s = 0.f;
        for (int i = 0; i < 8; i++) s += ssq[i][tx];
        g_csq[code] = s;
    }
}

// ---------------- K3: reduce stats -> scale/shift; zero run state ----------------
__global__ void k_reduce_stats(const float* __restrict__ gamma, const float* __restrict__ beta) {
    int d = threadIdx.x;
    float s = 0.f, s2 = 0.f, cnt = 0.f;
#pragma unroll 8
    for (int b = 0; b < 256; b++) {
        s  += g_partS [b][d];
        s2 += g_partS2[b][d];
        cnt += g_partC[b];
    }
    for (int i = d; i < KCODES; i += 256) g_counts[i] = 0.f;
    if (d == 0) { g_cnt = cnt; g_loss = 0.0; g_ticket = 0; g_nref = 0; }
    float nv = fmaxf(cnt, 1.f);
    float mu  = s / nv;
    float var = s2 / nv - mu * mu;
    float sc  = rsqrtf(var + 1e-5f) * gamma[d];
    g_scale[d] = sc;
    g_shift[d] = beta[d] - mu * sc;
}

// ---------------- K4: persistent coarse GEMM, 2 CTAs/SM -----------------------------
// 2-stage x 32KB double buffer (stage = 2 standard 16KB kc-chunks). One
// CP_WAIT(0)+__syncthreads per stage; next stage issued right after the barrier
// into the stage consumed last iteration. Syncs per rowTile: 34 -> 18.
#define NROWT    512
#define CA_BOFF  32768
#define CA_CSQ   (CA_BOFF + 2 * 32768)   // 98304
#define CA_XSQ   (CA_CSQ + 4096)         // 102400
#define CA_SP1   (CA_XSQ + 512)          // 102912
#define CA_SM2   (CA_SP1 + 2048)         // 104960
#define CA_TK    (CA_SM2 + 1024)         // 105984
#define SMEMSZ   (CA_TK + 16)            // 106000

__global__ void __launch_bounds__(256, 2) k_coarse(const float* __restrict__ x) {
    extern __shared__ char smem[];
    const uint32_t sbA = s2u(smem);
    const uint32_t sbB = sbA + CA_BOFF;
    const int tid  = threadIdx.x;
    const int lane = tid & 31;
    const int wid  = tid >> 5;
    const int wm   = wid >> 2;       // 0..1
    const int wn   = wid & 3;        // 0..3

    ((float4*)(smem + CA_CSQ))[tid] = ((const float4*)g_csq)[tid];
    int* s_tk = (int*)(smem + CA_TK);
    float* sxsq = (float*)(smem + CA_XSQ);
    unsigned long long* sp1 = (unsigned long long*)(smem + CA_SP1);  // [64][4]
    unsigned* sm2 = (unsigned*)(smem + CA_SM2);                      // [64][4]
    const float* scsq = (const float*)(smem + CA_CSQ);

    const int colA = tid & 63;
    const float4 scv = ((const float4*)g_scale)[colA];
    const float4 shv = ((const float4*)g_shift)[colA];

    const uint32_t aM  = (uint32_t)((lane & 7) + 8 * ((lane >> 3) & 1));
    const uint32_t aKG = (uint32_t)((lane >> 4) << 4);
    const uint32_t bN  = (uint32_t)(((lane >> 4) << 3) + (lane & 7));
    const uint32_t bKG = (uint32_t)(((lane >> 3) & 1) << 4);

    uint32_t aBase[2], aXor[2], bBase[2], bXor[2];
#pragma unroll
    for (int mf = 0; mf < 2; mf++) {
        uint32_t r = wm * 32 + mf * 16 + aM;
        aBase[mf] = r << 7;
        aXor[mf]  = (r & 7) << 4;
    }
#pragma unroll
    for (int np = 0; np < 2; np++) {
        uint32_t r = wn * 32 + np * 16 + bN;
        bBase[np] = r << 7;
        bXor[np]  = (r & 7) << 4;
    }
    uint32_t bDst[4], bSrc[4];
#pragma unroll
    for (int v = 0; v < 4; v++) {
        uint32_t idx = (uint32_t)tid + v * 256;
        uint32_t r = idx >> 3, j = idx & 7;
        bDst[v] = (r << 7) + ((j << 4) ^ ((r & 7) << 4));
        bSrc[v] = r * 1024 + j * 16;
    }

    for (;;) {
        __syncthreads();
        if (tid == 0) *s_tk = atomicAdd(&g_ticket, 1);
        __syncthreads();
        const int rowTile = *s_tk;
        if (rowTile >= NROWT) break;
        const int rowBase = rowTile << 6;    // 64 rows

        // ---- A load/convert: once per rowTile ----
        {
            const float4* xs = (const float4*)(x + (size_t)rowBase * DDIM);
            const int kc = colA >> 4;
            const int kb = (colA & 15) * 4;
#pragma unroll 4
            for (int i = 0; i < 16; i++) {
                int m = (tid >> 6) + i * 4;
                float4 v = xs[(size_t)m * 64 + colA];
                float b0 = v.x * scv.x + shv.x;
                float b1 = v.y * scv.y + shv.y;
                float b2 = v.z * scv.z + shv.z;
                float b3 = v.w * scv.w + shv.w;
                __half2 h01 = __floats2half2_rn(b0, b1);
                __half2 h23 = __floats2half2_rn(b2, b3);
                uint32_t so = swz((uint32_t)(m << 7) + (uint32_t)kb * 2);
                asm volatile("st.shared.v2.u32 [%0], {%1,%2};"
                             :: "r"(sbA + kc * 8192 + so),
                                "r"(*(uint32_t*)&h01), "r"(*(uint32_t*)&h23));
                float s = b0 * b0 + b1 * b1 + b2 * b2 + b3 * b3;
                for (int o = 16; o; o >>= 1) s += __shfl_down_sync(0xffffffffu, s, o);
                if (lane == 0) sxsq[m * 2 + (wid & 1)] = s;
            }
            __syncthreads();
            if (tid < 64) g_xsq[rowBase + tid] = sxsq[tid * 2] + sxsq[tid * 2 + 1];
        }

        // ---- loop over 4 code tiles with resident A ----
#pragma unroll 1
        for (int codeTile = 0; codeTile < 4; codeTile++) {
            const int codeBase = codeTile << 8;
            const char* bsrc = (const char*)(g_eB2 + (size_t)codeBase * 512);

            // prologue: super-chunk C0 = (nsub0, kc0+kc1) -> stage0
#pragma unroll
            for (int sub = 0; sub < 2; sub++)
#pragma unroll
                for (int v = 0; v < 4; v++)
                    cp16(sbB + sub * 16384 + bDst[v], bsrc + bSrc[v] + sub * 128);
            CP_COMMIT();

            float acc[2][4][4];
            unsigned long long p1[4];
            unsigned m2[4];
#pragma unroll
            for (int s = 0; s < 4; s++) { p1[s] = 0xFFFFFFFFFFFFFFFFull; m2[s] = 0xFFFFFFFFu; }

            // mainloop: 4 super-chunks (2 nsub x 2 kc-pairs), 2-stage double buffer
#pragma unroll 1
            for (int c = 0; c < 4; c++) {
                const int nsub = c >> 1;
                const int kp = c & 1;
                const int stage = c & 1;

                CP_WAIT(0);
                __syncthreads();

                // prefetch next super-chunk into the just-freed stage
                if (c + 1 < 4) {
                    const int cn = c + 1;
                    const char* bs2 = bsrc + (size_t)((cn >> 1) * 128) * 1024;
                    const int kb0 = (cn & 1) * 2;
#pragma unroll
                    for (int sub = 0; sub < 2; sub++)
#pragma unroll
                        for (int v = 0; v < 4; v++)
                            cp16(sbB + ((cn & 1) * 32768) + sub * 16384 + bDst[v],
                                 bs2 + bSrc[v] + (kb0 + sub) * 128);
                    CP_COMMIT();
                }

                if (kp == 0) {
#pragma unroll
                    for (int mf = 0; mf < 2; mf++)
#pragma unroll
                        for (int nf = 0; nf < 4; nf++)
#pragma unroll
                            for (int t = 0; t < 4; t++) acc[mf][nf][t] = 0.f;
                }

#pragma unroll
                for (int kk = 0; kk < 2; kk++) {
                    const int kc = kp * 2 + kk;
                    const uint32_t bstg = sbB + stage * 32768 + kk * 16384;
                    const uint32_t bb0 = bstg + bBase[0];
                    const uint32_t bb1 = bstg + bBase[1];
                    const uint32_t aa0 = sbA + kc * 8192 + aBase[0];
                    const uint32_t aa1 = sbA + kc * 8192 + aBase[1];
#pragma unroll
                    for (int ks = 0; ks < 4; ks++) {
                        const uint32_t kA = ks * 32 + aKG;
                        const uint32_t kB = ks * 32 + bKG;
                        uint32_t b[4][2];
                        {
                            uint32_t t0[4], t1[4];
                            ldsm_x4(t0, bb0 + (kB ^ bXor[0]));
                            ldsm_x4(t1, bb1 + (kB ^ bXor[1]));
                            b[0][0] = t0[0]; b[0][1] = t0[1]; b[1][0] = t0[2]; b[1][1] = t0[3];
                            b[2][0] = t1[0]; b[2][1] = t1[1]; b[3][0] = t1[2]; b[3][1] = t1[3];
                        }
                        uint32_t a[2][4];
                        ldsm_x4(a[0], aa0 + (kA ^ aXor[0]));
                        ldsm_x4(a[1], aa1 + (kA ^ aXor[1]));
#pragma unroll
                        for (int mf = 0; mf < 2; mf++)
#pragma unroll
                            for (int nf = 0; nf < 4; nf++)
                                mma16816(acc[mf][nf], a[mf], b[nf]);
                    }
                }

                if (kp == 1) {
                    const float* csqp = scsq + codeBase + nsub * 128 + wn * 32 + 2 * (lane & 3);
#pragma unroll
                    for (int nf = 0; nf < 4; nf++) {
                        float q0 = csqp[nf * 8];
                        float q1 = csqp[nf * 8 + 1];
                        int n0 = codeBase + nsub * 128 + wn * 32 + nf * 8 + 2 * (lane & 3);
#pragma unroll
                        for (int mf = 0; mf < 2; mf++) {
#pragma unroll
                            for (int h = 0; h < 2; h++) {
                                int s = mf * 2 + h;
#pragma unroll
                                for (int w = 0; w < 2; w++) {
                                    float d = (w ? q1 : q0) - 2.f * acc[mf][nf][h * 2 + w];
                                    unsigned mk = mono(d);
                                    unsigned long long pk =
                                        ((unsigned long long)mk << 32) | (unsigned)(n0 + w);
                                    if (pk < p1[s]) {
                                        m2[s] = min(m2[s], (unsigned)(p1[s] >> 32));
                                        p1[s] = pk;
                                    } else {
                                        m2[s] = min(m2[s], mk);
                                    }
                                }
                            }
                        }
                    }
                }
            }

            // per-codeTile (best1,idx,best2) reduce
            __syncthreads();
#pragma unroll
            for (int s = 0; s < 4; s++) {
                unsigned long long p = p1[s];
                unsigned m = m2[s];
#pragma unroll
                for (int off = 1; off <= 2; off <<= 1) {
                    unsigned long long op = __shfl_xor_sync(0xffffffffu, p, off);
                    unsigned om = __shfl_xor_sync(0xffffffffu, m, off);
                    if (op < p) {
                        m = min(min(m, (unsigned)(p >> 32)), om);
                        p = op;
                    } else {
                        m = min(min(m, (unsigned)(op >> 32)), om);
                    }
                }
                if ((lane & 3) == 0) {
                    int row = wm * 32 + (s >> 1) * 16 + (lane >> 2) + (s & 1) * 8;
                    sp1[row * 4 + wn] = p;
                    sm2[row * 4 + wn] = m;
                }
            }
            __syncthreads();
            if (tid < 64) {
                unsigned long long p = sp1[tid * 4];
                unsigned m = sm2[tid * 4];
#pragma unroll
                for (int t = 1; t < 4; t++) {
                    unsigned long long op = sp1[tid * 4 + t];
                    unsigned om = sm2[tid * 4 + t];
                    if (op < p) {
                        m = min(min(m, (unsigned)(p >> 32)), om);
                        p = op;
                    } else {
                        m = min(min(m, (unsigned)(op >> 32)), om);
                    }
                }
                ulonglong2 r;
                r.x = p; r.y = (unsigned long long)m;
                g_tres[(size_t)(rowBase + tid) * 4 + codeTile] = r;
            }
        }
    }
}

// ---------------- K5: select winners / build refine list -------------------------
__global__ void k_select() {
    int row = blockIdx.x * 256 + threadIdx.x;
    const ulonglong2* tr = &g_tres[(size_t)row * 4];
    ulonglong2 r0 = tr[0];
    unsigned long long p = r0.x;
    unsigned m = (unsigned)r0.y;
#pragma unroll
    for (int t = 1; t < 4; t++) {
        ulonglong2 rt = tr[t];
        unsigned long long op = rt.x;
        unsigned om = (unsigned)rt.y;
        if (op < p) {
            m = min(min(m, (unsigned)(p >> 32)), om);
            p = op;
        } else {
            m = min(min(m, (unsigned)(op >> 32)), om);
        }
    }
    float b1 = unmono((unsigned)(p >> 32));
    float b2 = unmono(m);
    bool refine = (b2 - b1 < THRESH);
    g_packed[row] = refine ? 0xFFFFFFFFFFFFFFFFull : p;
    if (refine) {
        int pos = atomicAdd(&g_nref, 1);
        g_reflist[pos] = row;
    }
}

// ---------------- K6: fp16x3 HMMA refine of flagged rows (gathered tiles) --------
#define NSTG     5
#define RB_OFF   131072                    // A: xh 64KB + xl 64KB
#define RCSQ_OFF (RB_OFF + NSTG * 16384)   // 212992
#define RSP_OFF  (RCSQ_OFF + 4096)         // 217088  u64[128][4]
#define RROW_OFF (RSP_OFF + 4096)          // 221184  int[128]
#define RSMEMSZ  (RROW_OFF + 512)          // 221696

__global__ void __launch_bounds__(512, 1) k_refmma(const float* __restrict__ x) {
    extern __shared__ char smem[];
    const uint32_t sbA = s2u(smem);
    const uint32_t sbB = sbA + RB_OFF;
    const int tid  = threadIdx.x;
    const int lane = tid & 31;
    const int wid  = tid >> 5;
    const int wm   = wid >> 2;
    const int wn   = wid & 3;

    const int nref = g_nref;
    const int ntick = ((nref + 127) >> 7) << 2;
    if (ntick == 0) return;

    if (tid < 256)
        ((float4*)(smem + RCSQ_OFF))[tid] = ((const float4*)g_csq)[tid];
    unsigned long long* sp1 = (unsigned long long*)(smem + RSP_OFF);
    int* srow = (int*)(smem + RROW_OFF);
    const float* scsq = (const float*)(smem + RCSQ_OFF);

    const int colA = tid & 63;
    const float4 scv = ((const float4*)g_scale)[colA];
    const float4 shv = ((const float4*)g_shift)[colA];

    const uint32_t aM  = (uint32_t)((lane & 7) + 8 * ((lane >> 3) & 1));
    const uint32_t aKG = (uint32_t)((lane >> 4) << 4);
    const uint32_t bN  = (uint32_t)(((lane >> 4) << 3) + (lane & 7));
    const uint32_t bKG = (uint32_t)(((lane >> 3) & 1) << 4);

    uint32_t aBase[2], aXor[2], bBase[2], bXor[2];
#pragma unroll
    for (int mf = 0; mf < 2; mf++) {
        uint32_t r = wm * 32 + mf * 16 + aM;
        aBase[mf] = r << 7;
        aXor[mf]  = (r & 7) << 4;
    }
#pragma unroll
    for (int np = 0; np < 2; np++) {
        uint32_t r = wn * 32 + np * 16 + bN;
        bBase[np] = r << 7;
        bXor[np]  = (r & 7) << 4;
    }
    uint32_t bDst[2], bSrc[2];
#pragma unroll
    for (int v = 0; v < 2; v++) {
        uint32_t idx = (uint32_t)tid + v * 512;
        uint32_t r = idx >> 3, j = idx & 7;
        bDst[v] = (r << 7) + ((j << 4) ^ ((r & 7) << 4));
        bSrc[v] = r * 1024 + j * 16;
    }

#pragma unroll 1
    for (int tk = blockIdx.x; tk < ntick; tk += 148) {
        const int rowBaseR = (tk >> 2) << 7;
        const int codeBase = (tk & 3) << 8;
        const char* bsrc = (const char*)(g_eB2 + (size_t)codeBase * 512);

        __syncthreads();
        if (tid < 128)
            srow[tid] = (rowBaseR + tid < nref) ? g_reflist[rowBaseR + tid] : -1;
        __syncthreads();

        // ---- B prologue: stages 0..3 = (nsub=0, eh, kc=0..3) ----
#pragma unroll
        for (int c0 = 0; c0 < 4; c0++) {
#pragma unroll
            for (int v = 0; v < 2; v++)
                cp16(sbB + c0 * 16384 + bDst[v], bsrc + bSrc[v] + c0 * 128);
            CP_COMMIT();
        }

        // ---- A gather/convert: hi + lo ----
        {
            const float4* xs = (const float4*)x;
            const int kc = colA >> 4;
            const int kb = (colA & 15) * 4;
#pragma unroll 4
            for (int i = 0; i < 16; i++) {
                int m = (tid >> 6) + i * 8;
                int grow = srow[m];
                if (grow < 0) grow = 0;
                float4 v = xs[(size_t)grow * 64 + colA];
                float b0 = v.x * scv.x + shv.x;
                float b1 = v.y * scv.y + shv.y;
                float b2 = v.z * scv.z + shv.z;
                float b3 = v.w * scv.w + shv.w;
                __half2 h01 = __floats2half2_rn(b0, b1);
                __half2 h23 = __floats2half2_rn(b2, b3);
                __half2 l01 = __floats2half2_rn(b0 - __low2float(h01), b1 - __high2float(h01));
                __half2 l23 = __floats2half2_rn(b2 - __low2float(h23), b3 - __high2float(h23));
                uint32_t so = swz((uint32_t)(m << 7) + (uint32_t)kb * 2);
                asm volatile("st.shared.v2.u32 [%0], {%1,%2};"
                             :: "r"(sbA + kc * 16384 + so),
                                "r"(*(uint32_t*)&h01), "r"(*(uint32_t*)&h23));
                asm volatile("st.shared.v2.u32 [%0], {%1,%2};"
                             :: "r"(sbA + 65536 + kc * 16384 + so),
                                "r"(*(uint32_t*)&l01), "r"(*(uint32_t*)&l23));
            }
        }

        unsigned long long p1[4];
#pragma unroll
        for (int s = 0; s < 4; s++) p1[s] = 0xFFFFFFFFFFFFFFFFull;

        float acc[2][4][4];

        // ---- mainloop: 16 chunks (2 nsub x {eh kc0-3, el kc0-3}) ----
#pragma unroll 1
        for (int c = 0; c < 16; c++) {
            const int nsub = c >> 3;
            const int within = c & 7;
            const int cls = within >> 2;     // 0 = eh (dual), 1 = el (single)
            const int kc = c & 3;
            const int stage = c % NSTG;

            if (c <= 12)      CP_WAIT(3);
            else if (c == 13) CP_WAIT(2);
            else if (c == 14) CP_WAIT(1);
            else              CP_WAIT(0);
            __syncthreads();

            if (within == 0) {
#pragma unroll
                for (int mf = 0; mf < 2; mf++)
#pragma unroll
                    for (int nf = 0; nf < 4; nf++)
#pragma unroll
                        for (int t = 0; t < 4; t++) acc[mf][nf][t] = 0.f;
            }

            const uint32_t bb0 = sbB + stage * 16384 + bBase[0];
            const uint32_t bb1 = sbB + stage * 16384 + bBase[1];
            const uint32_t aa0 = sbA + kc * 16384 + aBase[0];
            const uint32_t aa1 = sbA + kc * 16384 + aBase[1];
#pragma unroll
            for (int ks = 0; ks < 4; ks++) {
                const uint32_t kA = ks * 32 + aKG;
                const uint32_t kB = ks * 32 + bKG;
                uint32_t b[4][2];
                {
                    uint32_t t0[4], t1[4];
                    ldsm_x4(t0, bb0 + (kB ^ bXor[0]));
                    ldsm_x4(t1, bb1 + (kB ^ bXor[1]));
                    b[0][0] = t0[0]; b[0][1] = t0[1]; b[1][0] = t0[2]; b[1][1] = t0[3];
                    b[2][0] = t1[0]; b[2][1] = t1[1]; b[3][0] = t1[2]; b[3][1] = t1[3];
                }
                uint32_t a[2][4];
                ldsm_x4(a[0], aa0 + (kA ^ aXor[0]));
                ldsm_x4(a[1], aa1 + (kA ^ aXor[1]));
#pragma unroll
                for (int mf = 0; mf < 2; mf++)
#pragma unroll
                    for (int nf = 0; nf < 4; nf++)
                        mma16816(acc[mf][nf], a[mf], b[nf]);
                if (cls == 0) {
                    uint32_t a2[2][4];
                    ldsm_x4(a2[0], aa0 + 65536 + (kA ^ aXor[0]));
                    ldsm_x4(a2[1], aa1 + 65536 + (kA ^ aXor[1]));
#pragma unroll
                    for (int mf = 0; mf < 2; mf++)
#pragma unroll
                        for (int nf = 0; nf < 4; nf++)
                            mma16816(acc[mf][nf], a2[mf], b[nf]);
                }
            }

            if (within == 7) {
                const float* csqp = scsq + codeBase + nsub * 128 + wn * 32 + 2 * (lane & 3);
#pragma unroll
                for (int nf = 0; nf < 4; nf++) {
                    float q0 = csqp[nf * 8];
                    float q1 = csqp[nf * 8 + 1];
                    int n0 = codeBase + nsub * 128 + wn * 32 + nf * 8 + 2 * (lane & 3);
#pragma unroll
                    for (int mf = 0; mf < 2; mf++) {
#pragma unroll
                        for (int h = 0; h < 2; h++) {
                            int s = mf * 2 + h;
#pragma unroll
                            for (int w = 0; w < 2; w++) {
                                float d = (w ? q1 : q0) - 2.f * acc[mf][nf][h * 2 + w];
                                unsigned long long pk =
                                    ((unsigned long long)mono(d) << 32) | (unsigned)(n0 + w);
                                if (pk < p1[s]) p1[s] = pk;
                            }
                        }
                    }
                }
            }

            if (c + 4 < 16) {
                const int cc = c + 4;
                const int nsub2 = cc >> 3, cls2 = (cc >> 2) & 1, kc2 = cc & 3;
                const int st2 = cc % NSTG;
                const char* bs2 = bsrc + (size_t)(nsub2 * 128) * 1024;
#pragma unroll
                for (int v = 0; v < 2; v++)
                    cp16(sbB + st2 * 16384 + bDst[v], bs2 + bSrc[v] + cls2 * 512 + kc2 * 128);
                CP_COMMIT();
            }
        }

        // ---- reduce + merge ----
        __syncthreads();
#pragma unroll
        for (int s = 0; s < 4; s++) {
            unsigned long long p = p1[s];
#pragma unroll
            for (int off = 1; off <= 2; off <<= 1) {
                unsigned long long op = __shfl_xor_sync(0xffffffffu, p, off);
                if (op < p) p = op;
            }
            if ((lane & 3) == 0) {
                int row = wm * 32 + (s >> 1) * 16 + (lane >> 2) + (s & 1) * 8;
                sp1[row * 4 + wn] = p;
            }
        }
        __syncthreads();
        if (tid < 128) {
            int grow = srow[tid];
            if (grow >= 0) {
                unsigned long long p = sp1[tid * 4];
#pragma unroll
                for (int t = 1; t < 4; t++) {
                    unsigned long long op = sp1[tid * 4 + t];
                    if (op < p) p = op;
                }
                atomicMin(&g_packed[grow], p);
            }
        }
    }
}

// ---------------- K7: gather q, output, loss, counts, idx ------------------------
__global__ void k_quant(const int* __restrict__ mask,
                        float* __restrict__ outQ, float* __restrict__ outIdx) {
    int w = threadIdx.x >> 5, lane = threadIdx.x & 31;
    int row = blockIdx.x * 8 + w;
    int m = mask[row];
    unsigned long long pk = g_packed[row];
    int idx = (int)(pk & 0xffffffffull);
    const float4* qv = (const float4*)&g_ET[(size_t)idx * DDIM];
    float4* ov = (float4*)&outQ[(size_t)row * DDIM];
    float4 z = make_float4(0.f, 0.f, 0.f, 0.f);
#pragma unroll
    for (int t = 0; t < 2; t++) {
        int j = lane + t * 32;
        ov[j] = m ? qv[j] : z;
    }
    __shared__ float red[8];
    if (lane == 0) {
        float best = unmono((unsigned)(pk >> 32));
        red[w] = m ? (g_xsq[row] + best) : 0.f;
        outIdx[row] = m ? (float)idx : -1.f;
        if (m) atomicAdd(&g_counts[idx], 1.f);
    }
    __syncthreads();
    if (threadIdx.x == 0) {
        float t = 0.f;
        for (int i = 0; i < 8; i++) t += red[i];
        atomicAdd(&g_loss, (double)t);
    }
}

// ---------------- K8: finalize scalars -------------------------------------------
__global__ void k_final(float* __restrict__ out) {
    int t = threadIdx.x;  // 1024 threads
    float nv = fmaxf(g_cnt, 1.f);
    float p = g_counts[t] / nv;
    float h = -p * logf(p + 1e-10f);
    for (int o = 16; o; o >>= 1) h += __shfl_down_sync(0xffffffffu, h, o);
    __shared__ float red[32];
    if ((t & 31) == 0) red[t >> 5] = h;
    __syncthreads();
    if (t < 32) {
        float s = red[t];
        for (int o = 16; o; o >>= 1) s += __shfl_down_sync(0xffffffffu, s, o);
        if (t == 0) {
            float loss = (float)(g_loss / ((double)nv * (double)DDIM));
            out[OFF_DICT]   = loss;
            out[OFF_COMMIT] = loss;
            out[OFF_PERP]   = expf(s);
        }
    }
}

// ---------------- launch ------------------------------------------------------------
extern "C" void kernel_launch(void* const* d_in, const int* in_sizes, int n_in,
                              void* d_out, int out_size) {
    const float* x     = (const float*)d_in[0];
    const int*   mask  = (const int*)  d_in[1];
    const float* E     = (const float*)d_in[2];
    const float* gamma = (const float*)d_in[3];
    const float* beta  = (const float*)d_in[4];
    float* out = (float*)d_out;

    cudaFuncSetAttribute(k_coarse, cudaFuncAttributeMaxDynamicSharedMemorySize, SMEMSZ);
    cudaFuncSetAttribute(k_refmma, cudaFuncAttributeMaxDynamicSharedMemorySize, RSMEMSZ);

    k_stats<<<256, dim3(64, 4)>>>(x, mask);                  // 1
    k_prep_e<<<32, dim3(32, 8)>>>(E);                        // 2
    k_reduce_stats<<<1, 256>>>(gamma, beta);                 // 3
    k_coarse<<<296, 256, SMEMSZ>>>(x);                       // 4  (ncu lands here)
    k_select<<<128, 256>>>();                                // 5
    k_refmma<<<148, 512, RSMEMSZ>>>(x);                      // 6
    k_quant<<<BNROWS / 8, 256>>>(mask, out + OFF_Q, out + OFF_IDX);
    k_final<<<1, 1024>>>(out);
}

// round 17
// speedup vs baseline: 2.9333x; 1.0158x over previous
#include <cuda_runtime.h>
#include <cuda_fp16.h>
#include <cstdint>
#include <math.h>

// Problem dims
#define BNROWS 32768   // B*N
#define DDIM   256
#define KCODES 1024
#define THRESH 6.0f

// Output layout (float32, reference return order)
#define OFF_Q      0ull
#define OFF_DICT   8388608ull
#define OFF_COMMIT 8388609ull
#define OFF_IDX    8388610ull
#define OFF_PERP   8421378ull

// ---------------- scratch (device globals) -----------------------------------
__device__ float  g_partS [256][DDIM];
__device__ float  g_partS2[256][DDIM];
__device__ float  g_partC [256];
__device__ float  g_cnt;
__device__ __align__(16) float g_scale[DDIM];
__device__ __align__(16) float g_shift[DDIM];
__device__ __align__(16) __half g_eB2[(size_t)KCODES * 512]; // [e_h(256) | e_l(256)] per code
__device__ __align__(16) float g_ET[(size_t)KCODES * DDIM];  // codebook^T [K][D]
__device__ __align__(16) float g_csq[KCODES];
__device__ float  g_xsq[BNROWS];
__device__ unsigned long long g_packed[BNROWS];              // (mono(d)<<32)|idx
__device__ int    g_reflist[BNROWS];
__device__ int    g_nref;
__device__ float  g_counts[KCODES];
__device__ double g_loss;
__device__ int    g_ticket;

// ---------------- helpers ------------------------------------------------------
__device__ __forceinline__ uint32_t s2u(const void* p) {
    uint32_t a;
    asm("{ .reg .u64 t; cvta.to.shared.u64 t, %1; cvt.u32.u64 %0, t; }" : "=r"(a) : "l"(p));
    return a;
}
__device__ __forceinline__ uint32_t swz(uint32_t off) { return off ^ ((off >> 3) & 0x70); }

__device__ __forceinline__ void cp16(uint32_t dst, const void* src) {
    asm volatile("cp.async.cg.shared.global [%0], [%1], 16;" :: "r"(dst), "l"(src) : "memory");
}
#define CP_COMMIT() asm volatile("cp.async.commit_group;" ::: "memory")
#define CP_WAIT(N)  asm volatile("cp.async.wait_group %0;" :: "n"(N) : "memory")

__device__ __forceinline__ void ldsm_x4(uint32_t* r, uint32_t addr) {
    asm volatile("ldmatrix.sync.aligned.m8n8.x4.shared.b16 {%0,%1,%2,%3}, [%4];"
                 : "=r"(r[0]), "=r"(r[1]), "=r"(r[2]), "=r"(r[3]) : "r"(addr));
}
__device__ __forceinline__ void mma16816(float* c, const uint32_t* a, const uint32_t* b) {
    asm volatile(
        "mma.sync.aligned.m16n8k16.row.col.f32.f16.f16.f32 "
        "{%0,%1,%2,%3}, {%4,%5,%6,%7}, {%8,%9}, {%0,%1,%2,%3};"
        : "+f"(c[0]), "+f"(c[1]), "+f"(c[2]), "+f"(c[3])
        : "r"(a[0]), "r"(a[1]), "r"(a[2]), "r"(a[3]), "r"(b[0]), "r"(b[1]));
}
__device__ __forceinline__ unsigned mono(float d) {
    unsigned u = __float_as_uint(d);
    return ((int)u < 0) ? ~u : (u | 0x80000000u);
}
__device__ __forceinline__ float unmono(unsigned k) {
    unsigned u = (k & 0x80000000u) ? (k & 0x7fffffffu) : ~k;
    return __uint_as_float(u);
}

// ---------------- K1: masked stats partials -------------------------------------
__global__ void k_stats(const float* __restrict__ x, const int* __restrict__ mask) {
    int d4 = threadIdx.x;   // 0..63
    int ty = threadIdx.y;   // 0..3
    int b  = blockIdx.x;
    int r0 = b * 128 + ty * 32;
    const float4* x4 = (const float4*)x;
    float4 s  = make_float4(0.f, 0.f, 0.f, 0.f);
    float4 s2 = make_float4(0.f, 0.f, 0.f, 0.f);
    float  c  = 0.f;
    for (int r = 0; r < 32; r++) {
        if (mask[r0 + r]) {
            float4 v = x4[(size_t)(r0 + r) * 64 + d4];
            s.x += v.x; s.y += v.y; s.z += v.z; s.w += v.w;
            s2.x += v.x * v.x; s2.y += v.y * v.y; s2.z += v.z * v.z; s2.w += v.w * v.w;
            c += 1.f;
        }
    }
    __shared__ float4 sS[4][64], sS2[4][64];
    __shared__ float  sC[4];
    sS[ty][d4] = s; sS2[ty][d4] = s2;
    if (d4 == 0) sC[ty] = c;
    __syncthreads();
    if (ty == 0) {
        for (int y = 1; y < 4; y++) {
            float4 a = sS[y][d4], a2 = sS2[y][d4];
            s.x += a.x; s.y += a.y; s.z += a.z; s.w += a.w;
            s2.x += a2.x; s2.y += a2.y; s2.z += a2.z; s2.w += a2.w;
        }
        ((float4*)g_partS [b])[d4] = s;
        ((float4*)g_partS2[b])[d4] = s2;
        if (d4 == 0) g_partC[b] = sC[0] + sC[1] + sC[2] + sC[3];
    }
}

// ---------------- K2: transpose E + fp16 hi/lo + deterministic csq ---------------
__global__ void k_prep_e(const float* __restrict__ E) {   // grid 32, block (32,8)
    int tx = threadIdx.x;  // code local
    int ty = threadIdx.y;  // d group
    int code = blockIdx.x * 32 + tx;
    float sq = 0.f;
    for (int d = ty; d < DDIM; d += 8) {
        float v = E[(size_t)d * KCODES + code];
        g_ET[(size_t)code * DDIM + d] = v;
        __half h = __float2half_rn(v);
        g_eB2[(size_t)code * 512 + d]       = h;
        g_eB2[(size_t)code * 512 + 256 + d] = __float2half_rn(v - __half2float(h));
        sq = fmaf(v, v, sq);
    }
    __shared__ float ssq[8][32];
    ssq[ty][tx] = sq;
    __syncthreads();
    if (ty == 0) {
        float s = 0.f;
        for (int i = 0; i < 8; i++) s += ssq[i][tx];
        g_csq[code] = s;
    }
}

// ---------------- K3: reduce stats -> scale/shift; zero run state ----------------
__global__ void k_reduce_stats(const float* __restrict__ gamma, const float* __restrict__ beta) {
    int d = threadIdx.x;
    float s = 0.f, s2 = 0.f, cnt = 0.f;
#pragma unroll 8
    for (int b = 0; b < 256; b++) {
        s  += g_partS [b][d];
        s2 += g_partS2[b][d];
        cnt += g_partC[b];
    }
    for (int i = d; i < KCODES; i += 256) g_counts[i] = 0.f;
    if (d == 0) { g_cnt = cnt; g_loss = 0.0; g_ticket = 0; g_nref = 0; }
    float nv = fmaxf(cnt, 1.f);
    float mu  = s / nv;
    float var = s2 / nv - mu * mu;
    float sc  = rsqrtf(var + 1e-5f) * gamma[d];
    g_scale[d] = sc;
    g_shift[d] = beta[d] - mu * sc;
}

// ---------------- K4: persistent coarse GEMM + fused select ------------------------
// 2-stage x 32KB double buffer; rowTile tickets; one CTA owns all 4 codeTiles of
// a rowTile, so best1/best2 merge across tiles lives in registers (tid<64) and
// select (threshold + reflist append + g_packed write) is fused in. No g_tres.
#define NROWT    512
#define CA_BOFF  32768
#define CA_CSQ   (CA_BOFF + 2 * 32768)   // 98304
#define CA_XSQ   (CA_CSQ + 4096)         // 102400
#define CA_SP1   (CA_XSQ + 512)          // 102912
#define CA_SM2   (CA_SP1 + 2048)         // 104960
#define CA_TK    (CA_SM2 + 1024)         // 105984
#define SMEMSZ   (CA_TK + 16)            // 106000

__global__ void __launch_bounds__(256, 2) k_coarse(const float* __restrict__ x) {
    extern __shared__ char smem[];
    const uint32_t sbA = s2u(smem);
    const uint32_t sbB = sbA + CA_BOFF;
    const int tid  = threadIdx.x;
    const int lane = tid & 31;
    const int wid  = tid >> 5;
    const int wm   = wid >> 2;       // 0..1
    const int wn   = wid & 3;        // 0..3

    ((float4*)(smem + CA_CSQ))[tid] = ((const float4*)g_csq)[tid];
    int* s_tk = (int*)(smem + CA_TK);
    float* sxsq = (float*)(smem + CA_XSQ);
    unsigned long long* sp1 = (unsigned long long*)(smem + CA_SP1);  // [64][4]
    unsigned* sm2 = (unsigned*)(smem + CA_SM2);                      // [64][4]
    const float* scsq = (const float*)(smem + CA_CSQ);

    const int colA = tid & 63;
    const float4 scv = ((const float4*)g_scale)[colA];
    const float4 shv = ((const float4*)g_shift)[colA];

    const uint32_t aM  = (uint32_t)((lane & 7) + 8 * ((lane >> 3) & 1));
    const uint32_t aKG = (uint32_t)((lane >> 4) << 4);
    const uint32_t bN  = (uint32_t)(((lane >> 4) << 3) + (lane & 7));
    const uint32_t bKG = (uint32_t)(((lane >> 3) & 1) << 4);

    uint32_t aBase[2], aXor[2], bBase[2], bXor[2];
#pragma unroll
    for (int mf = 0; mf < 2; mf++) {
        uint32_t r = wm * 32 + mf * 16 + aM;
        aBase[mf] = r << 7;
        aXor[mf]  = (r & 7) << 4;
    }
#pragma unroll
    for (int np = 0; np < 2; np++) {
        uint32_t r = wn * 32 + np * 16 + bN;
        bBase[np] = r << 7;
        bXor[np]  = (r & 7) << 4;
    }
    uint32_t bDst[4], bSrc[4];
#pragma unroll
    for (int v = 0; v < 4; v++) {
        uint32_t idx = (uint32_t)tid + v * 256;
        uint32_t r = idx >> 3, j = idx & 7;
        bDst[v] = (r << 7) + ((j << 4) ^ ((r & 7) << 4));
        bSrc[v] = r * 1024 + j * 16;
    }

    for (;;) {
        __syncthreads();
        if (tid == 0) *s_tk = atomicAdd(&g_ticket, 1);
        __syncthreads();
        const int rowTile = *s_tk;
        if (rowTile >= NROWT) break;
        const int rowBase = rowTile << 6;    // 64 rows

        // ---- A load/convert: once per rowTile ----
        {
            const float4* xs = (const float4*)(x + (size_t)rowBase * DDIM);
            const int kc = colA >> 4;
            const int kb = (colA & 15) * 4;
#pragma unroll 4
            for (int i = 0; i < 16; i++) {
                int m = (tid >> 6) + i * 4;
                float4 v = xs[(size_t)m * 64 + colA];
                float b0 = v.x * scv.x + shv.x;
                float b1 = v.y * scv.y + shv.y;
                float b2 = v.z * scv.z + shv.z;
                float b3 = v.w * scv.w + shv.w;
                __half2 h01 = __floats2half2_rn(b0, b1);
                __half2 h23 = __floats2half2_rn(b2, b3);
                uint32_t so = swz((uint32_t)(m << 7) + (uint32_t)kb * 2);
                asm volatile("st.shared.v2.u32 [%0], {%1,%2};"
                             :: "r"(sbA + kc * 8192 + so),
                                "r"(*(uint32_t*)&h01), "r"(*(uint32_t*)&h23));
                float s = b0 * b0 + b1 * b1 + b2 * b2 + b3 * b3;
                for (int o = 16; o; o >>= 1) s += __shfl_down_sync(0xffffffffu, s, o);
                if (lane == 0) sxsq[m * 2 + (wid & 1)] = s;
            }
            __syncthreads();
            if (tid < 64) g_xsq[rowBase + tid] = sxsq[tid * 2] + sxsq[tid * 2 + 1];
        }

        unsigned long long pAll = 0xFFFFFFFFFFFFFFFFull;   // per-row running best (tid<64)
        unsigned mAll = 0xFFFFFFFFu;                       // per-row running best2

        // ---- loop over 4 code tiles with resident A ----
#pragma unroll 1
        for (int codeTile = 0; codeTile < 4; codeTile++) {
            const int codeBase = codeTile << 8;
            const char* bsrc = (const char*)(g_eB2 + (size_t)codeBase * 512);

            // prologue: super-chunk C0 = (nsub0, kc0+kc1) -> stage0
#pragma unroll
            for (int sub = 0; sub < 2; sub++)
#pragma unroll
                for (int v = 0; v < 4; v++)
                    cp16(sbB + sub * 16384 + bDst[v], bsrc + bSrc[v] + sub * 128);
            CP_COMMIT();

            float acc[2][4][4];
            unsigned long long p1[4];
            unsigned m2[4];
#pragma unroll
            for (int s = 0; s < 4; s++) { p1[s] = 0xFFFFFFFFFFFFFFFFull; m2[s] = 0xFFFFFFFFu; }

            // mainloop: 4 super-chunks (2 nsub x 2 kc-pairs), 2-stage double buffer
#pragma unroll 1
            for (int c = 0; c < 4; c++) {
                const int nsub = c >> 1;
                const int kp = c & 1;
                const int stage = c & 1;

                CP_WAIT(0);
                __syncthreads();

                if (c + 1 < 4) {
                    const int cn = c + 1;
                    const char* bs2 = bsrc + (size_t)((cn >> 1) * 128) * 1024;
                    const int kb0 = (cn & 1) * 2;
#pragma unroll
                    for (int sub = 0; sub < 2; sub++)
#pragma unroll
                        for (int v = 0; v < 4; v++)
                            cp16(sbB + ((cn & 1) * 32768) + sub * 16384 + bDst[v],
                                 bs2 + bSrc[v] + (kb0 + sub) * 128);
                    CP_COMMIT();
                }

                if (kp == 0) {
#pragma unroll
                    for (int mf = 0; mf < 2; mf++)
#pragma unroll
                        for (int nf = 0; nf < 4; nf++)
#pragma unroll
                            for (int t = 0; t < 4; t++) acc[mf][nf][t] = 0.f;
                }

#pragma unroll
                for (int kk = 0; kk < 2; kk++) {
                    const int kc = kp * 2 + kk;
                    const uint32_t bstg = sbB + stage * 32768 + kk * 16384;
                    const uint32_t bb0 = bstg + bBase[0];
                    const uint32_t bb1 = bstg + bBase[1];
                    const uint32_t aa0 = sbA + kc * 8192 + aBase[0];
                    const uint32_t aa1 = sbA + kc * 8192 + aBase[1];
#pragma unroll
                    for (int ks = 0; ks < 4; ks++) {
                        const uint32_t kA = ks * 32 + aKG;
                        const uint32_t kB = ks * 32 + bKG;
                        uint32_t b[4][2];
                        {
                            uint32_t t0[4], t1[4];
                            ldsm_x4(t0, bb0 + (kB ^ bXor[0]));
                            ldsm_x4(t1, bb1 + (kB ^ bXor[1]));
                            b[0][0] = t0[0]; b[0][1] = t0[1]; b[1][0] = t0[2]; b[1][1] = t0[3];
                            b[2][0] = t1[0]; b[2][1] = t1[1]; b[3][0] = t1[2]; b[3][1] = t1[3];
                        }
                        uint32_t a[2][4];
                        ldsm_x4(a[0], aa0 + (kA ^ aXor[0]));
                        ldsm_x4(a[1], aa1 + (kA ^ aXor[1]));
#pragma unroll
                        for (int mf = 0; mf < 2; mf++)
#pragma unroll
                            for (int nf = 0; nf < 4; nf++)
                                mma16816(acc[mf][nf], a[mf], b[nf]);
                    }
                }

                if (kp == 1) {
                    const float* csqp = scsq + codeBase + nsub * 128 + wn * 32 + 2 * (lane & 3);
#pragma unroll
                    for (int nf = 0; nf < 4; nf++) {
                        float q0 = csqp[nf * 8];
                        float q1 = csqp[nf * 8 + 1];
                        int n0 = codeBase + nsub * 128 + wn * 32 + nf * 8 + 2 * (lane & 3);
#pragma unroll
                        for (int mf = 0; mf < 2; mf++) {
#pragma unroll
                            for (int h = 0; h < 2; h++) {
                                int s = mf * 2 + h;
#pragma unroll
                                for (int w = 0; w < 2; w++) {
                                    float d = (w ? q1 : q0) - 2.f * acc[mf][nf][h * 2 + w];
                                    unsigned mk = mono(d);
                                    unsigned long long pk =
                                        ((unsigned long long)mk << 32) | (unsigned)(n0 + w);
                                    if (pk < p1[s]) {
                                        m2[s] = min(m2[s], (unsigned)(p1[s] >> 32));
                                        p1[s] = pk;
                                    } else {
                                        m2[s] = min(m2[s], mk);
                                    }
                                }
                            }
                        }
                    }
                }
            }

            // per-codeTile reduce -> merge into per-row running best (registers)
            __syncthreads();
#pragma unroll
            for (int s = 0; s < 4; s++) {
                unsigned long long p = p1[s];
                unsigned m = m2[s];
#pragma unroll
                for (int off = 1; off <= 2; off <<= 1) {
                    unsigned long long op = __shfl_xor_sync(0xffffffffu, p, off);
                    unsigned om = __shfl_xor_sync(0xffffffffu, m, off);
                    if (op < p) {
                        m = min(min(m, (unsigned)(p >> 32)), om);
                        p = op;
                    } else {
                        m = min(min(m, (unsigned)(op >> 32)), om);
                    }
                }
                if ((lane & 3) == 0) {
                    int row = wm * 32 + (s >> 1) * 16 + (lane >> 2) + (s & 1) * 8;
                    sp1[row * 4 + wn] = p;
                    sm2[row * 4 + wn] = m;
                }
            }
            __syncthreads();
            if (tid < 64) {
                unsigned long long p = sp1[tid * 4];
                unsigned m = sm2[tid * 4];
#pragma unroll
                for (int t = 1; t < 4; t++) {
                    unsigned long long op = sp1[tid * 4 + t];
                    unsigned om = sm2[tid * 4 + t];
                    if (op < p) {
                        m = min(min(m, (unsigned)(p >> 32)), om);
                        p = op;
                    } else {
                        m = min(min(m, (unsigned)(op >> 32)), om);
                    }
                }
                if (p < pAll) {
                    mAll = min(min(mAll, (unsigned)(pAll >> 32)), m);
                    pAll = p;
                } else {
                    mAll = min(min(mAll, (unsigned)(p >> 32)), m);
                }
            }
        }

        // ---- fused select: threshold + packed write + reflist append ----
        if (tid < 64) {
            float b1 = unmono((unsigned)(pAll >> 32));
            float b2 = unmono(mAll);
            bool refine = (b2 - b1 < THRESH);
            g_packed[rowBase + tid] = refine ? 0xFFFFFFFFFFFFFFFFull : pAll;
            if (refine) {
                int pos = atomicAdd(&g_nref, 1);
                g_reflist[pos] = rowBase + tid;
            }
        }
    }
}

// ---------------- K6: fp16x3 HMMA refine of flagged rows (gathered tiles) --------
#define NSTG     5
#define RB_OFF   131072                    // A: xh 64KB + xl 64KB
#define RCSQ_OFF (RB_OFF + NSTG * 16384)   // 212992
#define RSP_OFF  (RCSQ_OFF + 4096)         // 217088  u64[128][4]
#define RROW_OFF (RSP_OFF + 4096)          // 221184  int[128]
#define RSMEMSZ  (RROW_OFF + 512)          // 221696

__global__ void __launch_bounds__(512, 1) k_refmma(const float* __restrict__ x) {
    extern __shared__ char smem[];
    const uint32_t sbA = s2u(smem);
    const uint32_t sbB = sbA + RB_OFF;
    const int tid  = threadIdx.x;
    const int lane = tid & 31;
    const int wid  = tid >> 5;
    const int wm   = wid >> 2;
    const int wn   = wid & 3;

    const int nref = g_nref;
    const int ntick = ((nref + 127) >> 7) << 2;
    if (ntick == 0) return;

    if (tid < 256)
        ((float4*)(smem + RCSQ_OFF))[tid] = ((const float4*)g_csq)[tid];
    unsigned long long* sp1 = (unsigned long long*)(smem + RSP_OFF);
    int* srow = (int*)(smem + RROW_OFF);
    const float* scsq = (const float*)(smem + RCSQ_OFF);

    const int colA = tid & 63;
    const float4 scv = ((const float4*)g_scale)[colA];
    const float4 shv = ((const float4*)g_shift)[colA];

    const uint32_t aM  = (uint32_t)((lane & 7) + 8 * ((lane >> 3) & 1));
    const uint32_t aKG = (uint32_t)((lane >> 4) << 4);
    const uint32_t bN  = (uint32_t)(((lane >> 4) << 3) + (lane & 7));
    const uint32_t bKG = (uint32_t)(((lane >> 3) & 1) << 4);

    uint32_t aBase[2], aXor[2], bBase[2], bXor[2];
#pragma unroll
    for (int mf = 0; mf < 2; mf++) {
        uint32_t r = wm * 32 + mf * 16 + aM;
        aBase[mf] = r << 7;
        aXor[mf]  = (r & 7) << 4;
    }
#pragma unroll
    for (int np = 0; np < 2; np++) {
        uint32_t r = wn * 32 + np * 16 + bN;
        bBase[np] = r << 7;
        bXor[np]  = (r & 7) << 4;
    }
    uint32_t bDst[2], bSrc[2];
#pragma unroll
    for (int v = 0; v < 2; v++) {
        uint32_t idx = (uint32_t)tid + v * 512;
        uint32_t r = idx >> 3, j = idx & 7;
        bDst[v] = (r << 7) + ((j << 4) ^ ((r & 7) << 4));
        bSrc[v] = r * 1024 + j * 16;
    }

#pragma unroll 1
    for (int tk = blockIdx.x; tk < ntick; tk += 148) {
        const int rowBaseR = (tk >> 2) << 7;
        const int codeBase = (tk & 3) << 8;
        const char* bsrc = (const char*)(g_eB2 + (size_t)codeBase * 512);

        __syncthreads();
        if (tid < 128)
            srow[tid] = (rowBaseR + tid < nref) ? g_reflist[rowBaseR + tid] : -1;
        __syncthreads();

        // ---- B prologue: stages 0..3 = (nsub=0, eh, kc=0..3) ----
#pragma unroll
        for (int c0 = 0; c0 < 4; c0++) {
#pragma unroll
            for (int v = 0; v < 2; v++)
                cp16(sbB + c0 * 16384 + bDst[v], bsrc + bSrc[v] + c0 * 128);
            CP_COMMIT();
        }

        // ---- A gather/convert: hi + lo ----
        {
            const float4* xs = (const float4*)x;
            const int kc = colA >> 4;
            const int kb = (colA & 15) * 4;
#pragma unroll 4
            for (int i = 0; i < 16; i++) {
                int m = (tid >> 6) + i * 8;
                int grow = srow[m];
                if (grow < 0) grow = 0;
                float4 v = xs[(size_t)grow * 64 + colA];
                float b0 = v.x * scv.x + shv.x;
                float b1 = v.y * scv.y + shv.y;
                float b2 = v.z * scv.z + shv.z;
                float b3 = v.w * scv.w + shv.w;
                __half2 h01 = __floats2half2_rn(b0, b1);
                __half2 h23 = __floats2half2_rn(b2, b3);
                __half2 l01 = __floats2half2_rn(b0 - __low2float(h01), b1 - __high2float(h01));
                __half2 l23 = __floats2half2_rn(b2 - __low2float(h23), b3 - __high2float(h23));
                uint32_t so = swz((uint32_t)(m << 7) + (uint32_t)kb * 2);
                asm volatile("st.shared.v2.u32 [%0], {%1,%2};"
                             :: "r"(sbA + kc * 16384 + so),
                                "r"(*(uint32_t*)&h01), "r"(*(uint32_t*)&h23));
                asm volatile("st.shared.v2.u32 [%0], {%1,%2};"
                             :: "r"(sbA + 65536 + kc * 16384 + so),
                                "r"(*(uint32_t*)&l01), "r"(*(uint32_t*)&l23));
            }
        }

        unsigned long long p1[4];
#pragma unroll
        for (int s = 0; s < 4; s++) p1[s] = 0xFFFFFFFFFFFFFFFFull;

        float acc[2][4][4];

        // ---- mainloop: 16 chunks (2 nsub x {eh kc0-3, el kc0-3}) ----
#pragma unroll 1
        for (int c = 0; c < 16; c++) {
            const int nsub = c >> 3;
            const int within = c & 7;
            const int cls = within >> 2;     // 0 = eh (dual), 1 = el (single)
            const int kc = c & 3;
            const int stage = c % NSTG;

            if (c <= 12)      CP_WAIT(3);
            else if (c == 13) CP_WAIT(2);
            else if (c == 14) CP_WAIT(1);
            else              CP_WAIT(0);
            __syncthreads();

            if (within == 0) {
#pragma unroll
                for (int mf = 0; mf < 2; mf++)
#pragma unroll
                    for (int nf = 0; nf < 4; nf++)
#pragma unroll
                        for (int t = 0; t < 4; t++) acc[mf][nf][t] = 0.f;
            }

            const uint32_t bb0 = sbB + stage * 16384 + bBase[0];
            const uint32_t bb1 = sbB + stage * 16384 + bBase[1];
            const uint32_t aa0 = sbA + kc * 16384 + aBase[0];
            const uint32_t aa1 = sbA + kc * 16384 + aBase[1];
#pragma unroll
            for (int ks = 0; ks < 4; ks++) {
                const uint32_t kA = ks * 32 + aKG;
                const uint32_t kB = ks * 32 + bKG;
                uint32_t b[4][2];
                {
                    uint32_t t0[4], t1[4];
                    ldsm_x4(t0, bb0 + (kB ^ bXor[0]));
                    ldsm_x4(t1, bb1 + (kB ^ bXor[1]));
                    b[0][0] = t0[0]; b[0][1] = t0[1]; b[1][0] = t0[2]; b[1][1] = t0[3];
                    b[2][0] = t1[0]; b[2][1] = t1[1]; b[3][0] = t1[2]; b[3][1] = t1[3];
                }
                uint32_t a[2][4];
                ldsm_x4(a[0], aa0 + (kA ^ aXor[0]));
                ldsm_x4(a[1], aa1 + (kA ^ aXor[1]));
#pragma unroll
                for (int mf = 0; mf < 2; mf++)
#pragma unroll
                    for (int nf = 0; nf < 4; nf++)
                        mma16816(acc[mf][nf], a[mf], b[nf]);
                if (cls == 0) {
                    uint32_t a2[2][4];
                    ldsm_x4(a2[0], aa0 + 65536 + (kA ^ aXor[0]));
                    ldsm_x4(a2[1], aa1 + 65536 + (kA ^ aXor[1]));
#pragma unroll
                    for (int mf = 0; mf < 2; mf++)
#pragma unroll
                        for (int nf = 0; nf < 4; nf++)
                            mma16816(acc[mf][nf], a2[mf], b[nf]);
                }
            }

            if (within == 7) {
                const float* csqp = scsq + codeBase + nsub * 128 + wn * 32 + 2 * (lane & 3);
#pragma unroll
                for (int nf = 0; nf < 4; nf++) {
                    float q0 = csqp[nf * 8];
                    float q1 = csqp[nf * 8 + 1];
                    int n0 = codeBase + nsub * 128 + wn * 32 + nf * 8 + 2 * (lane & 3);
#pragma unroll
                    for (int mf = 0; mf < 2; mf++) {
#pragma unroll
                        for (int h = 0; h < 2; h++) {
                            int s = mf * 2 + h;
#pragma unroll
                            for (int w = 0; w < 2; w++) {
                                float d = (w ? q1 : q0) - 2.f * acc[mf][nf][h * 2 + w];
                                unsigned long long pk =
                                    ((unsigned long long)mono(d) << 32) | (unsigned)(n0 + w);
                                if (pk < p1[s]) p1[s] = pk;
                            }
                        }
                    }
                }
            }

            if (c + 4 < 16) {
                const int cc = c + 4;
                const int nsub2 = cc >> 3, cls2 = (cc >> 2) & 1, kc2 = cc & 3;
                const int st2 = cc % NSTG;
                const char* bs2 = bsrc + (size_t)(nsub2 * 128) * 1024;
#pragma unroll
                for (int v = 0; v < 2; v++)
                    cp16(sbB + st2 * 16384 + bDst[v], bs2 + bSrc[v] + cls2 * 512 + kc2 * 128);
                CP_COMMIT();
            }
        }

        // ---- reduce + merge ----
        __syncthreads();
#pragma unroll
        for (int s = 0; s < 4; s++) {
            unsigned long long p = p1[s];
#pragma unroll
            for (int off = 1; off <= 2; off <<= 1) {
                unsigned long long op = __shfl_xor_sync(0xffffffffu, p, off);
                if (op < p) p = op;
            }
            if ((lane & 3) == 0) {
                int row = wm * 32 + (s >> 1) * 16 + (lane >> 2) + (s & 1) * 8;
                sp1[row * 4 + wn] = p;
            }
        }
        __syncthreads();
        if (tid < 128) {
            int grow = srow[tid];
            if (grow >= 0) {
                unsigned long long p = sp1[tid * 4];
#pragma unroll
                for (int t = 1; t < 4; t++) {
                    unsigned long long op = sp1[tid * 4 + t];
                    if (op < p) p = op;
                }
                atomicMin(&g_packed[grow], p);
            }
        }
    }
}

// ---------------- K7: gather q, output, loss, counts, idx ------------------------
__global__ void k_quant(const int* __restrict__ mask,
                        float* __restrict__ outQ, float* __restrict__ outIdx) {
    int w = threadIdx.x >> 5, lane = threadIdx.x & 31;
    int row = blockIdx.x * 8 + w;
    int m = mask[row];
    unsigned long long pk = g_packed[row];
    int idx = (int)(pk & 0xffffffffull);
    const float4* qv = (const float4*)&g_ET[(size_t)idx * DDIM];
    float4* ov = (float4*)&outQ[(size_t)row * DDIM];
    float4 z = make_float4(0.f, 0.f, 0.f, 0.f);
#pragma unroll
    for (int t = 0; t < 2; t++) {
        int j = lane + t * 32;
        ov[j] = m ? qv[j] : z;
    }
    __shared__ float red[8];
    if (lane == 0) {
        float best = unmono((unsigned)(pk >> 32));
        red[w] = m ? (g_xsq[row] + best) : 0.f;
        outIdx[row] = m ? (float)idx : -1.f;
        if (m) atomicAdd(&g_counts[idx], 1.f);
    }
    __syncthreads();
    if (threadIdx.x == 0) {
        float t = 0.f;
        for (int i = 0; i < 8; i++) t += red[i];
        atomicAdd(&g_loss, (double)t);
    }
}

// ---------------- K8: finalize scalars -------------------------------------------
__global__ void k_final(float* __restrict__ out) {
    int t = threadIdx.x;  // 1024 threads
    float nv = fmaxf(g_cnt, 1.f);
    float p = g_counts[t] / nv;
    float h = -p * logf(p + 1e-10f);
    for (int o = 16; o; o >>= 1) h += __shfl_down_sync(0xffffffffu, h, o);
    __shared__ float red[32];
    if ((t & 31) == 0) red[t >> 5] = h;
    __syncthreads();
    if (t < 32) {
        float s = red[t];
        for (int o = 16; o; o >>= 1) s += __shfl_down_sync(0xffffffffu, s, o);
        if (t == 0) {
            float loss = (float)(g_loss / ((double)nv * (double)DDIM));
            out[OFF_DICT]   = loss;
            out[OFF_COMMIT] = loss;
            out[OFF_PERP]   = expf(s);
        }
    }
}

// ---------------- launch ------------------------------------------------------------
extern "C" void kernel_launch(void* const* d_in, const int* in_sizes, int n_in,
                              void* d_out, int out_size) {
    const float* x     = (const float*)d_in[0];
    const int*   mask  = (const int*)  d_in[1];
    const float* E     = (const float*)d_in[2];
    const float* gamma = (const float*)d_in[3];
    const float* beta  = (const float*)d_in[4];
    float* out = (float*)d_out;

    cudaFuncSetAttribute(k_coarse, cudaFuncAttributeMaxDynamicSharedMemorySize, SMEMSZ);
    cudaFuncSetAttribute(k_refmma, cudaFuncAttributeMaxDynamicSharedMemorySize, RSMEMSZ);

    k_stats<<<256, dim3(64, 4)>>>(x, mask);                  // 1
    k_prep_e<<<32, dim3(32, 8)>>>(E);                        // 2
    k_reduce_stats<<<1, 256>>>(gamma, beta);                 // 3
    k_coarse<<<296, 256, SMEMSZ>>>(x);                       // 4  (ncu lands here)
    k_refmma<<<148, 512, RSMEMSZ>>>(x);                      // 5
    k_quant<<<BNROWS / 8, 256>>>(mask, out + OFF_Q, out + OFF_IDX);
    k_final<<<1, 1024>>>(out);
}